// round 1
// baseline (speedup 1.0000x reference)
#include <cuda_runtime.h>
#include <math.h>

// Problem constants (fixed shapes)
#define LQ   512
#define NB   32
#define DIM  768
#define NH   8
#define HD   96
#define NR   196
#define TT   316               // text length = LQ - NR
#define MLB  (LQ*NB)           // 16384 rows of (l,b)
#define BH   (NB*NH)           // 256 batch-heads
#define EPSW 1e-8f

// -------------------- device scratch (no allocations allowed) --------------------
__device__ float g_twoq  [MLB*DIM];           // 50 MB
__device__ float g_threeq[MLB*DIM];           // 50 MB
__device__ float g_Q  [BH*LQ*HD];             // 50 MB  [b,h,l,j]
__device__ float g_K  [BH*LQ*HD];             // 50 MB
__device__ float g_V  [BH*LQ*HD];             // 50 MB
__device__ float g_S  [(size_t)BH*LQ*LQ];     // 268 MB [b,h,q,k]
__device__ float g_ctx[MLB*DIM];              // 50 MB  [l,b,c]

// -------------------- copy visual tokens into two_q/three_q --------------------
__global__ void copy_visual_kernel(const float* __restrict__ q,
                                   float* __restrict__ twoq,
                                   float* __restrict__ threeq)
{
    int i = blockIdx.x * blockDim.x + threadIdx.x;
    const int n = NR * NB * DIM / 4;
    if (i < n) {
        float4 v = reinterpret_cast<const float4*>(q)[i];
        reinterpret_cast<float4*>(twoq)[i]   = v;
        reinterpret_cast<float4*>(threeq)[i] = v;
    }
}

// -------------------- window aggregation (both windows in one kernel) --------------------
// block = (t, b), 256 threads. x[w] = text[b, t+w-2] (zero OOB).
// two  uses anchor x[2], window w=1..3
// three uses anchor x[3], window w=0..4
__global__ void window_agg_kernel(const float* __restrict__ q,
                                  float* __restrict__ twoq,
                                  float* __restrict__ threeq)
{
    int t = blockIdx.x;
    int b = blockIdx.y;
    int tid = threadIdx.x;

    __shared__ float xs[5][DIM];
    __shared__ float red[10][8];
    __shared__ float fin[10];

    #pragma unroll
    for (int w = 0; w < 5; w++) {
        int tw = t + w - 2;
        bool ok = (tw >= 0) && (tw < TT);
        const float* src = q + ((size_t)(NR + tw) * NB + b) * DIM;
        for (int c = tid; c < DIM; c += 256)
            xs[w][c] = ok ? src[c] : 0.0f;
    }
    __syncthreads();

    float p[10];
    #pragma unroll
    for (int k = 0; k < 10; k++) p[k] = 0.0f;

    for (int c = tid; c < DIM; c += 256) {
        float x0 = xs[0][c], x1 = xs[1][c], x2 = xs[2][c], x3 = xs[3][c], x4 = xs[4][c];
        p[0] += x0 * x0;  p[1] += x1 * x1;  p[2] += x2 * x2;
        p[3] += x3 * x3;  p[4] += x4 * x4;
        p[5] += x2 * x1;  p[6] += x2 * x3;
        p[7] += x3 * x0;  p[8] += x3 * x1;  p[9] += x3 * x4;
    }
    #pragma unroll
    for (int o = 16; o; o >>= 1) {
        #pragma unroll
        for (int k = 0; k < 10; k++)
            p[k] += __shfl_xor_sync(0xFFFFFFFFu, p[k], o);
    }
    int wid = tid >> 5, lane = tid & 31;
    if (lane == 0) {
        #pragma unroll
        for (int k = 0; k < 10; k++) red[k][wid] = p[k];
    }
    __syncthreads();
    if (tid < 10) {
        float s = 0.0f;
        #pragma unroll
        for (int w = 0; w < 8; w++) s += red[tid][w];
        fin[tid] = s;
    }
    __syncthreads();

    float n0 = fin[0], n1 = fin[1], n2 = fin[2], n3 = fin[3], n4 = fin[4];
    float in0 = 1.0f / fmaxf(sqrtf(n0), EPSW);
    float in1 = 1.0f / fmaxf(sqrtf(n1), EPSW);
    float in2 = 1.0f / fmaxf(sqrtf(n2), EPSW);
    float in3 = 1.0f / fmaxf(sqrtf(n3), EPSW);
    float in4 = 1.0f / fmaxf(sqrtf(n4), EPSW);

    // window-3 weights (anchor = x2)
    float w2_1 = fin[5] * in2 * in1;
    float w2_2 = n2     * in2 * in2;
    float w2_3 = fin[6] * in2 * in3;
    // window-5 weights (anchor = x3)
    float w3_0 = fin[7] * in3 * in0;
    float w3_1 = fin[8] * in3 * in1;
    float w3_2 = fin[6] * in3 * in2;
    float w3_3 = n3     * in3 * in3;
    float w3_4 = fin[9] * in3 * in4;

    size_t base = ((size_t)(NR + t) * NB + b) * DIM;
    for (int c = tid; c < DIM; c += 256) {
        float x0 = xs[0][c], x1 = xs[1][c], x2 = xs[2][c], x3 = xs[3][c], x4 = xs[4][c];
        twoq[base + c]   = w2_1 * x1 + w2_2 * x2 + w2_3 * x3;
        threeq[base + c] = w3_0 * x0 + w3_1 * x1 + w3_2 * x2 + w3_3 * x3 + w3_4 * x4;
    }
}

// -------------------- generic register-tiled SGEMM --------------------
// C = A * op(B), A: [M,K] row-major (lda), BT=true: B is [N,K] (NT), else [K,N] (NN).
// Epilogues:
//  0: C[z*sC + row*N + col] = acc                              (scores)
//  1: [B,H,L,hd] scatter, acc*scale                            (projections)
//  2: ctx [L,B,d] scatter from per-(b,h) O                     (attn output)
//  3: C[row*N+col] = (ACCUM? old:0) + (*scale_ptr)*acc         (final out)
template<bool BT, int EPI, bool ACCUM>
__global__ __launch_bounds__(256)
void gemm_kernel(const float* __restrict__ Ag, const float* __restrict__ Bg,
                 float* __restrict__ Cg,
                 int M, int N, int K, int lda, int ldb,
                 size_t sA, size_t sB, size_t sC,
                 float scale, const float* __restrict__ scale_ptr)
{
    const int BM = 128, BN = 128, BK = 8;
    __shared__ float As[BK][BM];
    __shared__ float Bs[BK][BN];

    int z = blockIdx.z;
    const float* A = Ag + (size_t)z * sA;
    const float* B = Bg + (size_t)z * sB;

    int m0 = blockIdx.y * BM;
    int n0 = blockIdx.x * BN;
    int tid = threadIdx.x;
    int tx = tid & 15;        // 0..15 (col group)
    int ty = tid >> 4;        // 0..15 (row group)

    float acc[8][8];
    #pragma unroll
    for (int i = 0; i < 8; i++)
        #pragma unroll
        for (int j = 0; j < 8; j++) acc[i][j] = 0.0f;

    int arow = tid >> 1;            // 0..127
    int acol = (tid & 1) * 4;       // 0 or 4
    int brow2 = tid >> 5;           // 0..7   (NN)
    int bcol2 = (tid & 31) * 4;     // 0..124 (NN)

    for (int k0 = 0; k0 < K; k0 += BK) {
        // A tile -> As[k][m]
        {
            float4 a = make_float4(0.f, 0.f, 0.f, 0.f);
            int gm = m0 + arow;
            if (gm < M)
                a = *reinterpret_cast<const float4*>(A + (size_t)gm * lda + k0 + acol);
            As[acol + 0][arow] = a.x;
            As[acol + 1][arow] = a.y;
            As[acol + 2][arow] = a.z;
            As[acol + 3][arow] = a.w;
        }
        // B tile -> Bs[k][n]
        if (BT) {
            float4 v = make_float4(0.f, 0.f, 0.f, 0.f);
            int gn = n0 + arow;
            if (gn < N)
                v = *reinterpret_cast<const float4*>(B + (size_t)gn * ldb + k0 + acol);
            Bs[acol + 0][arow] = v.x;
            Bs[acol + 1][arow] = v.y;
            Bs[acol + 2][arow] = v.z;
            Bs[acol + 3][arow] = v.w;
        } else {
            float4 v = make_float4(0.f, 0.f, 0.f, 0.f);
            int gn = n0 + bcol2;
            if (gn < N)
                v = *reinterpret_cast<const float4*>(B + (size_t)(k0 + brow2) * ldb + gn);
            *reinterpret_cast<float4*>(&Bs[brow2][bcol2]) = v;
        }
        __syncthreads();

        #pragma unroll
        for (int kk = 0; kk < BK; kk++) {
            float a[8], bb[8];
            float4 a0 = *reinterpret_cast<const float4*>(&As[kk][ty * 8]);
            float4 a1 = *reinterpret_cast<const float4*>(&As[kk][ty * 8 + 4]);
            float4 b0 = *reinterpret_cast<const float4*>(&Bs[kk][tx * 8]);
            float4 b1 = *reinterpret_cast<const float4*>(&Bs[kk][tx * 8 + 4]);
            a[0]=a0.x; a[1]=a0.y; a[2]=a0.z; a[3]=a0.w; a[4]=a1.x; a[5]=a1.y; a[6]=a1.z; a[7]=a1.w;
            bb[0]=b0.x; bb[1]=b0.y; bb[2]=b0.z; bb[3]=b0.w; bb[4]=b1.x; bb[5]=b1.y; bb[6]=b1.z; bb[7]=b1.w;
            #pragma unroll
            for (int i = 0; i < 8; i++)
                #pragma unroll
                for (int j = 0; j < 8; j++)
                    acc[i][j] = fmaf(a[i], bb[j], acc[i][j]);
        }
        __syncthreads();
    }

    float sp = 1.0f;
    if (EPI == 3) sp = *scale_ptr;

    #pragma unroll
    for (int i = 0; i < 8; i++) {
        int row = m0 + ty * 8 + i;
        if (row >= M) continue;
        #pragma unroll
        for (int j = 0; j < 8; j++) {
            int col = n0 + tx * 8 + j;
            if (col >= N) continue;
            float v = acc[i][j];
            if (EPI == 0) {
                Cg[(size_t)z * sC + (size_t)row * N + col] = v;
            } else if (EPI == 1) {
                int l = row >> 5, b = row & 31;       // row = l*32 + b
                int h = col / HD, jj = col % HD;
                Cg[(((size_t)(b * NH + h)) * LQ + l) * HD + jj] = v * scale;
            } else if (EPI == 2) {
                int b = z >> 3, h = z & 7;            // z = b*8 + h
                Cg[((size_t)row * NB + b) * DIM + h * HD + col] = v;
            } else {
                size_t idx = (size_t)row * N + col;
                float o = sp * v;
                if (ACCUM) o += Cg[idx];
                Cg[idx] = o;
            }
        }
    }
}

// -------------------- row softmax over scores (512 keys per row) --------------------
__global__ void softmax_rows_kernel(float* __restrict__ S)
{
    size_t row = (size_t)blockIdx.x * 8 + (threadIdx.x >> 5);
    int lane = threadIdx.x & 31;
    float* r = S + row * LQ;

    float v[16];
    float mx = -1e30f;
    #pragma unroll
    for (int i = 0; i < 16; i++) {
        v[i] = r[lane + 32 * i];
        mx = fmaxf(mx, v[i]);
    }
    #pragma unroll
    for (int o = 16; o; o >>= 1) mx = fmaxf(mx, __shfl_xor_sync(0xFFFFFFFFu, mx, o));
    float sm = 0.0f;
    #pragma unroll
    for (int i = 0; i < 16; i++) { v[i] = __expf(v[i] - mx); sm += v[i]; }
    #pragma unroll
    for (int o = 16; o; o >>= 1) sm += __shfl_xor_sync(0xFFFFFFFFu, sm, o);
    float inv = 1.0f / sm;
    #pragma unroll
    for (int i = 0; i < 16; i++) r[lane + 32 * i] = v[i] * inv;
}

// -------------------- launch --------------------
static float* sym_addr(const void* symbol)
{
    void* p = nullptr;
    cudaGetSymbolAddress(&p, symbol);
    return reinterpret_cast<float*>(p);
}

extern "C" void kernel_launch(void* const* d_in, const int* in_sizes, int n_in,
                              void* d_out, int out_size)
{
    const float* query = (const float*)d_in[0];
    const float* keyi  = (const float*)d_in[1];
    const float* value = (const float*)d_in[2];
    const float* w_in[3]  = { (const float*)d_in[3], (const float*)d_in[5], (const float*)d_in[7] };
    const float* w_out[3] = { (const float*)d_in[4], (const float*)d_in[6], (const float*)d_in[8] };
    const float* coef[3]  = { (const float*)d_in[9], (const float*)d_in[10], (const float*)d_in[11] };
    float* out = (float*)d_out;

    float* twoq   = sym_addr(g_twoq);
    float* threeq = sym_addr(g_threeq);
    float* Qb  = sym_addr(g_Q);
    float* Kb  = sym_addr(g_K);
    float* Vb  = sym_addr(g_V);
    float* Sb  = sym_addr(g_S);
    float* ctx = sym_addr(g_ctx);

    const float invs = 1.0f / sqrtf((float)HD);

    // Build two_q / three_q
    {
        int n4 = NR * NB * DIM / 4;
        copy_visual_kernel<<<(n4 + 255) / 256, 256>>>(query, twoq, threeq);
        window_agg_kernel<<<dim3(TT, NB), 256>>>(query, twoq, threeq);
    }

    const float* qsrc[3] = { query, twoq, threeq };
    dim3 gP(DIM / 128, MLB / 128, 1);       // (6,128)
    dim3 gS(LQ / 128, LQ / 128, BH);        // (4,4,256)
    dim3 gO(1, LQ / 128, BH);               // (1,4,256)

    for (int i = 0; i < 3; i++) {
        // Q/K/V projections into [B,H,L,hd]
        gemm_kernel<true, 1, false><<<gP, 256>>>(qsrc[i], w_in[i], Qb,
            MLB, DIM, DIM, DIM, DIM, 0, 0, 0, invs, nullptr);
        gemm_kernel<true, 1, false><<<gP, 256>>>(keyi, w_in[i] + DIM * DIM, Kb,
            MLB, DIM, DIM, DIM, DIM, 0, 0, 0, 1.0f, nullptr);
        gemm_kernel<true, 1, false><<<gP, 256>>>(value, w_in[i] + 2 * DIM * DIM, Vb,
            MLB, DIM, DIM, DIM, DIM, 0, 0, 0, 1.0f, nullptr);

        // S = Q K^T per (b,h)
        gemm_kernel<true, 0, false><<<gS, 256>>>(Qb, Kb, Sb,
            LQ, LQ, HD, HD, HD,
            (size_t)LQ * HD, (size_t)LQ * HD, (size_t)LQ * LQ, 1.0f, nullptr);

        // softmax rows
        softmax_rows_kernel<<<BH * LQ / 8, 256>>>(Sb);

        // O = S V  -> ctx in [L,B,d]
        gemm_kernel<false, 2, false><<<gO, 256>>>(Sb, Vb, ctx,
            LQ, HD, LQ, LQ, HD,
            (size_t)LQ * LQ, (size_t)LQ * HD, 0, 1.0f, nullptr);

        // out (+)= coef * ctx @ w_out^T
        if (i == 0)
            gemm_kernel<true, 3, false><<<gP, 256>>>(ctx, w_out[i], out,
                MLB, DIM, DIM, DIM, DIM, 0, 0, 0, 1.0f, coef[i]);
        else
            gemm_kernel<true, 3, true><<<gP, 256>>>(ctx, w_out[i], out,
                MLB, DIM, DIM, DIM, DIM, 0, 0, 0, 1.0f, coef[i]);
    }
}

// round 2
// speedup vs baseline: 3.2729x; 3.2729x over previous
#include <cuda_runtime.h>
#include <math.h>
#include <stdint.h>

// Problem constants (fixed shapes)
#define LQ   512
#define NB   32
#define DIM  768
#define NH   8
#define HD   96
#define NR   196
#define TT   316               // text length = LQ - NR
#define MLB  (LQ*NB)           // 16384 rows of (l,b)
#define BH   (NB*NH)           // 256 batch-heads
#define EPSW 1e-8f

// -------------------- device scratch (no allocations allowed) --------------------
__device__ float g_twoq  [MLB*DIM];
__device__ float g_threeq[MLB*DIM];
__device__ float g_Q  [BH*LQ*HD];
__device__ float g_K  [BH*LQ*HD];
__device__ float g_V  [BH*LQ*HD];
__device__ float g_S  [(size_t)BH*LQ*LQ];     // 268 MB scores
__device__ float g_ctx[MLB*DIM];

// -------------------- small PTX helpers --------------------
__device__ __forceinline__ void cp_async16(float* sptr, const float* gptr, bool valid) {
    uint32_t sa = (uint32_t)__cvta_generic_to_shared(sptr);
    int sz = valid ? 16 : 0;
    asm volatile("cp.async.cg.shared.global [%0], [%1], 16, %2;\n"
                 :: "r"(sa), "l"(gptr), "r"(sz));
}
__device__ __forceinline__ void cp_commit() { asm volatile("cp.async.commit_group;\n"); }
__device__ __forceinline__ void cp_wait1()  { asm volatile("cp.async.wait_group 1;\n"); }

__device__ __forceinline__ uint32_t f2tf(float x) {
    uint32_t r; asm("cvt.rna.tf32.f32 %0, %1;\n" : "=r"(r) : "f"(x)); return r;
}
__device__ __forceinline__ void mma_tf32(float c[4], const uint32_t a[4], const uint32_t b[2]) {
    asm volatile("mma.sync.aligned.m16n8k8.row.col.f32.tf32.tf32.f32 "
        "{%0,%1,%2,%3}, {%4,%5,%6,%7}, {%8,%9}, {%0,%1,%2,%3};\n"
        : "+f"(c[0]), "+f"(c[1]), "+f"(c[2]), "+f"(c[3])
        : "r"(a[0]), "r"(a[1]), "r"(a[2]), "r"(a[3]), "r"(b[0]), "r"(b[1]));
}

// -------------------- copy visual tokens into two_q/three_q --------------------
__global__ void copy_visual_kernel(const float* __restrict__ q,
                                   float* __restrict__ twoq,
                                   float* __restrict__ threeq)
{
    int i = blockIdx.x * blockDim.x + threadIdx.x;
    const int n = NR * NB * DIM / 4;
    if (i < n) {
        float4 v = reinterpret_cast<const float4*>(q)[i];
        reinterpret_cast<float4*>(twoq)[i]   = v;
        reinterpret_cast<float4*>(threeq)[i] = v;
    }
}

// -------------------- window aggregation (both windows in one kernel) --------------------
__global__ void window_agg_kernel(const float* __restrict__ q,
                                  float* __restrict__ twoq,
                                  float* __restrict__ threeq)
{
    int t = blockIdx.x;
    int b = blockIdx.y;
    int tid = threadIdx.x;

    __shared__ float xs[5][DIM];
    __shared__ float red[10][8];
    __shared__ float fin[10];

    #pragma unroll
    for (int w = 0; w < 5; w++) {
        int tw = t + w - 2;
        bool ok = (tw >= 0) && (tw < TT);
        const float* src = q + ((size_t)(NR + tw) * NB + b) * DIM;
        for (int c = tid; c < DIM; c += 256)
            xs[w][c] = ok ? src[c] : 0.0f;
    }
    __syncthreads();

    float p[10];
    #pragma unroll
    for (int k = 0; k < 10; k++) p[k] = 0.0f;

    for (int c = tid; c < DIM; c += 256) {
        float x0 = xs[0][c], x1 = xs[1][c], x2 = xs[2][c], x3 = xs[3][c], x4 = xs[4][c];
        p[0] += x0 * x0;  p[1] += x1 * x1;  p[2] += x2 * x2;
        p[3] += x3 * x3;  p[4] += x4 * x4;
        p[5] += x2 * x1;  p[6] += x2 * x3;
        p[7] += x3 * x0;  p[8] += x3 * x1;  p[9] += x3 * x4;
    }
    #pragma unroll
    for (int o = 16; o; o >>= 1) {
        #pragma unroll
        for (int k = 0; k < 10; k++)
            p[k] += __shfl_xor_sync(0xFFFFFFFFu, p[k], o);
    }
    int wid = tid >> 5, lane = tid & 31;
    if (lane == 0) {
        #pragma unroll
        for (int k = 0; k < 10; k++) red[k][wid] = p[k];
    }
    __syncthreads();
    if (tid < 10) {
        float s = 0.0f;
        #pragma unroll
        for (int w = 0; w < 8; w++) s += red[tid][w];
        fin[tid] = s;
    }
    __syncthreads();

    float n0 = fin[0], n1 = fin[1], n2 = fin[2], n3 = fin[3], n4 = fin[4];
    float in0 = 1.0f / fmaxf(sqrtf(n0), EPSW);
    float in1 = 1.0f / fmaxf(sqrtf(n1), EPSW);
    float in2 = 1.0f / fmaxf(sqrtf(n2), EPSW);
    float in3 = 1.0f / fmaxf(sqrtf(n3), EPSW);
    float in4 = 1.0f / fmaxf(sqrtf(n4), EPSW);

    float w2_1 = fin[5] * in2 * in1;
    float w2_2 = n2     * in2 * in2;
    float w2_3 = fin[6] * in2 * in3;
    float w3_0 = fin[7] * in3 * in0;
    float w3_1 = fin[8] * in3 * in1;
    float w3_2 = fin[6] * in3 * in2;
    float w3_3 = n3     * in3 * in3;
    float w3_4 = fin[9] * in3 * in4;

    size_t base = ((size_t)(NR + t) * NB + b) * DIM;
    for (int c = tid; c < DIM; c += 256) {
        float x0 = xs[0][c], x1 = xs[1][c], x2 = xs[2][c], x3 = xs[3][c], x4 = xs[4][c];
        twoq[base + c]   = w2_1 * x1 + w2_2 * x2 + w2_3 * x3;
        threeq[base + c] = w3_0 * x0 + w3_1 * x1 + w3_2 * x2 + w3_3 * x3 + w3_4 * x4;
    }
}

// -------------------- tf32 tensor-core GEMM --------------------
// C = A * op(B). A: [M,K] row-major. BT=true: B is [N,K] (NT), else [K,N] (NN).
// Epilogues:
//  0: scores   C[z*sC + row*N + col] = acc
//  1: proj     [B,H,L,hd] scatter, acc*scale
//  2: attn-out ctx [L,B,d] scatter from per-(b,h) O (z = b*8+h)
//  3: final    C[row*N+col] = (ACCUM? old:0) + (*scale_ptr)*acc
template<bool BT, int EPI, bool ACCUM>
__global__ __launch_bounds__(256, 2)
void mma_gemm(const float* __restrict__ Ag, const float* __restrict__ Bg,
              float* __restrict__ Cg,
              int M, int N, int K, int lda, int ldb,
              size_t sA, size_t sB, size_t sC,
              float scale, const float* __restrict__ scale_ptr)
{
    constexpr int BM = 128, BN = 128, BK = 16;
    constexpr int AST = BK + 4;          // A smem [m][k] stride 20 (conflict-free frags)
    constexpr int BSTT = BK + 4;         // B-NT smem [n][k] stride 20
    constexpr int BSTN = BN + 8;         // B-NN smem [k][n] stride 136
    constexpr int AS_SZ = BM * AST;
    constexpr int BS_SZ = BT ? (BN * BSTT) : (BK * BSTN);

    __shared__ __align__(16) float As[2][AS_SZ];
    __shared__ __align__(16) float Bs[2][BS_SZ];

    const int z = blockIdx.z;
    const float* A = Ag + (size_t)z * sA;
    const float* B = Bg + (size_t)z * sB;
    const int m0 = blockIdx.y * BM;
    const int n0 = blockIdx.x * BN;
    const int tid = threadIdx.x;
    const int lane = tid & 31;
    const int wid = tid >> 5;
    const int warp_m = (wid >> 2) * 64;   // 2 warps along M
    const int warp_n = (wid & 3) * 32;    // 4 warps along N
    const int gr = lane >> 2;             // 0..7
    const int tg = lane & 3;              // 0..3

    float acc[4][4][4];
    #pragma unroll
    for (int i = 0; i < 4; i++)
        #pragma unroll
        for (int j = 0; j < 4; j++)
            #pragma unroll
            for (int e = 0; e < 4; e++) acc[i][j][e] = 0.0f;

    const int nt = K / BK;

    // ---- tile loader (cp.async, 2 chunks of 16B per thread per operand) ----
    auto load_tile = [&](int s, int kt) {
        int k0 = kt * BK;
        #pragma unroll
        for (int r = 0; r < 2; r++) {
            int c = tid + 256 * r;
            int row = c >> 2, kq = c & 3;
            const float* g = A + (size_t)(m0 + row) * lda + k0 + kq * 4;
            cp_async16(&As[s][row * AST + kq * 4], g, true);
        }
        if (BT) {
            #pragma unroll
            for (int r = 0; r < 2; r++) {
                int c = tid + 256 * r;
                int row = c >> 2, kq = c & 3;
                bool v = (n0 + row) < N;
                const float* g = B + (size_t)(n0 + row) * ldb + k0 + kq * 4;
                cp_async16(&Bs[s][row * BSTT + kq * 4], v ? g : B, v);
            }
        } else {
            #pragma unroll
            for (int r = 0; r < 2; r++) {
                int c = tid + 256 * r;
                int kr = c >> 5, nq = c & 31;
                bool v = (n0 + nq * 4) < N;
                const float* g = B + (size_t)(k0 + kr) * ldb + n0 + nq * 4;
                cp_async16(&Bs[s][kr * BSTN + nq * 4], v ? g : B, v);
            }
        }
    };

    load_tile(0, 0);
    cp_commit();

    for (int kt = 0; kt < nt; kt++) {
        int s = kt & 1;
        if (kt + 1 < nt) load_tile(s ^ 1, kt + 1);
        cp_commit();
        cp_wait1();
        __syncthreads();

        #pragma unroll
        for (int ks = 0; ks < 2; ks++) {
            int kb = ks * 8;
            uint32_t af[4][4];
            #pragma unroll
            for (int i = 0; i < 4; i++) {
                int rb = warp_m + i * 16 + gr;
                af[i][0] = f2tf(As[s][(rb)     * AST + kb + tg]);
                af[i][1] = f2tf(As[s][(rb + 8) * AST + kb + tg]);
                af[i][2] = f2tf(As[s][(rb)     * AST + kb + tg + 4]);
                af[i][3] = f2tf(As[s][(rb + 8) * AST + kb + tg + 4]);
            }
            uint32_t bf[4][2];
            #pragma unroll
            for (int j = 0; j < 4; j++) {
                int nb = warp_n + j * 8 + gr;
                if (BT) {
                    bf[j][0] = f2tf(Bs[s][nb * BSTT + kb + tg]);
                    bf[j][1] = f2tf(Bs[s][nb * BSTT + kb + tg + 4]);
                } else {
                    bf[j][0] = f2tf(Bs[s][(kb + tg)     * BSTN + nb]);
                    bf[j][1] = f2tf(Bs[s][(kb + tg + 4) * BSTN + nb]);
                }
            }
            #pragma unroll
            for (int i = 0; i < 4; i++)
                #pragma unroll
                for (int j = 0; j < 4; j++)
                    mma_tf32(acc[i][j], af[i], bf[j]);
        }
        __syncthreads();
    }

    float sp = 1.0f;
    if (EPI == 3) sp = *scale_ptr;

    #pragma unroll
    for (int i = 0; i < 4; i++) {
        #pragma unroll
        for (int j = 0; j < 4; j++) {
            #pragma unroll
            for (int e = 0; e < 4; e++) {
                int row = m0 + warp_m + i * 16 + gr + ((e >= 2) ? 8 : 0);
                int col = n0 + warp_n + j * 8 + 2 * tg + (e & 1);
                if (col >= N || row >= M) continue;
                float v = acc[i][j][e];
                if (EPI == 0) {
                    Cg[(size_t)z * sC + (size_t)row * N + col] = v;
                } else if (EPI == 1) {
                    int l = row >> 5, b = row & 31;      // row = l*32 + b
                    int h = col / HD, jj = col % HD;
                    Cg[(((size_t)(b * NH + h)) * LQ + l) * HD + jj] = v * scale;
                } else if (EPI == 2) {
                    int b = z >> 3, h = z & 7;           // z = b*8 + h
                    Cg[((size_t)row * NB + b) * DIM + h * HD + col] = v;
                } else {
                    size_t idx = (size_t)row * N + col;
                    float o = sp * v;
                    if (ACCUM) o += Cg[idx];
                    Cg[idx] = o;
                }
            }
        }
    }
}

// -------------------- row softmax over scores (512 keys per row) --------------------
__global__ void softmax_rows_kernel(float* __restrict__ S)
{
    size_t row = (size_t)blockIdx.x * 8 + (threadIdx.x >> 5);
    int lane = threadIdx.x & 31;
    float* r = S + row * LQ;

    float v[16];
    float mx = -1e30f;
    #pragma unroll
    for (int i = 0; i < 16; i++) {
        v[i] = r[lane + 32 * i];
        mx = fmaxf(mx, v[i]);
    }
    #pragma unroll
    for (int o = 16; o; o >>= 1) mx = fmaxf(mx, __shfl_xor_sync(0xFFFFFFFFu, mx, o));
    float sm = 0.0f;
    #pragma unroll
    for (int i = 0; i < 16; i++) { v[i] = __expf(v[i] - mx); sm += v[i]; }
    #pragma unroll
    for (int o = 16; o; o >>= 1) sm += __shfl_xor_sync(0xFFFFFFFFu, sm, o);
    float inv = 1.0f / sm;
    #pragma unroll
    for (int i = 0; i < 16; i++) r[lane + 32 * i] = v[i] * inv;
}

// -------------------- launch --------------------
static float* sym_addr(const void* symbol)
{
    void* p = nullptr;
    cudaGetSymbolAddress(&p, symbol);
    return reinterpret_cast<float*>(p);
}

extern "C" void kernel_launch(void* const* d_in, const int* in_sizes, int n_in,
                              void* d_out, int out_size)
{
    const float* query = (const float*)d_in[0];
    const float* keyi  = (const float*)d_in[1];
    const float* value = (const float*)d_in[2];
    const float* w_in[3]  = { (const float*)d_in[3], (const float*)d_in[5], (const float*)d_in[7] };
    const float* w_out[3] = { (const float*)d_in[4], (const float*)d_in[6], (const float*)d_in[8] };
    const float* coef[3]  = { (const float*)d_in[9], (const float*)d_in[10], (const float*)d_in[11] };
    float* out = (float*)d_out;

    float* twoq   = sym_addr(g_twoq);
    float* threeq = sym_addr(g_threeq);
    float* Qb  = sym_addr(g_Q);
    float* Kb  = sym_addr(g_K);
    float* Vb  = sym_addr(g_V);
    float* Sb  = sym_addr(g_S);
    float* ctx = sym_addr(g_ctx);

    const float invs = 1.0f / sqrtf((float)HD);

    // Build two_q / three_q
    {
        int n4 = NR * NB * DIM / 4;
        copy_visual_kernel<<<(n4 + 255) / 256, 256>>>(query, twoq, threeq);
        window_agg_kernel<<<dim3(TT, NB), 256>>>(query, twoq, threeq);
    }

    const float* qsrc[3] = { query, twoq, threeq };
    dim3 gP(DIM / 128, MLB / 128, 1);       // (6,128)
    dim3 gS(LQ / 128, LQ / 128, BH);        // (4,4,256)
    dim3 gO(1, LQ / 128, BH);               // (1,4,256)

    for (int i = 0; i < 3; i++) {
        // Q/K/V projections into [B,H,L,hd]
        mma_gemm<true, 1, false><<<gP, 256>>>(qsrc[i], w_in[i], Qb,
            MLB, DIM, DIM, DIM, DIM, 0, 0, 0, invs, nullptr);
        mma_gemm<true, 1, false><<<gP, 256>>>(keyi, w_in[i] + DIM * DIM, Kb,
            MLB, DIM, DIM, DIM, DIM, 0, 0, 0, 1.0f, nullptr);
        mma_gemm<true, 1, false><<<gP, 256>>>(value, w_in[i] + 2 * DIM * DIM, Vb,
            MLB, DIM, DIM, DIM, DIM, 0, 0, 0, 1.0f, nullptr);

        // S = Q K^T per (b,h)
        mma_gemm<true, 0, false><<<gS, 256>>>(Qb, Kb, Sb,
            LQ, LQ, HD, HD, HD,
            (size_t)LQ * HD, (size_t)LQ * HD, (size_t)LQ * LQ, 1.0f, nullptr);

        // softmax rows
        softmax_rows_kernel<<<BH * LQ / 8, 256>>>(Sb);

        // O = S V  -> ctx in [L,B,d]
        mma_gemm<false, 2, false><<<gO, 256>>>(Sb, Vb, ctx,
            LQ, HD, LQ, LQ, HD,
            (size_t)LQ * LQ, (size_t)LQ * HD, 0, 1.0f, nullptr);

        // out (+)= coef * ctx @ w_out^T
        if (i == 0)
            mma_gemm<true, 3, false><<<gP, 256>>>(ctx, w_out[i], out,
                MLB, DIM, DIM, DIM, DIM, 0, 0, 0, 1.0f, coef[i]);
        else
            mma_gemm<true, 3, true><<<gP, 256>>>(ctx, w_out[i], out,
                MLB, DIM, DIM, DIM, DIM, 0, 0, 0, 1.0f, coef[i]);
    }
}

// round 3
// speedup vs baseline: 3.3926x; 1.0366x over previous
#include <cuda_runtime.h>
#include <math.h>
#include <stdint.h>

// Problem constants (fixed shapes)
#define LQ   512
#define NB   32
#define DIM  768
#define NH   8
#define HD   96
#define NR   196
#define TT   316               // text length
#define MLB  (LQ*NB)           // 16384
#define BH   (NB*NH)           // 256
#define LDQ  (NB*DIM)          // 24576 row stride of [L,B,D] per l
#define EPSW 1e-8f

#define WSZ  (2304*768 + 768*768)   // per-MHA rounded weights

// -------------------- device scratch --------------------
__device__ float g_twoq  [MLB*DIM];
__device__ float g_threeq[MLB*DIM];
__device__ float g_qr [MLB*DIM];
__device__ float g_kr [MLB*DIM];
__device__ float g_vr [MLB*DIM];
__device__ float g_wr [3*WSZ];
__device__ float g_Q  [MLB*DIM];              // [L,B,D] rounded
__device__ float g_K  [MLB*DIM];
__device__ float g_V  [MLB*DIM];
__device__ float g_S  [(size_t)BH*LQ*LQ];     // scores / probs
__device__ float g_ctx[MLB*DIM];

// -------------------- PTX helpers --------------------
__device__ __forceinline__ void cp_async16(float* sptr, const float* gptr, bool valid) {
    uint32_t sa = (uint32_t)__cvta_generic_to_shared(sptr);
    int sz = valid ? 16 : 0;
    asm volatile("cp.async.cg.shared.global [%0], [%1], 16, %2;\n"
                 :: "r"(sa), "l"(gptr), "r"(sz));
}
__device__ __forceinline__ void cp_commit() { asm volatile("cp.async.commit_group;\n"); }
__device__ __forceinline__ void cp_wait1()  { asm volatile("cp.async.wait_group 1;\n"); }

__device__ __forceinline__ float rnd_tf32(float x) {
    uint32_t r; asm("cvt.rna.tf32.f32 %0, %1;\n" : "=r"(r) : "f"(x));
    return __uint_as_float(r);
}
__device__ __forceinline__ void mma_tf32(float c[4], const uint32_t a[4], const uint32_t b[2]) {
    asm volatile("mma.sync.aligned.m16n8k8.row.col.f32.tf32.tf32.f32 "
        "{%0,%1,%2,%3}, {%4,%5,%6,%7}, {%8,%9}, {%0,%1,%2,%3};\n"
        : "+f"(c[0]), "+f"(c[1]), "+f"(c[2]), "+f"(c[3])
        : "r"(a[0]), "r"(a[1]), "r"(a[2]), "r"(a[3]), "r"(b[0]), "r"(b[1]));
}
__device__ __forceinline__ uint32_t fbits(float x) { return __float_as_uint(x); }

// -------------------- pre-round inputs to tf32 grid --------------------
__global__ void round_copy_kernel(const float* __restrict__ src,
                                  float* __restrict__ dst, int n4)
{
    int i = blockIdx.x * blockDim.x + threadIdx.x;
    if (i < n4) {
        float4 v = reinterpret_cast<const float4*>(src)[i];
        v.x = rnd_tf32(v.x); v.y = rnd_tf32(v.y);
        v.z = rnd_tf32(v.z); v.w = rnd_tf32(v.w);
        reinterpret_cast<float4*>(dst)[i] = v;
    }
}

// -------------------- visual tokens (rounded) into two_q/three_q --------------------
__global__ void copy_visual_kernel(const float* __restrict__ q,
                                   float* __restrict__ twoq,
                                   float* __restrict__ threeq)
{
    int i = blockIdx.x * blockDim.x + threadIdx.x;
    const int n = NR * NB * DIM / 4;
    if (i < n) {
        float4 v = reinterpret_cast<const float4*>(q)[i];
        v.x = rnd_tf32(v.x); v.y = rnd_tf32(v.y);
        v.z = rnd_tf32(v.z); v.w = rnd_tf32(v.w);
        reinterpret_cast<float4*>(twoq)[i]   = v;
        reinterpret_cast<float4*>(threeq)[i] = v;
    }
}

// -------------------- window aggregation (outputs rounded) --------------------
__global__ void window_agg_kernel(const float* __restrict__ q,
                                  float* __restrict__ twoq,
                                  float* __restrict__ threeq)
{
    int t = blockIdx.x;
    int b = blockIdx.y;
    int tid = threadIdx.x;

    __shared__ float xs[5][DIM];
    __shared__ float red[10][8];
    __shared__ float fin[10];

    #pragma unroll
    for (int w = 0; w < 5; w++) {
        int tw = t + w - 2;
        bool ok = (tw >= 0) && (tw < TT);
        const float* src = q + ((size_t)(NR + tw) * NB + b) * DIM;
        for (int c = tid; c < DIM; c += 256)
            xs[w][c] = ok ? src[c] : 0.0f;
    }
    __syncthreads();

    float p[10];
    #pragma unroll
    for (int k = 0; k < 10; k++) p[k] = 0.0f;

    for (int c = tid; c < DIM; c += 256) {
        float x0 = xs[0][c], x1 = xs[1][c], x2 = xs[2][c], x3 = xs[3][c], x4 = xs[4][c];
        p[0] += x0 * x0;  p[1] += x1 * x1;  p[2] += x2 * x2;
        p[3] += x3 * x3;  p[4] += x4 * x4;
        p[5] += x2 * x1;  p[6] += x2 * x3;
        p[7] += x3 * x0;  p[8] += x3 * x1;  p[9] += x3 * x4;
    }
    #pragma unroll
    for (int o = 16; o; o >>= 1) {
        #pragma unroll
        for (int k = 0; k < 10; k++)
            p[k] += __shfl_xor_sync(0xFFFFFFFFu, p[k], o);
    }
    int wid = tid >> 5, lane = tid & 31;
    if (lane == 0) {
        #pragma unroll
        for (int k = 0; k < 10; k++) red[k][wid] = p[k];
    }
    __syncthreads();
    if (tid < 10) {
        float s = 0.0f;
        #pragma unroll
        for (int w = 0; w < 8; w++) s += red[tid][w];
        fin[tid] = s;
    }
    __syncthreads();

    float n0 = fin[0], n1 = fin[1], n2 = fin[2], n3 = fin[3], n4 = fin[4];
    float in0 = 1.0f / fmaxf(sqrtf(n0), EPSW);
    float in1 = 1.0f / fmaxf(sqrtf(n1), EPSW);
    float in2 = 1.0f / fmaxf(sqrtf(n2), EPSW);
    float in3 = 1.0f / fmaxf(sqrtf(n3), EPSW);
    float in4 = 1.0f / fmaxf(sqrtf(n4), EPSW);

    float w2_1 = fin[5] * in2 * in1;
    float w2_2 = n2     * in2 * in2;
    float w2_3 = fin[6] * in2 * in3;
    float w3_0 = fin[7] * in3 * in0;
    float w3_1 = fin[8] * in3 * in1;
    float w3_2 = fin[6] * in3 * in2;
    float w3_3 = n3     * in3 * in3;
    float w3_4 = fin[9] * in3 * in4;

    size_t base = ((size_t)(NR + t) * NB + b) * DIM;
    for (int c = tid; c < DIM; c += 256) {
        float x0 = xs[0][c], x1 = xs[1][c], x2 = xs[2][c], x3 = xs[3][c], x4 = xs[4][c];
        twoq[base + c]   = rnd_tf32(w2_1 * x1 + w2_2 * x2 + w2_3 * x3);
        threeq[base + c] = rnd_tf32(w3_0 * x0 + w3_1 * x1 + w3_2 * x2 + w3_3 * x3 + w3_4 * x4);
    }
}

// -------------------- tf32 tensor-core GEMM (3-stage pipeline, no inner cvt) ----------
// C = A * op(B). A: [M,K] row-major (lda). BT: B [N,K] (NT) else [K,N] (NN).
// AZ/BZ: per-z base offset (z>>3)*DIM + (z&7)*HD (for [L,B,D] Q/K/V views),
//        otherwise z*sA / z*sB.
// Epilogues:
//  0: scores  C[z*sC + row*N + col] = acc               (fp32, feeds softmax)
//  1: proj    C[row*DIM + col] = rnd(acc*scale)         ([L,B,D] natural)
//  2: ctx     C[row*LDQ + zoff + col] = rnd(acc)        (per-(b,h) cols of [L,B,D])
//  3: final   C[row*N+col] = (ACCUM? old:0) + (*scale_ptr)*acc
template<bool BT, int EPI, bool ACCUM, bool AZ, bool BZ>
__global__ __launch_bounds__(256, 2)
void mma_gemm(const float* __restrict__ Ag, const float* __restrict__ Bg,
              float* __restrict__ Cg,
              int M, int N, int K, int lda, int ldb,
              size_t sA, size_t sB, size_t sC,
              float scale, const float* __restrict__ scale_ptr)
{
    constexpr int BM = 128, BN = 128, BK = 16, ST = 3;
    constexpr int AST  = BK + 4;          // [m][k] stride 20
    constexpr int BSTT = BK + 4;          // NT [n][k] stride 20
    constexpr int BSTN = BN + 8;          // NN [k][n] stride 136
    constexpr int AS_SZ = BM * AST;
    constexpr int BS_SZ = BT ? (BN * BSTT) : (BK * BSTN);

    extern __shared__ float dsm[];
    float* As = dsm;                      // [ST][AS_SZ]
    float* Bs = dsm + ST * AS_SZ;         // [ST][BS_SZ]

    const int z = blockIdx.z;
    const size_t zoff = (size_t)(z >> 3) * DIM + (size_t)(z & 7) * HD;
    const float* A = Ag + (AZ ? zoff : (size_t)z * sA);
    const float* B = Bg + (BZ ? zoff : (size_t)z * sB);
    const int m0 = blockIdx.y * BM;
    const int n0 = blockIdx.x * BN;
    const int tid = threadIdx.x;
    const int lane = tid & 31;
    const int wid = tid >> 5;
    const int warp_m = (wid >> 2) * 64;
    const int warp_n = (wid & 3) * 32;
    const int gr = lane >> 2;
    const int tg = lane & 3;

    float acc[4][4][4];
    #pragma unroll
    for (int i = 0; i < 4; i++)
        #pragma unroll
        for (int j = 0; j < 4; j++)
            #pragma unroll
            for (int e = 0; e < 4; e++) acc[i][j][e] = 0.0f;

    const int nt = K / BK;

    auto load_tile = [&](int s, int kt) {
        int k0 = kt * BK;
        float* as = As + s * AS_SZ;
        float* bs = Bs + s * BS_SZ;
        #pragma unroll
        for (int r = 0; r < 2; r++) {
            int c = tid + 256 * r;
            int row = c >> 2, kq = c & 3;
            const float* g = A + (size_t)(m0 + row) * lda + k0 + kq * 4;
            cp_async16(&as[row * AST + kq * 4], g, true);
        }
        if (BT) {
            #pragma unroll
            for (int r = 0; r < 2; r++) {
                int c = tid + 256 * r;
                int row = c >> 2, kq = c & 3;
                bool v = (n0 + row) < N;
                const float* g = B + (size_t)(n0 + row) * ldb + k0 + kq * 4;
                cp_async16(&bs[row * BSTT + kq * 4], v ? g : B, v);
            }
        } else {
            #pragma unroll
            for (int r = 0; r < 2; r++) {
                int c = tid + 256 * r;
                int kr = c >> 5, nq = c & 31;
                bool v = (n0 + nq * 4) < N;
                const float* g = B + (size_t)(k0 + kr) * ldb + n0 + nq * 4;
                cp_async16(&bs[kr * BSTN + nq * 4], v ? g : B, v);
            }
        }
    };

    // prologue: 2 tiles in flight
    load_tile(0, 0); cp_commit();
    if (nt > 1) load_tile(1, 1);
    cp_commit();

    for (int kt = 0; kt < nt; kt++) {
        cp_wait1();
        __syncthreads();
        // prefetch kt+2 into buffer (kt+2)%3 == (kt-1)%3 (safe: consumed at kt-1)
        if (kt + 2 < nt) load_tile((kt + 2) % ST, kt + 2);
        cp_commit();

        const float* as = As + (kt % ST) * AS_SZ;
        const float* bs = Bs + (kt % ST) * BS_SZ;

        #pragma unroll
        for (int ks = 0; ks < 2; ks++) {
            int kb = ks * 8;
            uint32_t af[4][4];
            #pragma unroll
            for (int i = 0; i < 4; i++) {
                int rb = warp_m + i * 16 + gr;
                af[i][0] = fbits(as[(rb)     * AST + kb + tg]);
                af[i][1] = fbits(as[(rb + 8) * AST + kb + tg]);
                af[i][2] = fbits(as[(rb)     * AST + kb + tg + 4]);
                af[i][3] = fbits(as[(rb + 8) * AST + kb + tg + 4]);
            }
            uint32_t bf[4][2];
            #pragma unroll
            for (int j = 0; j < 4; j++) {
                int nb = warp_n + j * 8 + gr;
                if (BT) {
                    bf[j][0] = fbits(bs[nb * BSTT + kb + tg]);
                    bf[j][1] = fbits(bs[nb * BSTT + kb + tg + 4]);
                } else {
                    bf[j][0] = fbits(bs[(kb + tg)     * BSTN + nb]);
                    bf[j][1] = fbits(bs[(kb + tg + 4) * BSTN + nb]);
                }
            }
            #pragma unroll
            for (int i = 0; i < 4; i++)
                #pragma unroll
                for (int j = 0; j < 4; j++)
                    mma_tf32(acc[i][j], af[i], bf[j]);
        }
    }

    float sp = 1.0f;
    if (EPI == 3) sp = *scale_ptr;

    #pragma unroll
    for (int i = 0; i < 4; i++) {
        #pragma unroll
        for (int j = 0; j < 4; j++) {
            int row = m0 + warp_m + i * 16 + gr;
            int col = n0 + warp_n + j * 8 + 2 * tg;
            if (col >= N) continue;
            #pragma unroll
            for (int half = 0; half < 2; half++) {
                int r = row + half * 8;
                float v0 = acc[i][j][half * 2 + 0];
                float v1 = acc[i][j][half * 2 + 1];
                if (EPI == 0) {
                    float2 o = make_float2(v0, v1);
                    *reinterpret_cast<float2*>(&Cg[(size_t)z * sC + (size_t)r * N + col]) = o;
                } else if (EPI == 1) {
                    float2 o = make_float2(rnd_tf32(v0 * scale), rnd_tf32(v1 * scale));
                    *reinterpret_cast<float2*>(&Cg[(size_t)r * DIM + col]) = o;
                } else if (EPI == 2) {
                    float2 o = make_float2(rnd_tf32(v0), rnd_tf32(v1));
                    *reinterpret_cast<float2*>(&Cg[(size_t)r * LDQ + zoff + col]) = o;
                } else {
                    size_t idx = (size_t)r * N + col;
                    float2 o = make_float2(sp * v0, sp * v1);
                    if (ACCUM) {
                        float2 old = *reinterpret_cast<const float2*>(&Cg[idx]);
                        o.x += old.x; o.y += old.y;
                    }
                    *reinterpret_cast<float2*>(&Cg[idx]) = o;
                }
            }
        }
    }
}

// -------------------- row softmax (rounded outputs) --------------------
__global__ void softmax_rows_kernel(float* __restrict__ S)
{
    size_t row = (size_t)blockIdx.x * 8 + (threadIdx.x >> 5);
    int lane = threadIdx.x & 31;
    float* r = S + row * LQ;

    float v[16];
    float mx = -1e30f;
    #pragma unroll
    for (int i = 0; i < 16; i++) {
        v[i] = r[lane + 32 * i];
        mx = fmaxf(mx, v[i]);
    }
    #pragma unroll
    for (int o = 16; o; o >>= 1) mx = fmaxf(mx, __shfl_xor_sync(0xFFFFFFFFu, mx, o));
    float sm = 0.0f;
    #pragma unroll
    for (int i = 0; i < 16; i++) { v[i] = __expf(v[i] - mx); sm += v[i]; }
    #pragma unroll
    for (int o = 16; o; o >>= 1) sm += __shfl_xor_sync(0xFFFFFFFFu, sm, o);
    float inv = 1.0f / sm;
    #pragma unroll
    for (int i = 0; i < 16; i++) r[lane + 32 * i] = rnd_tf32(v[i] * inv);
}

// -------------------- launch --------------------
static float* sym_addr(const void* symbol)
{
    void* p = nullptr;
    cudaGetSymbolAddress(&p, symbol);
    return reinterpret_cast<float*>(p);
}

extern "C" void kernel_launch(void* const* d_in, const int* in_sizes, int n_in,
                              void* d_out, int out_size)
{
    const float* query = (const float*)d_in[0];
    const float* keyi  = (const float*)d_in[1];
    const float* value = (const float*)d_in[2];
    const float* w_in[3]  = { (const float*)d_in[3], (const float*)d_in[5], (const float*)d_in[7] };
    const float* w_out[3] = { (const float*)d_in[4], (const float*)d_in[6], (const float*)d_in[8] };
    const float* coef[3]  = { (const float*)d_in[9], (const float*)d_in[10], (const float*)d_in[11] };
    float* out = (float*)d_out;

    float* twoq   = sym_addr(g_twoq);
    float* threeq = sym_addr(g_threeq);
    float* qr  = sym_addr(g_qr);
    float* kr  = sym_addr(g_kr);
    float* vr  = sym_addr(g_vr);
    float* wr  = sym_addr(g_wr);
    float* Qb  = sym_addr(g_Q);
    float* Kb  = sym_addr(g_K);
    float* Vb  = sym_addr(g_V);
    float* Sb  = sym_addr(g_S);
    float* ctx = sym_addr(g_ctx);

    const float invs = 1.0f / sqrtf((float)HD);

    // dynamic smem sizes
    const int SM_NT = 3 * (128 * 20 + 128 * 20) * 4;   // 61440
    const int SM_NN = 3 * (128 * 20 + 16 * 136) * 4;   // 56832
    cudaFuncSetAttribute(mma_gemm<true, 1, false, false, false>, cudaFuncAttributeMaxDynamicSharedMemorySize, SM_NT);
    cudaFuncSetAttribute(mma_gemm<true, 0, false, true,  true >, cudaFuncAttributeMaxDynamicSharedMemorySize, SM_NT);
    cudaFuncSetAttribute(mma_gemm<false,2, false, false, true >, cudaFuncAttributeMaxDynamicSharedMemorySize, SM_NN);
    cudaFuncSetAttribute(mma_gemm<true, 3, false, false, false>, cudaFuncAttributeMaxDynamicSharedMemorySize, SM_NT);
    cudaFuncSetAttribute(mma_gemm<true, 3, true,  false, false>, cudaFuncAttributeMaxDynamicSharedMemorySize, SM_NT);

    // ---- pre-round raw inputs to tf32 grid ----
    {
        int n4 = MLB * DIM / 4;
        int nb = (n4 + 255) / 256;
        round_copy_kernel<<<nb, 256>>>(query, qr, n4);
        round_copy_kernel<<<nb, 256>>>(keyi,  kr, n4);
        round_copy_kernel<<<nb, 256>>>(value, vr, n4);
        int nwi = 2304 * 768 / 4, nwo = 768 * 768 / 4;
        for (int i = 0; i < 3; i++) {
            round_copy_kernel<<<(nwi + 255) / 256, 256>>>(w_in[i],  wr + (size_t)i * WSZ, nwi);
            round_copy_kernel<<<(nwo + 255) / 256, 256>>>(w_out[i], wr + (size_t)i * WSZ + 2304 * 768, nwo);
        }
        int nv4 = NR * NB * DIM / 4;
        copy_visual_kernel<<<(nv4 + 255) / 256, 256>>>(query, twoq, threeq);
        window_agg_kernel<<<dim3(TT, NB), 256>>>(query, twoq, threeq);
    }

    const float* qsrc[3] = { qr, twoq, threeq };
    dim3 gP(DIM / 128, MLB / 128, 1);       // (6,128)
    dim3 gS(LQ / 128, LQ / 128, BH);        // (4,4,256)
    dim3 gO(1, LQ / 128, BH);               // (1,4,256)

    for (int i = 0; i < 3; i++) {
        const float* wi = wr + (size_t)i * WSZ;
        const float* wo = wi + 2304 * 768;

        // Q/K/V projections -> [L,B,D] rounded
        mma_gemm<true, 1, false, false, false><<<gP, 256, SM_NT>>>(qsrc[i], wi, Qb,
            MLB, DIM, DIM, DIM, DIM, 0, 0, 0, invs, nullptr);
        mma_gemm<true, 1, false, false, false><<<gP, 256, SM_NT>>>(kr, wi + DIM * DIM, Kb,
            MLB, DIM, DIM, DIM, DIM, 0, 0, 0, 1.0f, nullptr);
        mma_gemm<true, 1, false, false, false><<<gP, 256, SM_NT>>>(vr, wi + 2 * DIM * DIM, Vb,
            MLB, DIM, DIM, DIM, DIM, 0, 0, 0, 1.0f, nullptr);

        // S = Q K^T per (b,h): A,B are [L,B,D] views with per-z col offset
        mma_gemm<true, 0, false, true, true><<<gS, 256, SM_NT>>>(Qb, Kb, Sb,
            LQ, LQ, HD, LDQ, LDQ, 0, 0, (size_t)LQ * LQ, 1.0f, nullptr);

        softmax_rows_kernel<<<BH * LQ / 8, 256>>>(Sb);

        // O = S V -> ctx [L,B,D]
        mma_gemm<false, 2, false, false, true><<<gO, 256, SM_NN>>>(Sb, Vb, ctx,
            LQ, HD, LQ, LQ, LDQ, (size_t)LQ * LQ, 0, 0, 1.0f, nullptr);

        // out (+)= coef * ctx @ w_out^T
        if (i == 0)
            mma_gemm<true, 3, false, false, false><<<gP, 256, SM_NT>>>(ctx, wo, out,
                MLB, DIM, DIM, DIM, DIM, 0, 0, 0, 1.0f, coef[i]);
        else
            mma_gemm<true, 3, true, false, false><<<gP, 256, SM_NT>>>(ctx, wo, out,
                MLB, DIM, DIM, DIM, DIM, 0, 0, 0, 1.0f, coef[i]);
    }
}

// round 4
// speedup vs baseline: 3.4181x; 1.0075x over previous
#include <cuda_runtime.h>
#include <math.h>
#include <stdint.h>

// Problem constants (fixed shapes)
#define LQ   512
#define NB   32
#define DIM  768
#define NH   8
#define HD   96
#define NR   196
#define TT   316               // text length
#define MLB  (LQ*NB)           // 16384
#define BH   (NB*NH)           // 256
#define LDQ  (NB*DIM)          // 24576 row stride of [L,B,D] per l
#define EPSW 1e-8f

#define WSZ  (2304*768 + 768*768)   // per-MHA rounded weights

// -------------------- device scratch --------------------
__device__ float g_twoq  [MLB*DIM];
__device__ float g_threeq[MLB*DIM];
__device__ float g_qr [MLB*DIM];
__device__ float g_kr [MLB*DIM];
__device__ float g_vr [MLB*DIM];
__device__ float g_wr [3*WSZ];
__device__ float g_Q  [MLB*DIM];              // [L,B,D] rounded
__device__ float g_K  [MLB*DIM];
__device__ float g_V  [MLB*DIM];
__device__ float g_S  [(size_t)BH*LQ*LQ];     // scores / probs
__device__ float g_ctx[MLB*DIM];

// -------------------- PTX helpers --------------------
__device__ __forceinline__ void cp_async16(float* sptr, const float* gptr, bool valid) {
    uint32_t sa = (uint32_t)__cvta_generic_to_shared(sptr);
    int sz = valid ? 16 : 0;
    asm volatile("cp.async.cg.shared.global [%0], [%1], 16, %2;\n"
                 :: "r"(sa), "l"(gptr), "r"(sz));
}
__device__ __forceinline__ void cp_commit() { asm volatile("cp.async.commit_group;\n"); }
__device__ __forceinline__ void cp_wait1()  { asm volatile("cp.async.wait_group 1;\n"); }

__device__ __forceinline__ float rnd_tf32(float x) {
    uint32_t r; asm("cvt.rna.tf32.f32 %0, %1;\n" : "=r"(r) : "f"(x));
    return __uint_as_float(r);
}
__device__ __forceinline__ void mma_tf32(float c[4], const uint32_t a[4], const uint32_t b[2]) {
    asm volatile("mma.sync.aligned.m16n8k8.row.col.f32.tf32.tf32.f32 "
        "{%0,%1,%2,%3}, {%4,%5,%6,%7}, {%8,%9}, {%0,%1,%2,%3};\n"
        : "+f"(c[0]), "+f"(c[1]), "+f"(c[2]), "+f"(c[3])
        : "r"(a[0]), "r"(a[1]), "r"(a[2]), "r"(a[3]), "r"(b[0]), "r"(b[1]));
}
__device__ __forceinline__ uint32_t fbits(float x) { return __float_as_uint(x); }

// -------------------- pre-round inputs to tf32 grid --------------------
__global__ void round_copy_kernel(const float* __restrict__ src,
                                  float* __restrict__ dst, int n4)
{
    int i = blockIdx.x * blockDim.x + threadIdx.x;
    if (i < n4) {
        float4 v = reinterpret_cast<const float4*>(src)[i];
        v.x = rnd_tf32(v.x); v.y = rnd_tf32(v.y);
        v.z = rnd_tf32(v.z); v.w = rnd_tf32(v.w);
        reinterpret_cast<float4*>(dst)[i] = v;
    }
}

// -------------------- visual tokens (rounded) into two_q/three_q --------------------
__global__ void copy_visual_kernel(const float* __restrict__ q,
                                   float* __restrict__ twoq,
                                   float* __restrict__ threeq)
{
    int i = blockIdx.x * blockDim.x + threadIdx.x;
    const int n = NR * NB * DIM / 4;
    if (i < n) {
        float4 v = reinterpret_cast<const float4*>(q)[i];
        v.x = rnd_tf32(v.x); v.y = rnd_tf32(v.y);
        v.z = rnd_tf32(v.z); v.w = rnd_tf32(v.w);
        reinterpret_cast<float4*>(twoq)[i]   = v;
        reinterpret_cast<float4*>(threeq)[i] = v;
    }
}

// -------------------- window aggregation (outputs rounded) --------------------
__global__ void window_agg_kernel(const float* __restrict__ q,
                                  float* __restrict__ twoq,
                                  float* __restrict__ threeq)
{
    int t = blockIdx.x;
    int b = blockIdx.y;
    int tid = threadIdx.x;

    __shared__ float xs[5][DIM];
    __shared__ float red[10][8];
    __shared__ float fin[10];

    #pragma unroll
    for (int w = 0; w < 5; w++) {
        int tw = t + w - 2;
        bool ok = (tw >= 0) && (tw < TT);
        const float* src = q + ((size_t)(NR + tw) * NB + b) * DIM;
        for (int c = tid; c < DIM; c += 256)
            xs[w][c] = ok ? src[c] : 0.0f;
    }
    __syncthreads();

    float p[10];
    #pragma unroll
    for (int k = 0; k < 10; k++) p[k] = 0.0f;

    for (int c = tid; c < DIM; c += 256) {
        float x0 = xs[0][c], x1 = xs[1][c], x2 = xs[2][c], x3 = xs[3][c], x4 = xs[4][c];
        p[0] += x0 * x0;  p[1] += x1 * x1;  p[2] += x2 * x2;
        p[3] += x3 * x3;  p[4] += x4 * x4;
        p[5] += x2 * x1;  p[6] += x2 * x3;
        p[7] += x3 * x0;  p[8] += x3 * x1;  p[9] += x3 * x4;
    }
    #pragma unroll
    for (int o = 16; o; o >>= 1) {
        #pragma unroll
        for (int k = 0; k < 10; k++)
            p[k] += __shfl_xor_sync(0xFFFFFFFFu, p[k], o);
    }
    int wid = tid >> 5, lane = tid & 31;
    if (lane == 0) {
        #pragma unroll
        for (int k = 0; k < 10; k++) red[k][wid] = p[k];
    }
    __syncthreads();
    if (tid < 10) {
        float s = 0.0f;
        #pragma unroll
        for (int w = 0; w < 8; w++) s += red[tid][w];
        fin[tid] = s;
    }
    __syncthreads();

    float n0 = fin[0], n1 = fin[1], n2 = fin[2], n3 = fin[3], n4 = fin[4];
    float in0 = 1.0f / fmaxf(sqrtf(n0), EPSW);
    float in1 = 1.0f / fmaxf(sqrtf(n1), EPSW);
    float in2 = 1.0f / fmaxf(sqrtf(n2), EPSW);
    float in3 = 1.0f / fmaxf(sqrtf(n3), EPSW);
    float in4 = 1.0f / fmaxf(sqrtf(n4), EPSW);

    float w2_1 = fin[5] * in2 * in1;
    float w2_2 = n2     * in2 * in2;
    float w2_3 = fin[6] * in2 * in3;
    float w3_0 = fin[7] * in3 * in0;
    float w3_1 = fin[8] * in3 * in1;
    float w3_2 = fin[6] * in3 * in2;
    float w3_3 = n3     * in3 * in3;
    float w3_4 = fin[9] * in3 * in4;

    size_t base = ((size_t)(NR + t) * NB + b) * DIM;
    for (int c = tid; c < DIM; c += 256) {
        float x0 = xs[0][c], x1 = xs[1][c], x2 = xs[2][c], x3 = xs[3][c], x4 = xs[4][c];
        twoq[base + c]   = rnd_tf32(w2_1 * x1 + w2_2 * x2 + w2_3 * x3);
        threeq[base + c] = rnd_tf32(w3_0 * x0 + w3_1 * x1 + w3_2 * x2 + w3_3 * x3 + w3_4 * x4);
    }
}

// -------------------- tf32 tensor-core GEMM (128 thr, 64x64 warp tiles) ----------
// C = A * op(B). A: [M,K] row-major (lda). BT: B [N,K] (NT) else [K,N] (NN).
// AZ/BZ: per-z base offset (z>>3)*DIM + (z&7)*HD ([L,B,D] Q/K/V views).
// Epilogues:
//  0: scores  C[z*sC + row*N + col] = acc*scale          (fp32, feeds softmax)
//  1: proj    C[row*DIM + col] = rnd(acc)                ([L,B,D] natural)
//  2: ctx     C[row*LDQ + zoff + col] = rnd(acc)         (per-(b,h) cols of [L,B,D])
//  3: final   C[row*N+col] = (ACCUM? old:0) + (*scale_ptr)*acc
template<bool BT, int EPI, bool ACCUM, bool AZ, bool BZ>
__global__ __launch_bounds__(128, 2)
void mma_gemm(const float* __restrict__ Ag, const float* __restrict__ Bg,
              float* __restrict__ Cg,
              int M, int N, int K, int lda, int ldb,
              size_t sA, size_t sB, size_t sC,
              float scale, const float* __restrict__ scale_ptr)
{
    constexpr int BM = 128, BN = 128, BK = 16, ST = 3;
    constexpr int AST  = BK + 4;          // [m][k] stride 20
    constexpr int BSTT = BK + 4;          // NT [n][k] stride 20
    constexpr int BSTN = BN + 8;          // NN [k][n] stride 136
    constexpr int AS_SZ = BM * AST;
    constexpr int BS_SZ = BT ? (BN * BSTT) : (BK * BSTN);

    extern __shared__ float dsm[];
    float* As = dsm;
    float* Bs = dsm + ST * AS_SZ;

    const int z = blockIdx.z;
    const size_t zoff = (size_t)(z >> 3) * DIM + (size_t)(z & 7) * HD;
    const float* A = Ag + (AZ ? zoff : (size_t)z * sA);
    const float* B = Bg + (BZ ? zoff : (size_t)z * sB);
    const int m0 = blockIdx.y * BM;
    const int n0 = blockIdx.x * BN;
    const int tid = threadIdx.x;
    const int lane = tid & 31;
    const int wid = tid >> 5;
    const int warp_m = (wid >> 1) * 64;   // 2 warps along M
    const int warp_n = (wid & 1) * 64;    // 2 warps along N
    const int gr = lane >> 2;
    const int tg = lane & 3;

    float acc[4][8][4];
    #pragma unroll
    for (int i = 0; i < 4; i++)
        #pragma unroll
        for (int j = 0; j < 8; j++)
            #pragma unroll
            for (int e = 0; e < 4; e++) acc[i][j][e] = 0.0f;

    const int nt = K / BK;

    auto load_tile = [&](int s, int kt) {
        int k0 = kt * BK;
        float* as = As + s * AS_SZ;
        float* bs = Bs + s * BS_SZ;
        #pragma unroll
        for (int r = 0; r < 4; r++) {
            int c = tid + 128 * r;
            int row = c >> 2, kq = c & 3;
            const float* g = A + (size_t)(m0 + row) * lda + k0 + kq * 4;
            cp_async16(&as[row * AST + kq * 4], g, true);
        }
        if (BT) {
            #pragma unroll
            for (int r = 0; r < 4; r++) {
                int c = tid + 128 * r;
                int row = c >> 2, kq = c & 3;
                bool v = (n0 + row) < N;
                const float* g = B + (size_t)(n0 + row) * ldb + k0 + kq * 4;
                cp_async16(&bs[row * BSTT + kq * 4], v ? g : B, v);
            }
        } else {
            #pragma unroll
            for (int r = 0; r < 4; r++) {
                int c = tid + 128 * r;
                int kr = c >> 5, nq = c & 31;
                bool v = (n0 + nq * 4) < N;
                const float* g = B + (size_t)(k0 + kr) * ldb + n0 + nq * 4;
                cp_async16(&bs[kr * BSTN + nq * 4], v ? g : B, v);
            }
        }
    };

    load_tile(0, 0); cp_commit();
    if (nt > 1) load_tile(1, 1);
    cp_commit();

    for (int kt = 0; kt < nt; kt++) {
        cp_wait1();
        __syncthreads();
        if (kt + 2 < nt) load_tile((kt + 2) % ST, kt + 2);
        cp_commit();

        const float* as = As + (kt % ST) * AS_SZ;
        const float* bs = Bs + (kt % ST) * BS_SZ;

        #pragma unroll
        for (int ks = 0; ks < 2; ks++) {
            int kb = ks * 8;
            uint32_t af[4][4];
            #pragma unroll
            for (int i = 0; i < 4; i++) {
                int rb = warp_m + i * 16 + gr;
                af[i][0] = fbits(as[(rb)     * AST + kb + tg]);
                af[i][1] = fbits(as[(rb + 8) * AST + kb + tg]);
                af[i][2] = fbits(as[(rb)     * AST + kb + tg + 4]);
                af[i][3] = fbits(as[(rb + 8) * AST + kb + tg + 4]);
            }
            uint32_t bf[8][2];
            #pragma unroll
            for (int j = 0; j < 8; j++) {
                int nb = warp_n + j * 8 + gr;
                if (BT) {
                    bf[j][0] = fbits(bs[nb * BSTT + kb + tg]);
                    bf[j][1] = fbits(bs[nb * BSTT + kb + tg + 4]);
                } else {
                    bf[j][0] = fbits(bs[(kb + tg)     * BSTN + nb]);
                    bf[j][1] = fbits(bs[(kb + tg + 4) * BSTN + nb]);
                }
            }
            #pragma unroll
            for (int i = 0; i < 4; i++)
                #pragma unroll
                for (int j = 0; j < 8; j++)
                    mma_tf32(acc[i][j], af[i], bf[j]);
        }
    }

    float sp = 1.0f;
    if (EPI == 3) sp = *scale_ptr;

    #pragma unroll
    for (int i = 0; i < 4; i++) {
        #pragma unroll
        for (int j = 0; j < 8; j++) {
            int row = m0 + warp_m + i * 16 + gr;
            int col = n0 + warp_n + j * 8 + 2 * tg;
            if (col >= N) continue;
            #pragma unroll
            for (int half = 0; half < 2; half++) {
                int r = row + half * 8;
                float v0 = acc[i][j][half * 2 + 0];
                float v1 = acc[i][j][half * 2 + 1];
                if (EPI == 0) {
                    float2 o = make_float2(v0 * scale, v1 * scale);
                    *reinterpret_cast<float2*>(&Cg[(size_t)z * sC + (size_t)r * N + col]) = o;
                } else if (EPI == 1) {
                    float2 o = make_float2(rnd_tf32(v0), rnd_tf32(v1));
                    *reinterpret_cast<float2*>(&Cg[(size_t)r * DIM + col]) = o;
                } else if (EPI == 2) {
                    float2 o = make_float2(rnd_tf32(v0), rnd_tf32(v1));
                    *reinterpret_cast<float2*>(&Cg[(size_t)r * LDQ + zoff + col]) = o;
                } else {
                    size_t idx = (size_t)r * N + col;
                    float2 o = make_float2(sp * v0, sp * v1);
                    if (ACCUM) {
                        float2 old = *reinterpret_cast<const float2*>(&Cg[idx]);
                        o.x += old.x; o.y += old.y;
                    }
                    *reinterpret_cast<float2*>(&Cg[idx]) = o;
                }
            }
        }
    }
}

// -------------------- row softmax (rounded outputs) --------------------
__global__ void softmax_rows_kernel(float* __restrict__ S)
{
    size_t row = (size_t)blockIdx.x * 8 + (threadIdx.x >> 5);
    int lane = threadIdx.x & 31;
    float* r = S + row * LQ;

    float v[16];
    float mx = -1e30f;
    #pragma unroll
    for (int i = 0; i < 16; i++) {
        v[i] = r[lane + 32 * i];
        mx = fmaxf(mx, v[i]);
    }
    #pragma unroll
    for (int o = 16; o; o >>= 1) mx = fmaxf(mx, __shfl_xor_sync(0xFFFFFFFFu, mx, o));
    float sm = 0.0f;
    #pragma unroll
    for (int i = 0; i < 16; i++) { v[i] = __expf(v[i] - mx); sm += v[i]; }
    #pragma unroll
    for (int o = 16; o; o >>= 1) sm += __shfl_xor_sync(0xFFFFFFFFu, sm, o);
    float inv = 1.0f / sm;
    #pragma unroll
    for (int i = 0; i < 16; i++) r[lane + 32 * i] = rnd_tf32(v[i] * inv);
}

// -------------------- launch --------------------
static float* sym_addr(const void* symbol)
{
    void* p = nullptr;
    cudaGetSymbolAddress(&p, symbol);
    return reinterpret_cast<float*>(p);
}

extern "C" void kernel_launch(void* const* d_in, const int* in_sizes, int n_in,
                              void* d_out, int out_size)
{
    const float* query = (const float*)d_in[0];
    const float* keyi  = (const float*)d_in[1];
    const float* value = (const float*)d_in[2];
    const float* w_in[3]  = { (const float*)d_in[3], (const float*)d_in[5], (const float*)d_in[7] };
    const float* w_out[3] = { (const float*)d_in[4], (const float*)d_in[6], (const float*)d_in[8] };
    const float* coef[3]  = { (const float*)d_in[9], (const float*)d_in[10], (const float*)d_in[11] };
    float* out = (float*)d_out;

    float* twoq   = sym_addr(g_twoq);
    float* threeq = sym_addr(g_threeq);
    float* qr  = sym_addr(g_qr);
    float* kr  = sym_addr(g_kr);
    float* vr  = sym_addr(g_vr);
    float* wr  = sym_addr(g_wr);
    float* Qb  = sym_addr(g_Q);
    float* Kb  = sym_addr(g_K);
    float* Vb  = sym_addr(g_V);
    float* Sb  = sym_addr(g_S);
    float* ctx = sym_addr(g_ctx);

    const float invs = 1.0f / sqrtf((float)HD);

    const int SM_NT = 3 * (128 * 20 + 128 * 20) * 4;   // 61440
    const int SM_NN = 3 * (128 * 20 + 16 * 136) * 4;   // 56832
    cudaFuncSetAttribute(mma_gemm<true, 1, false, false, false>, cudaFuncAttributeMaxDynamicSharedMemorySize, SM_NT);
    cudaFuncSetAttribute(mma_gemm<true, 0, false, true,  true >, cudaFuncAttributeMaxDynamicSharedMemorySize, SM_NT);
    cudaFuncSetAttribute(mma_gemm<false,2, false, false, true >, cudaFuncAttributeMaxDynamicSharedMemorySize, SM_NN);
    cudaFuncSetAttribute(mma_gemm<true, 3, false, false, false>, cudaFuncAttributeMaxDynamicSharedMemorySize, SM_NT);
    cudaFuncSetAttribute(mma_gemm<true, 3, true,  false, false>, cudaFuncAttributeMaxDynamicSharedMemorySize, SM_NT);

    // ---- pre-round raw inputs to tf32 grid ----
    {
        int n4 = MLB * DIM / 4;
        int nb = (n4 + 255) / 256;
        round_copy_kernel<<<nb, 256>>>(query, qr, n4);
        round_copy_kernel<<<nb, 256>>>(keyi,  kr, n4);
        round_copy_kernel<<<nb, 256>>>(value, vr, n4);
        int nwi = 2304 * 768 / 4, nwo = 768 * 768 / 4;
        for (int i = 0; i < 3; i++) {
            round_copy_kernel<<<(nwi + 255) / 256, 256>>>(w_in[i],  wr + (size_t)i * WSZ, nwi);
            round_copy_kernel<<<(nwo + 255) / 256, 256>>>(w_out[i], wr + (size_t)i * WSZ + 2304 * 768, nwo);
        }
        int nv4 = NR * NB * DIM / 4;
        copy_visual_kernel<<<(nv4 + 255) / 256, 256>>>(query, twoq, threeq);
        window_agg_kernel<<<dim3(TT, NB), 256>>>(query, twoq, threeq);
    }

    const float* qsrc[3] = { qr, twoq, threeq };
    dim3 gP(DIM / 128, MLB / 128, 1);       // (6,128)
    dim3 gS(LQ / 128, LQ / 128, BH);        // (4,4,256)
    dim3 gO(1, LQ / 128, BH);               // (1,4,256)

    for (int i = 0; i < 3; i++) {
        const float* wi = wr + (size_t)i * WSZ;
        const float* wo = wi + 2304 * 768;

        // Q/K/V projections -> [L,B,D] rounded (Q scale folded into score epilogue)
        mma_gemm<true, 1, false, false, false><<<gP, 128, SM_NT>>>(qsrc[i], wi, Qb,
            MLB, DIM, DIM, DIM, DIM, 0, 0, 0, 1.0f, nullptr);
        mma_gemm<true, 1, false, false, false><<<gP, 128, SM_NT>>>(kr, wi + DIM * DIM, Kb,
            MLB, DIM, DIM, DIM, DIM, 0, 0, 0, 1.0f, nullptr);
        mma_gemm<true, 1, false, false, false><<<gP, 128, SM_NT>>>(vr, wi + 2 * DIM * DIM, Vb,
            MLB, DIM, DIM, DIM, DIM, 0, 0, 0, 1.0f, nullptr);

        // S = (Q K^T)/sqrt(hd) per (b,h)
        mma_gemm<true, 0, false, true, true><<<gS, 128, SM_NT>>>(Qb, Kb, Sb,
            LQ, LQ, HD, LDQ, LDQ, 0, 0, (size_t)LQ * LQ, invs, nullptr);

        softmax_rows_kernel<<<BH * LQ / 8, 256>>>(Sb);

        // O = S V -> ctx [L,B,D]
        mma_gemm<false, 2, false, false, true><<<gO, 128, SM_NN>>>(Sb, Vb, ctx,
            LQ, HD, LQ, LQ, LDQ, (size_t)LQ * LQ, 0, 0, 1.0f, nullptr);

        // out (+)= coef * ctx @ w_out^T
        if (i == 0)
            mma_gemm<true, 3, false, false, false><<<gP, 128, SM_NT>>>(ctx, wo, out,
                MLB, DIM, DIM, DIM, DIM, 0, 0, 0, 1.0f, coef[i]);
        else
            mma_gemm<true, 3, true, false, false><<<gP, 128, SM_NT>>>(ctx, wo, out,
                MLB, DIM, DIM, DIM, DIM, 0, 0, 0, 1.0f, coef[i]);
    }
}

// round 7
// speedup vs baseline: 5.1009x; 1.4923x over previous
#include <cuda_runtime.h>
#include <cuda_fp16.h>
#include <math.h>
#include <stdint.h>

// Problem constants (fixed shapes)
#define LQ   512
#define NB   32
#define DIM  768
#define NH   8
#define HD   96
#define NR   196
#define TT   316               // text length
#define MLB  (LQ*NB)           // 16384
#define BH   (NB*NH)           // 256
#define LDQ  (NB*DIM)          // 24576 row stride of [L,B,D] per l
#define EPSW 1e-8f

#define WSZ  (2304*768 + 768*768)   // per-MHA fp16 weights (w_in + w_out)

// -------------------- device scratch --------------------
__device__ __half g_qh [MLB*DIM];
__device__ __half g_kh [MLB*DIM];
__device__ __half g_vh [MLB*DIM];
__device__ __half g_twoq  [MLB*DIM];
__device__ __half g_threeq[MLB*DIM];
__device__ __half g_wh [3*WSZ];
__device__ __half g_Qh [MLB*DIM];             // [L,B,D] fp16 proj
__device__ __half g_Kh [MLB*DIM];
__device__ float  g_V  [MLB*DIM];             // fp32 V proj (tf32-RN rounded)
__device__ float  g_S  [(size_t)BH*LQ*LQ];    // scores / probs
__device__ __half g_ctx[MLB*DIM];             // fp16 attn output

// -------------------- PTX helpers --------------------
__device__ __forceinline__ void cp16(uint32_t dst, const void* gptr) {
    asm volatile("cp.async.cg.shared.global [%0], [%1], 16;\n" :: "r"(dst), "l"(gptr));
}
__device__ __forceinline__ void cp16f(float* sptr, const float* gptr, bool valid) {
    uint32_t sa = (uint32_t)__cvta_generic_to_shared(sptr);
    int sz = valid ? 16 : 0;
    asm volatile("cp.async.cg.shared.global [%0], [%1], 16, %2;\n"
                 :: "r"(sa), "l"(gptr), "r"(sz));
}
__device__ __forceinline__ void cp_commit() { asm volatile("cp.async.commit_group;\n"); }
__device__ __forceinline__ void cp_wait1()  { asm volatile("cp.async.wait_group 1;\n"); }

__device__ __forceinline__ float rnd_tf32(float x) {
    uint32_t r; asm("cvt.rna.tf32.f32 %0, %1;\n" : "=r"(r) : "f"(x));
    return __uint_as_float(r);
}
__device__ __forceinline__ void mma_f16(float c[4], const uint32_t a[4], const uint32_t b[2]) {
    asm volatile("mma.sync.aligned.m16n8k16.row.col.f32.f16.f16.f32 "
        "{%0,%1,%2,%3}, {%4,%5,%6,%7}, {%8,%9}, {%0,%1,%2,%3};\n"
        : "+f"(c[0]), "+f"(c[1]), "+f"(c[2]), "+f"(c[3])
        : "r"(a[0]), "r"(a[1]), "r"(a[2]), "r"(a[3]), "r"(b[0]), "r"(b[1]));
}
__device__ __forceinline__ void mma_tf32(float c[4], const uint32_t a[4], const uint32_t b[2]) {
    asm volatile("mma.sync.aligned.m16n8k8.row.col.f32.tf32.tf32.f32 "
        "{%0,%1,%2,%3}, {%4,%5,%6,%7}, {%8,%9}, {%0,%1,%2,%3};\n"
        : "+f"(c[0]), "+f"(c[1]), "+f"(c[2]), "+f"(c[3])
        : "r"(a[0]), "r"(a[1]), "r"(a[2]), "r"(a[3]), "r"(b[0]), "r"(b[1]));
}
__device__ __forceinline__ uint32_t fbits(float x) { return __float_as_uint(x); }

// -------------------- fp32 -> fp16 conversion --------------------
__global__ void cvt_half_kernel(const float* __restrict__ src,
                                __half* __restrict__ dst, int n4)
{
    int i = blockIdx.x * blockDim.x + threadIdx.x;
    if (i < n4) {
        float4 v = reinterpret_cast<const float4*>(src)[i];
        __half2* d = reinterpret_cast<__half2*>(dst) + 2 * i;
        d[0] = __floats2half2_rn(v.x, v.y);
        d[1] = __floats2half2_rn(v.z, v.w);
    }
}

// -------------------- visual tokens -> two_q/three_q (fp16) --------------------
__global__ void copy_visual_kernel(const float* __restrict__ q,
                                   __half* __restrict__ twoq,
                                   __half* __restrict__ threeq)
{
    int i = blockIdx.x * blockDim.x + threadIdx.x;
    const int n = NR * NB * DIM / 4;
    if (i < n) {
        float4 v = reinterpret_cast<const float4*>(q)[i];
        __half2 h0 = __floats2half2_rn(v.x, v.y);
        __half2 h1 = __floats2half2_rn(v.z, v.w);
        reinterpret_cast<__half2*>(twoq)[2 * i]     = h0;
        reinterpret_cast<__half2*>(twoq)[2 * i + 1] = h1;
        reinterpret_cast<__half2*>(threeq)[2 * i]     = h0;
        reinterpret_cast<__half2*>(threeq)[2 * i + 1] = h1;
    }
}

// -------------------- window aggregation (fp16 outputs) --------------------
__global__ void window_agg_kernel(const float* __restrict__ q,
                                  __half* __restrict__ twoq,
                                  __half* __restrict__ threeq)
{
    int t = blockIdx.x;
    int b = blockIdx.y;
    int tid = threadIdx.x;

    __shared__ float xs[5][DIM];
    __shared__ float red[10][8];
    __shared__ float fin[10];

    #pragma unroll
    for (int w = 0; w < 5; w++) {
        int tw = t + w - 2;
        bool ok = (tw >= 0) && (tw < TT);
        const float* src = q + ((size_t)(NR + tw) * NB + b) * DIM;
        for (int c = tid; c < DIM; c += 256)
            xs[w][c] = ok ? src[c] : 0.0f;
    }
    __syncthreads();

    float p[10];
    #pragma unroll
    for (int k = 0; k < 10; k++) p[k] = 0.0f;

    for (int c = tid; c < DIM; c += 256) {
        float x0 = xs[0][c], x1 = xs[1][c], x2 = xs[2][c], x3 = xs[3][c], x4 = xs[4][c];
        p[0] += x0 * x0;  p[1] += x1 * x1;  p[2] += x2 * x2;
        p[3] += x3 * x3;  p[4] += x4 * x4;
        p[5] += x2 * x1;  p[6] += x2 * x3;
        p[7] += x3 * x0;  p[8] += x3 * x1;  p[9] += x3 * x4;
    }
    #pragma unroll
    for (int o = 16; o; o >>= 1) {
        #pragma unroll
        for (int k = 0; k < 10; k++)
            p[k] += __shfl_xor_sync(0xFFFFFFFFu, p[k], o);
    }
    int wid = tid >> 5, lane = tid & 31;
    if (lane == 0) {
        #pragma unroll
        for (int k = 0; k < 10; k++) red[k][wid] = p[k];
    }
    __syncthreads();
    if (tid < 10) {
        float s = 0.0f;
        #pragma unroll
        for (int w = 0; w < 8; w++) s += red[tid][w];
        fin[tid] = s;
    }
    __syncthreads();

    float n0 = fin[0], n1 = fin[1], n2 = fin[2], n3 = fin[3], n4 = fin[4];
    float in0 = 1.0f / fmaxf(sqrtf(n0), EPSW);
    float in1 = 1.0f / fmaxf(sqrtf(n1), EPSW);
    float in2 = 1.0f / fmaxf(sqrtf(n2), EPSW);
    float in3 = 1.0f / fmaxf(sqrtf(n3), EPSW);
    float in4 = 1.0f / fmaxf(sqrtf(n4), EPSW);

    float w2_1 = fin[5] * in2 * in1;
    float w2_2 = n2     * in2 * in2;
    float w2_3 = fin[6] * in2 * in3;
    float w3_0 = fin[7] * in3 * in0;
    float w3_1 = fin[8] * in3 * in1;
    float w3_2 = fin[6] * in3 * in2;
    float w3_3 = n3     * in3 * in3;
    float w3_4 = fin[9] * in3 * in4;

    size_t base = ((size_t)(NR + t) * NB + b) * DIM;
    for (int c = tid; c < DIM; c += 256) {
        float x0 = xs[0][c], x1 = xs[1][c], x2 = xs[2][c], x3 = xs[3][c], x4 = xs[4][c];
        twoq[base + c]   = __float2half(w2_1 * x1 + w2_2 * x2 + w2_3 * x3);
        threeq[base + c] = __float2half(w3_0 * x0 + w3_1 * x1 + w3_2 * x2 + w3_3 * x3 + w3_4 * x4);
    }
}

// ==================== fp16 NT GEMM (m16n8k16) ====================
// C = A[M,K] * B[N,K]^T, A/B fp16, fp32 accum. CTA 128x128, BK=32, 8 warps 32x64.
// AZ/BZ: per-z element offset (z>>3)*DIM + (z&7)*HD into [L,B,D] half views.
// EPI 0: scores  Cf[z*sC + r*N + col] = acc*scale
// EPI 1: proj    Ch[r*N + col] = half(acc)
// EPI 2: V proj  Cf[r*N + col] = rnd_tf32(acc)   (RN to tf32 grid for SV GEMM)
// EPI 3: final   Cf[r*N + col] = (ACCUM?old:0) + (*coef)*acc
template<int EPI, bool ACCUM, bool AZ, bool BZ>
__global__ __launch_bounds__(256, 2)
void hgemm_nt(const __half* __restrict__ Ag, const __half* __restrict__ Bg,
              float* __restrict__ Cf, __half* __restrict__ Ch,
              int M, int N, int K, int lda, int ldb, size_t sC,
              float scale, const float* __restrict__ coef)
{
    constexpr int BM = 128, BN = 128, BK = 32, ST = 3;
    constexpr int AST = BK + 8;           // 40 halves (u32-stride 20 -> conflict-free frags)
    constexpr int TS  = BM * AST;         // 5120 halves per tile

    extern __shared__ __half hsm[];
    __half* As = hsm;                     // [ST][TS]
    __half* Bs = hsm + ST * TS;

    const int z = blockIdx.z;
    const size_t zoff = (size_t)(z >> 3) * DIM + (size_t)(z & 7) * HD;
    const __half* A = Ag + (AZ ? zoff : 0);
    const __half* B = Bg + (BZ ? zoff : 0);
    const int m0 = blockIdx.y * BM;
    const int n0 = blockIdx.x * BN;
    const int tid = threadIdx.x;
    const int lane = tid & 31;
    const int wid = tid >> 5;
    const int warp_m = (wid & 3) * 32;    // 4 warps along M
    const int warp_n = (wid >> 2) * 64;   // 2 warps along N
    const int gr = lane >> 2;             // 0..7
    const int tg = lane & 3;              // 0..3

    float acc[2][8][4];
    #pragma unroll
    for (int i = 0; i < 2; i++)
        #pragma unroll
        for (int j = 0; j < 8; j++)
            #pragma unroll
            for (int e = 0; e < 4; e++) acc[i][j][e] = 0.0f;

    const int nt = K / BK;

    uint32_t as_sh = (uint32_t)__cvta_generic_to_shared(As);
    uint32_t bs_sh = (uint32_t)__cvta_generic_to_shared(Bs);

    auto load_tile = [&](int s, int kt) {
        int k0 = kt * BK;
        #pragma unroll
        for (int r = 0; r < 2; r++) {
            int c = tid + 256 * r;
            int row = c >> 2, ch = c & 3;          // 4 chunks of 8 halves per row
            const __half* g = A + (size_t)(m0 + row) * lda + k0 + ch * 8;
            cp16(as_sh + (s * TS + row * AST + ch * 8) * 2, g);
        }
        #pragma unroll
        for (int r = 0; r < 2; r++) {
            int c = tid + 256 * r;
            int row = c >> 2, ch = c & 3;
            const __half* g = B + (size_t)(n0 + row) * ldb + k0 + ch * 8;
            cp16(bs_sh + (s * TS + row * AST + ch * 8) * 2, g);
        }
    };

    load_tile(0, 0); cp_commit();
    if (nt > 1) load_tile(1, 1);
    cp_commit();

    for (int kt = 0; kt < nt; kt++) {
        cp_wait1();
        __syncthreads();
        if (kt + 2 < nt) load_tile((kt + 2) % ST, kt + 2);
        cp_commit();

        const uint32_t* au = reinterpret_cast<const uint32_t*>(As + (kt % ST) * TS);
        const uint32_t* bu = reinterpret_cast<const uint32_t*>(Bs + (kt % ST) * TS);

        #pragma unroll
        for (int ks = 0; ks < 2; ks++) {           // two k16 steps per BK=32
            int kb = ks * 8;                       // u32 offset within row (20 per row)
            uint32_t af[2][4];
            #pragma unroll
            for (int i = 0; i < 2; i++) {
                int rb = warp_m + i * 16 + gr;
                af[i][0] = au[rb * 20 + kb + tg];
                af[i][1] = au[(rb + 8) * 20 + kb + tg];
                af[i][2] = au[rb * 20 + kb + tg + 4];
                af[i][3] = au[(rb + 8) * 20 + kb + tg + 4];
            }
            uint32_t bf[8][2];
            #pragma unroll
            for (int j = 0; j < 8; j++) {
                int nb = warp_n + j * 8 + gr;
                bf[j][0] = bu[nb * 20 + kb + tg];
                bf[j][1] = bu[nb * 20 + kb + tg + 4];
            }
            #pragma unroll
            for (int i = 0; i < 2; i++)
                #pragma unroll
                for (int j = 0; j < 8; j++)
                    mma_f16(acc[i][j], af[i], bf[j]);
        }
        __syncthreads();
    }

    float cfv = 1.0f;
    if (EPI == 3) cfv = *coef;

    #pragma unroll
    for (int i = 0; i < 2; i++) {
        #pragma unroll
        for (int j = 0; j < 8; j++) {
            int row = m0 + warp_m + i * 16 + gr;
            int col = n0 + warp_n + j * 8 + 2 * tg;
            #pragma unroll
            for (int half_ = 0; half_ < 2; half_++) {
                int r = row + half_ * 8;
                float v0 = acc[i][j][half_ * 2 + 0];
                float v1 = acc[i][j][half_ * 2 + 1];
                if (EPI == 0) {
                    float2 o = make_float2(v0 * scale, v1 * scale);
                    *reinterpret_cast<float2*>(&Cf[(size_t)z * sC + (size_t)r * N + col]) = o;
                } else if (EPI == 1) {
                    *reinterpret_cast<__half2*>(&Ch[(size_t)r * N + col]) =
                        __floats2half2_rn(v0, v1);
                } else if (EPI == 2) {
                    *reinterpret_cast<float2*>(&Cf[(size_t)r * N + col]) =
                        make_float2(rnd_tf32(v0), rnd_tf32(v1));
                } else {
                    size_t idx = (size_t)r * N + col;
                    float2 o = make_float2(cfv * v0, cfv * v1);
                    if (ACCUM) {
                        float2 old = *reinterpret_cast<const float2*>(&Cf[idx]);
                        o.x += old.x; o.y += old.y;
                    }
                    *reinterpret_cast<float2*>(&Cf[idx]) = o;
                }
            }
        }
    }
}

// -------------------- tf32 NN GEMM: O = S·V -> ctx (fp16) --------------------
// A = probs [LQ,LQ] fp32 tf32-rounded, B = V [L,B,D] fp32 tf32-rounded.
__global__ __launch_bounds__(128, 2)
void sv_gemm(const float* __restrict__ Ag, const float* __restrict__ Bg,
             __half* __restrict__ Ch)
{
    constexpr int BM = 128, BN = 128, BK = 16, ST = 3;
    constexpr int AST  = BK + 4;
    constexpr int BSTN = BN + 8;
    constexpr int AS_SZ = BM * AST;
    constexpr int BS_SZ = BK * BSTN;
    const int N = HD, K = LQ;

    extern __shared__ float dsmf[];
    float* As = dsmf;
    float* Bs = dsmf + ST * AS_SZ;

    const int z = blockIdx.z;
    const size_t zoff = (size_t)(z >> 3) * DIM + (size_t)(z & 7) * HD;
    const float* A = Ag + (size_t)z * LQ * LQ;
    const float* B = Bg + zoff;
    const int m0 = blockIdx.y * BM;
    const int tid = threadIdx.x;
    const int lane = tid & 31;
    const int wid = tid >> 5;
    const int warp_m = (wid >> 1) * 64;
    const int warp_n = (wid & 1) * 64;
    const int gr = lane >> 2;
    const int tg = lane & 3;

    float acc[4][8][4];
    #pragma unroll
    for (int i = 0; i < 4; i++)
        #pragma unroll
        for (int j = 0; j < 8; j++)
            #pragma unroll
            for (int e = 0; e < 4; e++) acc[i][j][e] = 0.0f;

    const int nt = K / BK;

    auto load_tile = [&](int s, int kt) {
        int k0 = kt * BK;
        float* as = As + s * AS_SZ;
        float* bs = Bs + s * BS_SZ;
        #pragma unroll
        for (int r = 0; r < 4; r++) {
            int c = tid + 128 * r;
            int row = c >> 2, kq = c & 3;
            const float* g = A + (size_t)(m0 + row) * LQ + k0 + kq * 4;
            cp16f(&as[row * AST + kq * 4], g, true);
        }
        #pragma unroll
        for (int r = 0; r < 4; r++) {
            int c = tid + 128 * r;
            int kr = c >> 5, nq = c & 31;
            bool v = (nq * 4) < N;
            const float* g = B + (size_t)(k0 + kr) * LDQ + nq * 4;
            cp16f(&bs[kr * BSTN + nq * 4], v ? g : B, v);
        }
    };

    load_tile(0, 0); cp_commit();
    load_tile(1, 1); cp_commit();

    for (int kt = 0; kt < nt; kt++) {
        cp_wait1();
        __syncthreads();
        if (kt + 2 < nt) load_tile((kt + 2) % ST, kt + 2);
        cp_commit();

        const float* as = As + (kt % ST) * AS_SZ;
        const float* bs = Bs + (kt % ST) * BS_SZ;

        #pragma unroll
        for (int ks = 0; ks < 2; ks++) {
            int kb = ks * 8;
            uint32_t af[4][4];
            #pragma unroll
            for (int i = 0; i < 4; i++) {
                int rb = warp_m + i * 16 + gr;
                af[i][0] = fbits(as[(rb)     * AST + kb + tg]);
                af[i][1] = fbits(as[(rb + 8) * AST + kb + tg]);
                af[i][2] = fbits(as[(rb)     * AST + kb + tg + 4]);
                af[i][3] = fbits(as[(rb + 8) * AST + kb + tg + 4]);
            }
            uint32_t bf[8][2];
            #pragma unroll
            for (int j = 0; j < 8; j++) {
                int nb = warp_n + j * 8 + gr;
                bf[j][0] = fbits(bs[(kb + tg)     * BSTN + nb]);
                bf[j][1] = fbits(bs[(kb + tg + 4) * BSTN + nb]);
            }
            #pragma unroll
            for (int i = 0; i < 4; i++)
                #pragma unroll
                for (int j = 0; j < 8; j++)
                    mma_tf32(acc[i][j], af[i], bf[j]);
        }
        __syncthreads();
    }

    #pragma unroll
    for (int i = 0; i < 4; i++) {
        #pragma unroll
        for (int j = 0; j < 8; j++) {
            int row = m0 + warp_m + i * 16 + gr;
            int col = warp_n + j * 8 + 2 * tg;
            if (col >= N) continue;
            #pragma unroll
            for (int half_ = 0; half_ < 2; half_++) {
                int r = row + half_ * 8;
                float v0 = acc[i][j][half_ * 2 + 0];
                float v1 = acc[i][j][half_ * 2 + 1];
                *reinterpret_cast<__half2*>(&Ch[(size_t)r * LDQ + zoff + col]) =
                    __floats2half2_rn(v0, v1);
            }
        }
    }
}

// -------------------- row softmax (RN-rounded tf32 outputs) --------------------
__global__ void softmax_rows_kernel(float* __restrict__ S)
{
    size_t row = (size_t)blockIdx.x * 8 + (threadIdx.x >> 5);
    int lane = threadIdx.x & 31;
    float* r = S + row * LQ;

    float v[16];
    float mx = -1e30f;
    #pragma unroll
    for (int i = 0; i < 16; i++) {
        v[i] = r[lane + 32 * i];
        mx = fmaxf(mx, v[i]);
    }
    #pragma unroll
    for (int o = 16; o; o >>= 1) mx = fmaxf(mx, __shfl_xor_sync(0xFFFFFFFFu, mx, o));
    float sm = 0.0f;
    #pragma unroll
    for (int i = 0; i < 16; i++) { v[i] = __expf(v[i] - mx); sm += v[i]; }
    #pragma unroll
    for (int o = 16; o; o >>= 1) sm += __shfl_xor_sync(0xFFFFFFFFu, sm, o);
    float inv = 1.0f / sm;
    #pragma unroll
    for (int i = 0; i < 16; i++) r[lane + 32 * i] = rnd_tf32(v[i] * inv);
}

// -------------------- launch --------------------
template<typename T>
static T* sym_addr_t(const void* symbol)
{
    void* p = nullptr;
    cudaGetSymbolAddress(&p, symbol);
    return reinterpret_cast<T*>(p);
}

extern "C" void kernel_launch(void* const* d_in, const int* in_sizes, int n_in,
                              void* d_out, int out_size)
{
    const float* query = (const float*)d_in[0];
    const float* keyi  = (const float*)d_in[1];
    const float* value = (const float*)d_in[2];
    const float* w_in[3]  = { (const float*)d_in[3], (const float*)d_in[5], (const float*)d_in[7] };
    const float* w_out[3] = { (const float*)d_in[4], (const float*)d_in[6], (const float*)d_in[8] };
    const float* coef[3]  = { (const float*)d_in[9], (const float*)d_in[10], (const float*)d_in[11] };
    float* out = (float*)d_out;

    __half* qh  = sym_addr_t<__half>(g_qh);
    __half* kh  = sym_addr_t<__half>(g_kh);
    __half* vh  = sym_addr_t<__half>(g_vh);
    __half* twoq   = sym_addr_t<__half>(g_twoq);
    __half* threeq = sym_addr_t<__half>(g_threeq);
    __half* wh  = sym_addr_t<__half>(g_wh);
    __half* Qh  = sym_addr_t<__half>(g_Qh);
    __half* Kh  = sym_addr_t<__half>(g_Kh);
    float*  Vb  = sym_addr_t<float>(g_V);
    float*  Sb  = sym_addr_t<float>(g_S);
    __half* ctx = sym_addr_t<__half>(g_ctx);

    const float invs = 1.0f / sqrtf((float)HD);

    const int SM_H  = 3 * 2 * 128 * 40 * 2;                    // 61440 B (fp16 gemm)
    const int SM_SV = 3 * (128 * 20 + 16 * 136) * 4;           // 56832 B
    cudaFuncSetAttribute(hgemm_nt<0, false, true,  true >, cudaFuncAttributeMaxDynamicSharedMemorySize, SM_H);
    cudaFuncSetAttribute(hgemm_nt<1, false, false, false>, cudaFuncAttributeMaxDynamicSharedMemorySize, SM_H);
    cudaFuncSetAttribute(hgemm_nt<2, false, false, false>, cudaFuncAttributeMaxDynamicSharedMemorySize, SM_H);
    cudaFuncSetAttribute(hgemm_nt<3, false, false, false>, cudaFuncAttributeMaxDynamicSharedMemorySize, SM_H);
    cudaFuncSetAttribute(hgemm_nt<3, true,  false, false>, cudaFuncAttributeMaxDynamicSharedMemorySize, SM_H);
    cudaFuncSetAttribute(sv_gemm, cudaFuncAttributeMaxDynamicSharedMemorySize, SM_SV);

    // ---- fp32 -> fp16 conversions + window aggregation ----
    {
        int n4 = MLB * DIM / 4;
        int nb = (n4 + 255) / 256;
        cvt_half_kernel<<<nb, 256>>>(query, qh, n4);
        cvt_half_kernel<<<nb, 256>>>(keyi,  kh, n4);
        cvt_half_kernel<<<nb, 256>>>(value, vh, n4);
        int nwi = 2304 * 768 / 4, nwo = 768 * 768 / 4;
        for (int i = 0; i < 3; i++) {
            cvt_half_kernel<<<(nwi + 255) / 256, 256>>>(w_in[i],  wh + (size_t)i * WSZ, nwi);
            cvt_half_kernel<<<(nwo + 255) / 256, 256>>>(w_out[i], wh + (size_t)i * WSZ + 2304 * 768, nwo);
        }
        int nv4 = NR * NB * DIM / 4;
        copy_visual_kernel<<<(nv4 + 255) / 256, 256>>>(query, twoq, threeq);
        window_agg_kernel<<<dim3(TT, NB), 256>>>(query, twoq, threeq);
    }

    const __half* qsrc[3] = { qh, twoq, threeq };
    dim3 gP(DIM / 128, MLB / 128, 1);       // (6,128)
    dim3 gS(LQ / 128, LQ / 128, BH);        // (4,4,256)
    dim3 gO(1, LQ / 128, BH);               // (1,4,256)

    for (int i = 0; i < 3; i++) {
        const __half* wi = wh + (size_t)i * WSZ;
        const __half* wo = wi + 2304 * 768;

        // Q/K projections -> fp16 [L,B,D]; V -> fp32 (tf32 RN) [L,B,D]
        hgemm_nt<1, false, false, false><<<gP, 256, SM_H>>>(qsrc[i], wi, nullptr, Qh,
            MLB, DIM, DIM, DIM, DIM, 0, 1.0f, nullptr);
        hgemm_nt<1, false, false, false><<<gP, 256, SM_H>>>(kh, wi + DIM * DIM, nullptr, Kh,
            MLB, DIM, DIM, DIM, DIM, 0, 1.0f, nullptr);
        hgemm_nt<2, false, false, false><<<gP, 256, SM_H>>>(vh, wi + 2 * DIM * DIM, Vb, nullptr,
            MLB, DIM, DIM, DIM, DIM, 0, 1.0f, nullptr);

        // S = (Q K^T)/sqrt(hd) per (b,h)
        hgemm_nt<0, false, true, true><<<gS, 256, SM_H>>>(Qh, Kh, Sb, nullptr,
            LQ, LQ, HD, LDQ, LDQ, (size_t)LQ * LQ, invs, nullptr);

        softmax_rows_kernel<<<BH * LQ / 8, 256>>>(Sb);

        // O = S V -> ctx fp16 [L,B,D]
        sv_gemm<<<gO, 128, SM_SV>>>(Sb, Vb, ctx);

        // out (+)= coef * ctx @ w_out^T
        if (i == 0)
            hgemm_nt<3, false, false, false><<<gP, 256, SM_H>>>(ctx, wo, out, nullptr,
                MLB, DIM, DIM, DIM, DIM, 0, 1.0f, coef[i]);
        else
            hgemm_nt<3, true, false, false><<<gP, 256, SM_H>>>(ctx, wo, out, nullptr,
                MLB, DIM, DIM, DIM, DIM, 0, 1.0f, coef[i]);
    }
}

// round 8
// speedup vs baseline: 6.6891x; 1.3114x over previous
#include <cuda_runtime.h>
#include <cuda_fp16.h>
#include <math.h>
#include <stdint.h>

// Problem constants (fixed shapes)
#define LQ   512
#define NB   32
#define DIM  768
#define NH   8
#define HD   96
#define NR   196
#define TT   316               // text length
#define MLB  (LQ*NB)           // 16384
#define BH   (NB*NH)           // 256
#define LDQ  (NB*DIM)          // 24576 row stride of [L,B,D] per l
#define EPSW 1e-8f

#define WSZ  (2304*768 + 768*768)   // per-MHA fp16 weights (w_in + w_out)

// -------------------- device scratch --------------------
__device__ __half g_qh [MLB*DIM];
__device__ __half g_kh [MLB*DIM];
__device__ __half g_vh [MLB*DIM];
__device__ __half g_twoq  [MLB*DIM];
__device__ __half g_threeq[MLB*DIM];
__device__ __half g_wh [3*WSZ];
__device__ __half g_Qh [MLB*DIM];             // [L,B,D] fp16 Q proj
__device__ __half g_Kh [MLB*DIM];             // [L,B,D] fp16 K proj
__device__ __half g_Vh [MLB*DIM];             // [L,B,D] fp16 V proj
__device__ __half g_ctx[MLB*DIM];             // fp16 attn output

// -------------------- PTX helpers --------------------
__device__ __forceinline__ void cp16(uint32_t dst, const void* gptr) {
    asm volatile("cp.async.cg.shared.global [%0], [%1], 16;\n" :: "r"(dst), "l"(gptr));
}
__device__ __forceinline__ void cp_commit() { asm volatile("cp.async.commit_group;\n"); }
__device__ __forceinline__ void cp_wait1()  { asm volatile("cp.async.wait_group 1;\n"); }

__device__ __forceinline__ void mma_f16(float c[4], const uint32_t a[4],
                                        uint32_t b0, uint32_t b1) {
    asm volatile("mma.sync.aligned.m16n8k16.row.col.f32.f16.f16.f32 "
        "{%0,%1,%2,%3}, {%4,%5,%6,%7}, {%8,%9}, {%0,%1,%2,%3};\n"
        : "+f"(c[0]), "+f"(c[1]), "+f"(c[2]), "+f"(c[3])
        : "r"(a[0]), "r"(a[1]), "r"(a[2]), "r"(a[3]), "r"(b0), "r"(b1));
}
__device__ __forceinline__ void ldmx4t(uint32_t& r0, uint32_t& r1,
                                       uint32_t& r2, uint32_t& r3, uint32_t addr) {
    asm volatile("ldmatrix.sync.aligned.m8n8.x4.trans.shared.b16 {%0,%1,%2,%3}, [%4];"
        : "=r"(r0), "=r"(r1), "=r"(r2), "=r"(r3) : "r"(addr));
}
__device__ __forceinline__ uint32_t packh2(float lo, float hi) {
    __half2 h = __floats2half2_rn(lo, hi);
    return reinterpret_cast<uint32_t&>(h);
}

// -------------------- fp32 -> fp16 conversion --------------------
__global__ void cvt_half_kernel(const float* __restrict__ src,
                                __half* __restrict__ dst, int n4)
{
    int i = blockIdx.x * blockDim.x + threadIdx.x;
    if (i < n4) {
        float4 v = reinterpret_cast<const float4*>(src)[i];
        __half2* d = reinterpret_cast<__half2*>(dst) + 2 * i;
        d[0] = __floats2half2_rn(v.x, v.y);
        d[1] = __floats2half2_rn(v.z, v.w);
    }
}

// -------------------- visual tokens -> two_q/three_q (fp16) --------------------
__global__ void copy_visual_kernel(const float* __restrict__ q,
                                   __half* __restrict__ twoq,
                                   __half* __restrict__ threeq)
{
    int i = blockIdx.x * blockDim.x + threadIdx.x;
    const int n = NR * NB * DIM / 4;
    if (i < n) {
        float4 v = reinterpret_cast<const float4*>(q)[i];
        __half2 h0 = __floats2half2_rn(v.x, v.y);
        __half2 h1 = __floats2half2_rn(v.z, v.w);
        reinterpret_cast<__half2*>(twoq)[2 * i]     = h0;
        reinterpret_cast<__half2*>(twoq)[2 * i + 1] = h1;
        reinterpret_cast<__half2*>(threeq)[2 * i]     = h0;
        reinterpret_cast<__half2*>(threeq)[2 * i + 1] = h1;
    }
}

// -------------------- window aggregation (fp16 outputs) --------------------
__global__ void window_agg_kernel(const float* __restrict__ q,
                                  __half* __restrict__ twoq,
                                  __half* __restrict__ threeq)
{
    int t = blockIdx.x;
    int b = blockIdx.y;
    int tid = threadIdx.x;

    __shared__ float xs[5][DIM];
    __shared__ float red[10][8];
    __shared__ float fin[10];

    #pragma unroll
    for (int w = 0; w < 5; w++) {
        int tw = t + w - 2;
        bool ok = (tw >= 0) && (tw < TT);
        const float* src = q + ((size_t)(NR + tw) * NB + b) * DIM;
        for (int c = tid; c < DIM; c += 256)
            xs[w][c] = ok ? src[c] : 0.0f;
    }
    __syncthreads();

    float p[10];
    #pragma unroll
    for (int k = 0; k < 10; k++) p[k] = 0.0f;

    for (int c = tid; c < DIM; c += 256) {
        float x0 = xs[0][c], x1 = xs[1][c], x2 = xs[2][c], x3 = xs[3][c], x4 = xs[4][c];
        p[0] += x0 * x0;  p[1] += x1 * x1;  p[2] += x2 * x2;
        p[3] += x3 * x3;  p[4] += x4 * x4;
        p[5] += x2 * x1;  p[6] += x2 * x3;
        p[7] += x3 * x0;  p[8] += x3 * x1;  p[9] += x3 * x4;
    }
    #pragma unroll
    for (int o = 16; o; o >>= 1) {
        #pragma unroll
        for (int k = 0; k < 10; k++)
            p[k] += __shfl_xor_sync(0xFFFFFFFFu, p[k], o);
    }
    int wid = tid >> 5, lane = tid & 31;
    if (lane == 0) {
        #pragma unroll
        for (int k = 0; k < 10; k++) red[k][wid] = p[k];
    }
    __syncthreads();
    if (tid < 10) {
        float s = 0.0f;
        #pragma unroll
        for (int w = 0; w < 8; w++) s += red[tid][w];
        fin[tid] = s;
    }
    __syncthreads();

    float n0 = fin[0], n1 = fin[1], n2 = fin[2], n3 = fin[3], n4 = fin[4];
    float in0 = 1.0f / fmaxf(sqrtf(n0), EPSW);
    float in1 = 1.0f / fmaxf(sqrtf(n1), EPSW);
    float in2 = 1.0f / fmaxf(sqrtf(n2), EPSW);
    float in3 = 1.0f / fmaxf(sqrtf(n3), EPSW);
    float in4 = 1.0f / fmaxf(sqrtf(n4), EPSW);

    float w2_1 = fin[5] * in2 * in1;
    float w2_2 = n2     * in2 * in2;
    float w2_3 = fin[6] * in2 * in3;
    float w3_0 = fin[7] * in3 * in0;
    float w3_1 = fin[8] * in3 * in1;
    float w3_2 = fin[6] * in3 * in2;
    float w3_3 = n3     * in3 * in3;
    float w3_4 = fin[9] * in3 * in4;

    size_t base = ((size_t)(NR + t) * NB + b) * DIM;
    for (int c = tid; c < DIM; c += 256) {
        float x0 = xs[0][c], x1 = xs[1][c], x2 = xs[2][c], x3 = xs[3][c], x4 = xs[4][c];
        twoq[base + c]   = __float2half(w2_1 * x1 + w2_2 * x2 + w2_3 * x3);
        threeq[base + c] = __float2half(w3_0 * x0 + w3_1 * x1 + w3_2 * x2 + w3_3 * x3 + w3_4 * x4);
    }
}

// ==================== fp16 NT GEMM (m16n8k16) -- projections & final ====================
// EPI 1: proj   Ch[r*N + col] = half(acc)
// EPI 3: final  Cf[r*N + col] = (ACCUM?old:0) + (*coef)*acc
template<int EPI, bool ACCUM>
__global__ __launch_bounds__(256, 2)
void hgemm_nt(const __half* __restrict__ Ag, const __half* __restrict__ Bg,
              float* __restrict__ Cf, __half* __restrict__ Ch,
              int M, int N, int K, int lda, int ldb,
              const float* __restrict__ coef)
{
    constexpr int BM = 128, BN = 128, BK = 32, ST = 3;
    constexpr int AST = BK + 8;           // 40 halves (u32-stride 20 -> conflict-free frags)
    constexpr int TS  = BM * AST;

    extern __shared__ __half hsm[];
    __half* As = hsm;
    __half* Bs = hsm + ST * TS;

    const int m0 = blockIdx.y * BM;
    const int n0 = blockIdx.x * BN;
    const int tid = threadIdx.x;
    const int lane = tid & 31;
    const int wid = tid >> 5;
    const int warp_m = (wid & 3) * 32;
    const int warp_n = (wid >> 2) * 64;
    const int gr = lane >> 2;
    const int tg = lane & 3;

    float acc[2][8][4];
    #pragma unroll
    for (int i = 0; i < 2; i++)
        #pragma unroll
        for (int j = 0; j < 8; j++)
            #pragma unroll
            for (int e = 0; e < 4; e++) acc[i][j][e] = 0.0f;

    const int nt = K / BK;

    uint32_t as_sh = (uint32_t)__cvta_generic_to_shared(As);
    uint32_t bs_sh = (uint32_t)__cvta_generic_to_shared(Bs);

    auto load_tile = [&](int s, int kt) {
        int k0 = kt * BK;
        #pragma unroll
        for (int r = 0; r < 2; r++) {
            int c = tid + 256 * r;
            int row = c >> 2, ch = c & 3;
            const __half* g = Ag + (size_t)(m0 + row) * lda + k0 + ch * 8;
            cp16(as_sh + (s * TS + row * AST + ch * 8) * 2, g);
        }
        #pragma unroll
        for (int r = 0; r < 2; r++) {
            int c = tid + 256 * r;
            int row = c >> 2, ch = c & 3;
            const __half* g = Bg + (size_t)(n0 + row) * ldb + k0 + ch * 8;
            cp16(bs_sh + (s * TS + row * AST + ch * 8) * 2, g);
        }
    };

    load_tile(0, 0); cp_commit();
    if (nt > 1) load_tile(1, 1);
    cp_commit();

    for (int kt = 0; kt < nt; kt++) {
        cp_wait1();
        __syncthreads();
        if (kt + 2 < nt) load_tile((kt + 2) % ST, kt + 2);
        cp_commit();

        const uint32_t* au = reinterpret_cast<const uint32_t*>(As + (kt % ST) * TS);
        const uint32_t* bu = reinterpret_cast<const uint32_t*>(Bs + (kt % ST) * TS);

        #pragma unroll
        for (int ks = 0; ks < 2; ks++) {
            int kb = ks * 8;
            uint32_t af[2][4];
            #pragma unroll
            for (int i = 0; i < 2; i++) {
                int rb = warp_m + i * 16 + gr;
                af[i][0] = au[rb * 20 + kb + tg];
                af[i][1] = au[(rb + 8) * 20 + kb + tg];
                af[i][2] = au[rb * 20 + kb + tg + 4];
                af[i][3] = au[(rb + 8) * 20 + kb + tg + 4];
            }
            uint32_t bf[8][2];
            #pragma unroll
            for (int j = 0; j < 8; j++) {
                int nb = warp_n + j * 8 + gr;
                bf[j][0] = bu[nb * 20 + kb + tg];
                bf[j][1] = bu[nb * 20 + kb + tg + 4];
            }
            #pragma unroll
            for (int i = 0; i < 2; i++)
                #pragma unroll
                for (int j = 0; j < 8; j++)
                    mma_f16(acc[i][j], af[i], bf[j][0], bf[j][1]);
        }
        __syncthreads();
    }

    float cfv = 1.0f;
    if (EPI == 3) cfv = *coef;

    #pragma unroll
    for (int i = 0; i < 2; i++) {
        #pragma unroll
        for (int j = 0; j < 8; j++) {
            int row = m0 + warp_m + i * 16 + gr;
            int col = n0 + warp_n + j * 8 + 2 * tg;
            #pragma unroll
            for (int half_ = 0; half_ < 2; half_++) {
                int r = row + half_ * 8;
                float v0 = acc[i][j][half_ * 2 + 0];
                float v1 = acc[i][j][half_ * 2 + 1];
                if (EPI == 1) {
                    *reinterpret_cast<__half2*>(&Ch[(size_t)r * N + col]) =
                        __floats2half2_rn(v0, v1);
                } else {
                    size_t idx = (size_t)r * N + col;
                    float2 o = make_float2(cfv * v0, cfv * v1);
                    if (ACCUM) {
                        float2 old = *reinterpret_cast<const float2*>(&Cf[idx]);
                        o.x += old.x; o.y += old.y;
                    }
                    *reinterpret_cast<float2*>(&Cf[idx]) = o;
                }
            }
        }
    }
}

// ==================== fused flash attention ====================
// grid (LQ/128, BH). CTA: 256 thr (8 warps x 16 q-rows). Online softmax.
// Q/K/V: fp16 [L,B,D] views, per-z col offset. Out: ctx fp16 [L,B,D].
#define FSTR  104              // smem row stride (halves)
#define FSTRU 52               // in u32
#define FTILE (128*FSTR)       // halves per 128-row tile

__global__ __launch_bounds__(256)
void flash_kernel(const __half* __restrict__ Qg, const __half* __restrict__ Kg,
                  const __half* __restrict__ Vg, __half* __restrict__ Ch, float invs)
{
    extern __shared__ __half fsm[];
    __half* Qs = fsm;                    // [128][104]
    __half* Ks = fsm + FTILE;            // [2][128][104]
    __half* Vs = Ks + 2 * FTILE;         // [2][128][104]

    const int z = blockIdx.y;
    const size_t zoff = (size_t)(z >> 3) * DIM + (size_t)(z & 7) * HD;
    const int m0 = blockIdx.x * 128;
    const int tid = threadIdx.x;
    const int lane = tid & 31;
    const int wid = tid >> 5;
    const int gr = lane >> 2, tg = lane & 3;

    uint32_t qs_sh = (uint32_t)__cvta_generic_to_shared(Qs);
    uint32_t ks_sh = (uint32_t)__cvta_generic_to_shared(Ks);
    uint32_t vs_sh = (uint32_t)__cvta_generic_to_shared(Vs);

    // tile loader: 128 rows x 96 halves (12 chunks of 16B per row)
    auto load_t = [&](uint32_t dst_sh, const __half* src, int l0) {
        #pragma unroll
        for (int r = 0; r < 6; r++) {
            int c = tid + 256 * r;
            int row = c / 12, ch = c % 12;
            const __half* g = src + (size_t)(l0 + row) * LDQ + zoff + ch * 8;
            cp16(dst_sh + (row * FSTR + ch * 8) * 2, g);
        }
    };

    // prologue
    load_t(qs_sh, Qg, m0);
    load_t(ks_sh, Kg, 0);
    load_t(vs_sh, Vg, 0);
    cp_commit();
    load_t(ks_sh + FTILE * 2, Kg, 128);
    load_t(vs_sh + FTILE * 2, Vg, 128);
    cp_commit();

    uint32_t qfrag[6][4];
    float o[12][4];
    #pragma unroll
    for (int j = 0; j < 12; j++)
        #pragma unroll
        for (int e = 0; e < 4; e++) o[j][e] = 0.0f;
    float m0r = -1e30f, m1r = -1e30f, l0 = 0.0f, l1 = 0.0f;

    // per-lane ldmatrix address part: matrices (g&1)->k half, (g>>1)->n half
    const int lg = lane >> 3, li = lane & 7;
    const int laneoff = ((lg & 1) * 8 + li) * FSTR + (lg >> 1) * 8;

    #pragma unroll
    for (int kt = 0; kt < 4; kt++) {
        if (kt < 3) { asm volatile("cp.async.wait_group 1;\n"); }
        else        { asm volatile("cp.async.wait_group 0;\n"); }
        __syncthreads();

        if (kt == 0) {
            const uint32_t* qu = reinterpret_cast<const uint32_t*>(Qs);
            #pragma unroll
            for (int ks = 0; ks < 6; ks++) {
                int rb = wid * 16 + gr;
                qfrag[ks][0] = qu[rb * FSTRU + ks * 8 + tg];
                qfrag[ks][1] = qu[(rb + 8) * FSTRU + ks * 8 + tg];
                qfrag[ks][2] = qu[rb * FSTRU + ks * 8 + tg + 4];
                qfrag[ks][3] = qu[(rb + 8) * FSTRU + ks * 8 + tg + 4];
            }
        }

        const int st = kt & 1;
        const uint32_t* ku = reinterpret_cast<const uint32_t*>(Ks + st * FTILE);
        const uint32_t vbase = vs_sh + (st * FTILE + laneoff) * 2;

        // ---- S = Q K^T (16 x 128) ----
        float s[16][4];
        #pragma unroll
        for (int nf = 0; nf < 16; nf++)
            #pragma unroll
            for (int e = 0; e < 4; e++) s[nf][e] = 0.0f;
        #pragma unroll
        for (int ks = 0; ks < 6; ks++) {
            #pragma unroll
            for (int nf = 0; nf < 16; nf++) {
                int nb = nf * 8 + gr;
                uint32_t b0 = ku[nb * FSTRU + ks * 8 + tg];
                uint32_t b1 = ku[nb * FSTRU + ks * 8 + tg + 4];
                mma_f16(s[nf], qfrag[ks], b0, b1);
            }
        }

        // ---- online softmax ----
        float mx0 = -1e30f, mx1 = -1e30f;
        #pragma unroll
        for (int nf = 0; nf < 16; nf++) {
            s[nf][0] *= invs; s[nf][1] *= invs; s[nf][2] *= invs; s[nf][3] *= invs;
            mx0 = fmaxf(mx0, fmaxf(s[nf][0], s[nf][1]));
            mx1 = fmaxf(mx1, fmaxf(s[nf][2], s[nf][3]));
        }
        mx0 = fmaxf(mx0, __shfl_xor_sync(0xFFFFFFFFu, mx0, 1));
        mx0 = fmaxf(mx0, __shfl_xor_sync(0xFFFFFFFFu, mx0, 2));
        mx1 = fmaxf(mx1, __shfl_xor_sync(0xFFFFFFFFu, mx1, 1));
        mx1 = fmaxf(mx1, __shfl_xor_sync(0xFFFFFFFFu, mx1, 2));

        float mn0 = fmaxf(m0r, mx0), mn1 = fmaxf(m1r, mx1);
        float al0 = __expf(m0r - mn0), al1 = __expf(m1r - mn1);
        m0r = mn0; m1r = mn1;

        float rs0 = 0.0f, rs1 = 0.0f;
        uint32_t ph[32];
        #pragma unroll
        for (int nf = 0; nf < 16; nf++) {
            float p0 = __expf(s[nf][0] - mn0);
            float p1 = __expf(s[nf][1] - mn0);
            float p2 = __expf(s[nf][2] - mn1);
            float p3 = __expf(s[nf][3] - mn1);
            rs0 += p0 + p1; rs1 += p2 + p3;
            ph[2 * nf]     = packh2(p0, p1);
            ph[2 * nf + 1] = packh2(p2, p3);
        }
        rs0 += __shfl_xor_sync(0xFFFFFFFFu, rs0, 1);
        rs0 += __shfl_xor_sync(0xFFFFFFFFu, rs0, 2);
        rs1 += __shfl_xor_sync(0xFFFFFFFFu, rs1, 1);
        rs1 += __shfl_xor_sync(0xFFFFFFFFu, rs1, 2);
        l0 = l0 * al0 + rs0;
        l1 = l1 * al1 + rs1;

        #pragma unroll
        for (int j = 0; j < 12; j++) {
            o[j][0] *= al0; o[j][1] *= al0;
            o[j][2] *= al1; o[j][3] *= al1;
        }

        // ---- O += P V (P: 16x128 fp16 frags from ph; V via ldmatrix.trans) ----
        #pragma unroll
        for (int s8 = 0; s8 < 8; s8++) {
            const uint32_t* a = &ph[4 * s8];
            #pragma unroll
            for (int np = 0; np < 6; np++) {
                uint32_t r0, r1, r2, r3;
                ldmx4t(r0, r1, r2, r3, vbase + (s8 * 16 * FSTR + np * 16) * 2);
                mma_f16(o[2 * np],     a, r0, r1);
                mma_f16(o[2 * np + 1], a, r2, r3);
            }
        }

        __syncthreads();
        if (kt + 2 < 4) {
            load_t(ks_sh + st * FTILE * 2, Kg, (kt + 2) * 128);
            load_t(vs_sh + st * FTILE * 2, Vg, (kt + 2) * 128);
        }
        cp_commit();
    }

    // ---- normalize + write ctx ----
    float il0 = 1.0f / l0, il1 = 1.0f / l1;
    int r0 = m0 + wid * 16 + gr;
    int r1 = r0 + 8;
    #pragma unroll
    for (int j = 0; j < 12; j++) {
        int col = j * 8 + 2 * tg;
        *reinterpret_cast<__half2*>(&Ch[(size_t)r0 * LDQ + zoff + col]) =
            __floats2half2_rn(o[j][0] * il0, o[j][1] * il0);
        *reinterpret_cast<__half2*>(&Ch[(size_t)r1 * LDQ + zoff + col]) =
            __floats2half2_rn(o[j][2] * il1, o[j][3] * il1);
    }
}

// -------------------- launch --------------------
template<typename T>
static T* sym_addr_t(const void* symbol)
{
    void* p = nullptr;
    cudaGetSymbolAddress(&p, symbol);
    return reinterpret_cast<T*>(p);
}

extern "C" void kernel_launch(void* const* d_in, const int* in_sizes, int n_in,
                              void* d_out, int out_size)
{
    const float* query = (const float*)d_in[0];
    const float* keyi  = (const float*)d_in[1];
    const float* value = (const float*)d_in[2];
    const float* w_in[3]  = { (const float*)d_in[3], (const float*)d_in[5], (const float*)d_in[7] };
    const float* w_out[3] = { (const float*)d_in[4], (const float*)d_in[6], (const float*)d_in[8] };
    const float* coef[3]  = { (const float*)d_in[9], (const float*)d_in[10], (const float*)d_in[11] };
    float* out = (float*)d_out;

    __half* qh  = sym_addr_t<__half>(g_qh);
    __half* kh  = sym_addr_t<__half>(g_kh);
    __half* vh  = sym_addr_t<__half>(g_vh);
    __half* twoq   = sym_addr_t<__half>(g_twoq);
    __half* threeq = sym_addr_t<__half>(g_threeq);
    __half* wh  = sym_addr_t<__half>(g_wh);
    __half* Qh  = sym_addr_t<__half>(g_Qh);
    __half* Kh  = sym_addr_t<__half>(g_Kh);
    __half* Vh  = sym_addr_t<__half>(g_Vh);
    __half* ctx = sym_addr_t<__half>(g_ctx);

    const float invs = 1.0f / sqrtf((float)HD);

    const int SM_H = 3 * 2 * 128 * 40 * 2;        // 61440 B
    const int SM_F = 5 * FTILE * 2;               // 133120 B (Q + 2K + 2V)
    cudaFuncSetAttribute(hgemm_nt<1, false>, cudaFuncAttributeMaxDynamicSharedMemorySize, SM_H);
    cudaFuncSetAttribute(hgemm_nt<3, false>, cudaFuncAttributeMaxDynamicSharedMemorySize, SM_H);
    cudaFuncSetAttribute(hgemm_nt<3, true >, cudaFuncAttributeMaxDynamicSharedMemorySize, SM_H);
    cudaFuncSetAttribute(flash_kernel, cudaFuncAttributeMaxDynamicSharedMemorySize, SM_F);

    // ---- fp32 -> fp16 conversions + window aggregation ----
    {
        int n4 = MLB * DIM / 4;
        int nb = (n4 + 255) / 256;
        cvt_half_kernel<<<nb, 256>>>(query, qh, n4);
        cvt_half_kernel<<<nb, 256>>>(keyi,  kh, n4);
        cvt_half_kernel<<<nb, 256>>>(value, vh, n4);
        int nwi = 2304 * 768 / 4, nwo = 768 * 768 / 4;
        for (int i = 0; i < 3; i++) {
            cvt_half_kernel<<<(nwi + 255) / 256, 256>>>(w_in[i],  wh + (size_t)i * WSZ, nwi);
            cvt_half_kernel<<<(nwo + 255) / 256, 256>>>(w_out[i], wh + (size_t)i * WSZ + 2304 * 768, nwo);
        }
        int nv4 = NR * NB * DIM / 4;
        copy_visual_kernel<<<(nv4 + 255) / 256, 256>>>(query, twoq, threeq);
        window_agg_kernel<<<dim3(TT, NB), 256>>>(query, twoq, threeq);
    }

    const __half* qsrc[3] = { qh, twoq, threeq };
    dim3 gP(DIM / 128, MLB / 128, 1);       // (6,128)
    dim3 gF(LQ / 128, BH);                  // (4,256)

    for (int i = 0; i < 3; i++) {
        const __half* wi = wh + (size_t)i * WSZ;
        const __half* wo = wi + 2304 * 768;

        // Q/K/V projections -> fp16 [L,B,D]
        hgemm_nt<1, false><<<gP, 256, SM_H>>>(qsrc[i], wi, nullptr, Qh,
            MLB, DIM, DIM, DIM, DIM, nullptr);
        hgemm_nt<1, false><<<gP, 256, SM_H>>>(kh, wi + DIM * DIM, nullptr, Kh,
            MLB, DIM, DIM, DIM, DIM, nullptr);
        hgemm_nt<1, false><<<gP, 256, SM_H>>>(vh, wi + 2 * DIM * DIM, nullptr, Vh,
            MLB, DIM, DIM, DIM, DIM, nullptr);

        // fused attention -> ctx fp16 [L,B,D]
        flash_kernel<<<gF, 256, SM_F>>>(Qh, Kh, Vh, ctx, invs);

        // out (+)= coef * ctx @ w_out^T
        if (i == 0)
            hgemm_nt<3, false><<<gP, 256, SM_H>>>(ctx, wo, out, nullptr,
                MLB, DIM, DIM, DIM, DIM, coef[i]);
        else
            hgemm_nt<3, true><<<gP, 256, SM_H>>>(ctx, wo, out, nullptr,
                MLB, DIM, DIM, DIM, DIM, coef[i]);
    }
}

// round 9
// speedup vs baseline: 7.7772x; 1.1627x over previous
#include <cuda_runtime.h>
#include <cuda_fp16.h>
#include <math.h>
#include <stdint.h>

// Problem constants (fixed shapes)
#define LQ   512
#define NB   32
#define DIM  768
#define NH   8
#define HD   96
#define NR   196
#define TT   316               // text length
#define MLB  (LQ*NB)           // 16384
#define BH   (NB*NH)           // 256
#define LDQ  (NB*DIM)          // 24576 row stride of [L,B,D] per l
#define CSTR (3*DIM)           // 2304: ctxcat row stride
#define WIN  (2304*DIM)        // fp16 w_in slab per MHA
#define EPSW 1e-8f

// -------------------- device scratch --------------------
__device__ __half g_qh [MLB*DIM];
__device__ __half g_kh [MLB*DIM];
__device__ __half g_vh [MLB*DIM];
__device__ __half g_twoq  [MLB*DIM];
__device__ __half g_threeq[MLB*DIM];
__device__ __half g_wh  [3*WIN];              // fp16 w_in x3
__device__ __half g_wcat[DIM*CSTR];           // [768, 2304] coef-folded w_out concat
__device__ __half g_Qh [3*MLB*DIM];           // per-MHA fp16 Q proj slabs
__device__ __half g_Kh [3*MLB*DIM];
__device__ __half g_Vh [3*MLB*DIM];
__device__ __half g_ctx[(size_t)MLB*CSTR];    // [M, 2304] ctx concat

// -------------------- PTX helpers --------------------
__device__ __forceinline__ void cp16(uint32_t dst, const void* gptr) {
    asm volatile("cp.async.cg.shared.global [%0], [%1], 16;\n" :: "r"(dst), "l"(gptr));
}
__device__ __forceinline__ void cp_commit() { asm volatile("cp.async.commit_group;\n"); }
__device__ __forceinline__ void cp_wait1()  { asm volatile("cp.async.wait_group 1;\n"); }

__device__ __forceinline__ void mma_f16(float c[4], const uint32_t a[4],
                                        uint32_t b0, uint32_t b1) {
    asm volatile("mma.sync.aligned.m16n8k16.row.col.f32.f16.f16.f32 "
        "{%0,%1,%2,%3}, {%4,%5,%6,%7}, {%8,%9}, {%0,%1,%2,%3};\n"
        : "+f"(c[0]), "+f"(c[1]), "+f"(c[2]), "+f"(c[3])
        : "r"(a[0]), "r"(a[1]), "r"(a[2]), "r"(a[3]), "r"(b0), "r"(b1));
}
__device__ __forceinline__ void ldmx4t(uint32_t& r0, uint32_t& r1,
                                       uint32_t& r2, uint32_t& r3, uint32_t addr) {
    asm volatile("ldmatrix.sync.aligned.m8n8.x4.trans.shared.b16 {%0,%1,%2,%3}, [%4];"
        : "=r"(r0), "=r"(r1), "=r"(r2), "=r"(r3) : "r"(addr));
}
__device__ __forceinline__ uint32_t packh2(float lo, float hi) {
    __half2 h = __floats2half2_rn(lo, hi);
    return reinterpret_cast<uint32_t&>(h);
}

// -------------------- fp32 -> fp16 conversion --------------------
__global__ void cvt_half_kernel(const float* __restrict__ src,
                                __half* __restrict__ dst, int n4)
{
    int i = blockIdx.x * blockDim.x + threadIdx.x;
    if (i < n4) {
        float4 v = reinterpret_cast<const float4*>(src)[i];
        __half2* d = reinterpret_cast<__half2*>(dst) + 2 * i;
        d[0] = __floats2half2_rn(v.x, v.y);
        d[1] = __floats2half2_rn(v.z, v.w);
    }
}

// -------------------- w_out concat (coef folded) --------------------
// dst[n*2304 + i*768 + k] = coef * w[n*768 + k]
__global__ void build_wcat_kernel(const float* __restrict__ w,
                                  const float* __restrict__ coef,
                                  __half* __restrict__ dst, int i)
{
    int idx = blockIdx.x * blockDim.x + threadIdx.x;   // over 768*768/2 half2
    if (idx < DIM * DIM / 2) {
        float c = *coef;
        float2 v = reinterpret_cast<const float2*>(w)[idx];
        int n = (2 * idx) / DIM, k = (2 * idx) % DIM;
        *reinterpret_cast<__half2*>(&dst[(size_t)n * CSTR + i * DIM + k]) =
            __floats2half2_rn(c * v.x, c * v.y);
    }
}

// -------------------- visual tokens -> two_q/three_q (fp16) --------------------
__global__ void copy_visual_kernel(const float* __restrict__ q,
                                   __half* __restrict__ twoq,
                                   __half* __restrict__ threeq)
{
    int i = blockIdx.x * blockDim.x + threadIdx.x;
    const int n = NR * NB * DIM / 4;
    if (i < n) {
        float4 v = reinterpret_cast<const float4*>(q)[i];
        __half2 h0 = __floats2half2_rn(v.x, v.y);
        __half2 h1 = __floats2half2_rn(v.z, v.w);
        reinterpret_cast<__half2*>(twoq)[2 * i]     = h0;
        reinterpret_cast<__half2*>(twoq)[2 * i + 1] = h1;
        reinterpret_cast<__half2*>(threeq)[2 * i]     = h0;
        reinterpret_cast<__half2*>(threeq)[2 * i + 1] = h1;
    }
}

// -------------------- window aggregation (fp16 outputs) --------------------
__global__ void window_agg_kernel(const float* __restrict__ q,
                                  __half* __restrict__ twoq,
                                  __half* __restrict__ threeq)
{
    int t = blockIdx.x;
    int b = blockIdx.y;
    int tid = threadIdx.x;

    __shared__ float xs[5][DIM];
    __shared__ float red[10][8];
    __shared__ float fin[10];

    #pragma unroll
    for (int w = 0; w < 5; w++) {
        int tw = t + w - 2;
        bool ok = (tw >= 0) && (tw < TT);
        const float* src = q + ((size_t)(NR + tw) * NB + b) * DIM;
        for (int c = tid; c < DIM; c += 256)
            xs[w][c] = ok ? src[c] : 0.0f;
    }
    __syncthreads();

    float p[10];
    #pragma unroll
    for (int k = 0; k < 10; k++) p[k] = 0.0f;

    for (int c = tid; c < DIM; c += 256) {
        float x0 = xs[0][c], x1 = xs[1][c], x2 = xs[2][c], x3 = xs[3][c], x4 = xs[4][c];
        p[0] += x0 * x0;  p[1] += x1 * x1;  p[2] += x2 * x2;
        p[3] += x3 * x3;  p[4] += x4 * x4;
        p[5] += x2 * x1;  p[6] += x2 * x3;
        p[7] += x3 * x0;  p[8] += x3 * x1;  p[9] += x3 * x4;
    }
    #pragma unroll
    for (int o = 16; o; o >>= 1) {
        #pragma unroll
        for (int k = 0; k < 10; k++)
            p[k] += __shfl_xor_sync(0xFFFFFFFFu, p[k], o);
    }
    int wid = tid >> 5, lane = tid & 31;
    if (lane == 0) {
        #pragma unroll
        for (int k = 0; k < 10; k++) red[k][wid] = p[k];
    }
    __syncthreads();
    if (tid < 10) {
        float s = 0.0f;
        #pragma unroll
        for (int w = 0; w < 8; w++) s += red[tid][w];
        fin[tid] = s;
    }
    __syncthreads();

    float n0 = fin[0], n1 = fin[1], n2 = fin[2], n3 = fin[3], n4 = fin[4];
    float in0 = 1.0f / fmaxf(sqrtf(n0), EPSW);
    float in1 = 1.0f / fmaxf(sqrtf(n1), EPSW);
    float in2 = 1.0f / fmaxf(sqrtf(n2), EPSW);
    float in3 = 1.0f / fmaxf(sqrtf(n3), EPSW);
    float in4 = 1.0f / fmaxf(sqrtf(n4), EPSW);

    float w2_1 = fin[5] * in2 * in1;
    float w2_2 = n2     * in2 * in2;
    float w2_3 = fin[6] * in2 * in3;
    float w3_0 = fin[7] * in3 * in0;
    float w3_1 = fin[8] * in3 * in1;
    float w3_2 = fin[6] * in3 * in2;
    float w3_3 = n3     * in3 * in3;
    float w3_4 = fin[9] * in3 * in4;

    size_t base = ((size_t)(NR + t) * NB + b) * DIM;
    for (int c = tid; c < DIM; c += 256) {
        float x0 = xs[0][c], x1 = xs[1][c], x2 = xs[2][c], x3 = xs[3][c], x4 = xs[4][c];
        twoq[base + c]   = __float2half(w2_1 * x1 + w2_2 * x2 + w2_3 * x3);
        threeq[base + c] = __float2half(w3_0 * x0 + w3_1 * x1 + w3_2 * x2 + w3_3 * x3 + w3_4 * x4);
    }
}

// ==================== fp16 NT GEMM (64x64 warp tiles, 128 thr) ====================
// C = A * B^T. A selected per z from {A0,A1,A2}; B = Bg + z*bz.
// EPI 1: Ch[z*cz + r*N + col] = half(acc)
// EPI 3: Cf[r*N + col] = acc   (fp32, full overwrite)
template<int EPI>
__global__ __launch_bounds__(128, 2)
void hgemm_nt(const __half* __restrict__ A0, const __half* __restrict__ A1,
              const __half* __restrict__ A2, const __half* __restrict__ Bg,
              float* __restrict__ Cf, __half* __restrict__ Ch,
              int M, int N, int K, int lda, int ldb,
              size_t bz, size_t cz)
{
    constexpr int BM = 128, BN = 128, BK = 32, ST = 3;
    constexpr int AST = BK + 8;           // 40 halves (u32-stride 20 -> conflict-free)
    constexpr int TS  = BM * AST;         // 5120 halves

    extern __shared__ __half hsm[];
    __half* As = hsm;
    __half* Bs = hsm + ST * TS;

    const int z = blockIdx.z;
    const __half* A = (z == 0) ? A0 : ((z == 1) ? A1 : A2);
    const __half* B = Bg + (size_t)z * bz;
    const int m0 = blockIdx.y * BM;
    const int n0 = blockIdx.x * BN;
    const int tid = threadIdx.x;
    const int lane = tid & 31;
    const int wid = tid >> 5;
    const int warp_m = (wid >> 1) * 64;   // 2 warps along M
    const int warp_n = (wid & 1) * 64;    // 2 warps along N
    const int gr = lane >> 2;
    const int tg = lane & 3;

    float acc[4][8][4];
    #pragma unroll
    for (int i = 0; i < 4; i++)
        #pragma unroll
        for (int j = 0; j < 8; j++)
            #pragma unroll
            for (int e = 0; e < 4; e++) acc[i][j][e] = 0.0f;

    const int nt = K / BK;

    uint32_t as_sh = (uint32_t)__cvta_generic_to_shared(As);
    uint32_t bs_sh = (uint32_t)__cvta_generic_to_shared(Bs);

    auto load_tile = [&](int s, int kt) {
        int k0 = kt * BK;
        #pragma unroll
        for (int r = 0; r < 4; r++) {
            int c = tid + 128 * r;
            int row = c >> 2, ch = c & 3;
            const __half* g = A + (size_t)(m0 + row) * lda + k0 + ch * 8;
            cp16(as_sh + (s * TS + row * AST + ch * 8) * 2, g);
        }
        #pragma unroll
        for (int r = 0; r < 4; r++) {
            int c = tid + 128 * r;
            int row = c >> 2, ch = c & 3;
            const __half* g = B + (size_t)(n0 + row) * ldb + k0 + ch * 8;
            cp16(bs_sh + (s * TS + row * AST + ch * 8) * 2, g);
        }
    };

    load_tile(0, 0); cp_commit();
    if (nt > 1) load_tile(1, 1);
    cp_commit();

    for (int kt = 0; kt < nt; kt++) {
        cp_wait1();
        __syncthreads();
        if (kt + 2 < nt) load_tile((kt + 2) % ST, kt + 2);
        cp_commit();

        const uint32_t* au = reinterpret_cast<const uint32_t*>(As + (kt % ST) * TS);
        const uint32_t* bu = reinterpret_cast<const uint32_t*>(Bs + (kt % ST) * TS);

        #pragma unroll
        for (int ks = 0; ks < 2; ks++) {
            int kb = ks * 8;
            uint32_t af[4][4];
            #pragma unroll
            for (int i = 0; i < 4; i++) {
                int rb = warp_m + i * 16 + gr;
                af[i][0] = au[rb * 20 + kb + tg];
                af[i][1] = au[(rb + 8) * 20 + kb + tg];
                af[i][2] = au[rb * 20 + kb + tg + 4];
                af[i][3] = au[(rb + 8) * 20 + kb + tg + 4];
            }
            uint32_t bf[8][2];
            #pragma unroll
            for (int j = 0; j < 8; j++) {
                int nb = warp_n + j * 8 + gr;
                bf[j][0] = bu[nb * 20 + kb + tg];
                bf[j][1] = bu[nb * 20 + kb + tg + 4];
            }
            #pragma unroll
            for (int i = 0; i < 4; i++)
                #pragma unroll
                for (int j = 0; j < 8; j++)
                    mma_f16(acc[i][j], af[i], bf[j][0], bf[j][1]);
        }
        __syncthreads();
    }

    #pragma unroll
    for (int i = 0; i < 4; i++) {
        #pragma unroll
        for (int j = 0; j < 8; j++) {
            int row = m0 + warp_m + i * 16 + gr;
            int col = n0 + warp_n + j * 8 + 2 * tg;
            #pragma unroll
            for (int half_ = 0; half_ < 2; half_++) {
                int r = row + half_ * 8;
                float v0 = acc[i][j][half_ * 2 + 0];
                float v1 = acc[i][j][half_ * 2 + 1];
                if (EPI == 1) {
                    *reinterpret_cast<__half2*>(&Ch[(size_t)z * cz + (size_t)r * N + col]) =
                        __floats2half2_rn(v0, v1);
                } else {
                    *reinterpret_cast<float2*>(&Cf[(size_t)r * N + col]) = make_float2(v0, v1);
                }
            }
        }
    }
}

// ==================== fused flash attention (batched over 3 MHAs) ====================
// grid (LQ/128, BH, 3). CTA: 256 thr (8 warps x 16 q-rows). Online softmax.
#define FSTR  104              // smem row stride (halves)
#define FSTRU 52               // in u32
#define FTILE (128*FSTR)       // halves per 128-row tile

__global__ __launch_bounds__(256)
void flash_kernel(const __half* __restrict__ Qg, const __half* __restrict__ Kg,
                  const __half* __restrict__ Vg, __half* __restrict__ Ch, float invs)
{
    extern __shared__ __half fsm[];
    __half* Qs = fsm;                    // [128][104]
    __half* Ks = fsm + FTILE;            // [2][128][104]
    __half* Vs = Ks + 2 * FTILE;         // [2][128][104]

    const int z  = blockIdx.y;           // b*8 + h
    const int z2 = blockIdx.z;           // MHA index
    const size_t slab = (size_t)z2 * MLB * DIM;
    const size_t qkvoff = slab + (size_t)(z >> 3) * DIM + (size_t)(z & 7) * HD;
    const int m0 = blockIdx.x * 128;
    const int tid = threadIdx.x;
    const int lane = tid & 31;
    const int wid = tid >> 5;
    const int gr = lane >> 2, tg = lane & 3;

    uint32_t qs_sh = (uint32_t)__cvta_generic_to_shared(Qs);
    uint32_t ks_sh = (uint32_t)__cvta_generic_to_shared(Ks);
    uint32_t vs_sh = (uint32_t)__cvta_generic_to_shared(Vs);

    auto load_t = [&](uint32_t dst_sh, const __half* src, int l0) {
        #pragma unroll
        for (int r = 0; r < 6; r++) {
            int c = tid + 256 * r;
            int row = c / 12, ch = c % 12;
            const __half* g = src + (size_t)(l0 + row) * LDQ + qkvoff + ch * 8;
            cp16(dst_sh + (row * FSTR + ch * 8) * 2, g);
        }
    };

    load_t(qs_sh, Qg, m0);
    load_t(ks_sh, Kg, 0);
    load_t(vs_sh, Vg, 0);
    cp_commit();
    load_t(ks_sh + FTILE * 2, Kg, 128);
    load_t(vs_sh + FTILE * 2, Vg, 128);
    cp_commit();

    uint32_t qfrag[6][4];
    float o[12][4];
    #pragma unroll
    for (int j = 0; j < 12; j++)
        #pragma unroll
        for (int e = 0; e < 4; e++) o[j][e] = 0.0f;
    float m0r = -1e30f, m1r = -1e30f, l0s = 0.0f, l1s = 0.0f;

    const int lg = lane >> 3, li = lane & 7;
    const int laneoff = ((lg & 1) * 8 + li) * FSTR + (lg >> 1) * 8;

    #pragma unroll
    for (int kt = 0; kt < 4; kt++) {
        if (kt < 3) { asm volatile("cp.async.wait_group 1;\n"); }
        else        { asm volatile("cp.async.wait_group 0;\n"); }
        __syncthreads();

        if (kt == 0) {
            const uint32_t* qu = reinterpret_cast<const uint32_t*>(Qs);
            #pragma unroll
            for (int ks = 0; ks < 6; ks++) {
                int rb = wid * 16 + gr;
                qfrag[ks][0] = qu[rb * FSTRU + ks * 8 + tg];
                qfrag[ks][1] = qu[(rb + 8) * FSTRU + ks * 8 + tg];
                qfrag[ks][2] = qu[rb * FSTRU + ks * 8 + tg + 4];
                qfrag[ks][3] = qu[(rb + 8) * FSTRU + ks * 8 + tg + 4];
            }
        }

        const int st = kt & 1;
        const uint32_t* ku = reinterpret_cast<const uint32_t*>(Ks + st * FTILE);
        const uint32_t vbase = vs_sh + (st * FTILE + laneoff) * 2;

        float s[16][4];
        #pragma unroll
        for (int nf = 0; nf < 16; nf++)
            #pragma unroll
            for (int e = 0; e < 4; e++) s[nf][e] = 0.0f;
        #pragma unroll
        for (int ks = 0; ks < 6; ks++) {
            #pragma unroll
            for (int nf = 0; nf < 16; nf++) {
                int nb = nf * 8 + gr;
                uint32_t b0 = ku[nb * FSTRU + ks * 8 + tg];
                uint32_t b1 = ku[nb * FSTRU + ks * 8 + tg + 4];
                mma_f16(s[nf], qfrag[ks], b0, b1);
            }
        }

        float mx0 = -1e30f, mx1 = -1e30f;
        #pragma unroll
        for (int nf = 0; nf < 16; nf++) {
            s[nf][0] *= invs; s[nf][1] *= invs; s[nf][2] *= invs; s[nf][3] *= invs;
            mx0 = fmaxf(mx0, fmaxf(s[nf][0], s[nf][1]));
            mx1 = fmaxf(mx1, fmaxf(s[nf][2], s[nf][3]));
        }
        mx0 = fmaxf(mx0, __shfl_xor_sync(0xFFFFFFFFu, mx0, 1));
        mx0 = fmaxf(mx0, __shfl_xor_sync(0xFFFFFFFFu, mx0, 2));
        mx1 = fmaxf(mx1, __shfl_xor_sync(0xFFFFFFFFu, mx1, 1));
        mx1 = fmaxf(mx1, __shfl_xor_sync(0xFFFFFFFFu, mx1, 2));

        float mn0 = fmaxf(m0r, mx0), mn1 = fmaxf(m1r, mx1);
        float al0 = __expf(m0r - mn0), al1 = __expf(m1r - mn1);
        m0r = mn0; m1r = mn1;

        float rs0 = 0.0f, rs1 = 0.0f;
        uint32_t ph[32];
        #pragma unroll
        for (int nf = 0; nf < 16; nf++) {
            float p0 = __expf(s[nf][0] - mn0);
            float p1 = __expf(s[nf][1] - mn0);
            float p2 = __expf(s[nf][2] - mn1);
            float p3 = __expf(s[nf][3] - mn1);
            rs0 += p0 + p1; rs1 += p2 + p3;
            ph[2 * nf]     = packh2(p0, p1);
            ph[2 * nf + 1] = packh2(p2, p3);
        }
        rs0 += __shfl_xor_sync(0xFFFFFFFFu, rs0, 1);
        rs0 += __shfl_xor_sync(0xFFFFFFFFu, rs0, 2);
        rs1 += __shfl_xor_sync(0xFFFFFFFFu, rs1, 1);
        rs1 += __shfl_xor_sync(0xFFFFFFFFu, rs1, 2);
        l0s = l0s * al0 + rs0;
        l1s = l1s * al1 + rs1;

        #pragma unroll
        for (int j = 0; j < 12; j++) {
            o[j][0] *= al0; o[j][1] *= al0;
            o[j][2] *= al1; o[j][3] *= al1;
        }

        #pragma unroll
        for (int s8 = 0; s8 < 8; s8++) {
            const uint32_t* a = &ph[4 * s8];
            #pragma unroll
            for (int np = 0; np < 6; np++) {
                uint32_t r0, r1, r2, r3;
                ldmx4t(r0, r1, r2, r3, vbase + (s8 * 16 * FSTR + np * 16) * 2);
                mma_f16(o[2 * np],     a, r0, r1);
                mma_f16(o[2 * np + 1], a, r2, r3);
            }
        }

        __syncthreads();
        if (kt + 2 < 4) {
            load_t(ks_sh + st * FTILE * 2, Kg, (kt + 2) * 128);
            load_t(vs_sh + st * FTILE * 2, Vg, (kt + 2) * 128);
        }
        cp_commit();
    }

    // ---- normalize + write ctx into [M, 2304] concat ----
    float il0 = 1.0f / l0s, il1 = 1.0f / l1s;
    int r0 = m0 + wid * 16 + gr;
    int r1 = r0 + 8;
    const size_t cbase = (size_t)(z >> 3) * CSTR + (size_t)z2 * DIM + (size_t)(z & 7) * HD;
    #pragma unroll
    for (int j = 0; j < 12; j++) {
        int col = j * 8 + 2 * tg;
        *reinterpret_cast<__half2*>(&Ch[(size_t)r0 * NB * CSTR + cbase + col]) =
            __floats2half2_rn(o[j][0] * il0, o[j][1] * il0);
        *reinterpret_cast<__half2*>(&Ch[(size_t)r1 * NB * CSTR + cbase + col]) =
            __floats2half2_rn(o[j][2] * il1, o[j][3] * il1);
    }
}

// -------------------- launch --------------------
template<typename T>
static T* sym_addr_t(const void* symbol)
{
    void* p = nullptr;
    cudaGetSymbolAddress(&p, symbol);
    return reinterpret_cast<T*>(p);
}

extern "C" void kernel_launch(void* const* d_in, const int* in_sizes, int n_in,
                              void* d_out, int out_size)
{
    const float* query = (const float*)d_in[0];
    const float* keyi  = (const float*)d_in[1];
    const float* value = (const float*)d_in[2];
    const float* w_in[3]  = { (const float*)d_in[3], (const float*)d_in[5], (const float*)d_in[7] };
    const float* w_out[3] = { (const float*)d_in[4], (const float*)d_in[6], (const float*)d_in[8] };
    const float* coef[3]  = { (const float*)d_in[9], (const float*)d_in[10], (const float*)d_in[11] };
    float* out = (float*)d_out;

    __half* qh  = sym_addr_t<__half>(g_qh);
    __half* kh  = sym_addr_t<__half>(g_kh);
    __half* vh  = sym_addr_t<__half>(g_vh);
    __half* twoq   = sym_addr_t<__half>(g_twoq);
    __half* threeq = sym_addr_t<__half>(g_threeq);
    __half* wh   = sym_addr_t<__half>(g_wh);
    __half* wcat = sym_addr_t<__half>(g_wcat);
    __half* Qh  = sym_addr_t<__half>(g_Qh);
    __half* Kh  = sym_addr_t<__half>(g_Kh);
    __half* Vh  = sym_addr_t<__half>(g_Vh);
    __half* ctx = sym_addr_t<__half>(g_ctx);

    const float invs = 1.0f / sqrtf((float)HD);

    const int SM_H = 3 * 2 * 128 * 40 * 2;        // 61440 B
    const int SM_F = 5 * FTILE * 2;               // 133120 B
    cudaFuncSetAttribute(hgemm_nt<1>, cudaFuncAttributeMaxDynamicSharedMemorySize, SM_H);
    cudaFuncSetAttribute(hgemm_nt<3>, cudaFuncAttributeMaxDynamicSharedMemorySize, SM_H);
    cudaFuncSetAttribute(flash_kernel, cudaFuncAttributeMaxDynamicSharedMemorySize, SM_F);

    // ---- prep: conversions, wcat, window aggregation ----
    {
        int n4 = MLB * DIM / 4;
        int nb = (n4 + 255) / 256;
        cvt_half_kernel<<<nb, 256>>>(query, qh, n4);
        cvt_half_kernel<<<nb, 256>>>(keyi,  kh, n4);
        cvt_half_kernel<<<nb, 256>>>(value, vh, n4);
        int nwi = 2304 * DIM / 4;
        int nwc = DIM * DIM / 2;
        for (int i = 0; i < 3; i++) {
            cvt_half_kernel<<<(nwi + 255) / 256, 256>>>(w_in[i], wh + (size_t)i * WIN, nwi);
            build_wcat_kernel<<<(nwc + 255) / 256, 256>>>(w_out[i], coef[i], wcat, i);
        }
        int nv4 = NR * NB * DIM / 4;
        copy_visual_kernel<<<(nv4 + 255) / 256, 256>>>(query, twoq, threeq);
        window_agg_kernel<<<dim3(TT, NB), 256>>>(query, twoq, threeq);
    }

    const size_t SLAB = (size_t)MLB * DIM;
    dim3 gP(DIM / 128, MLB / 128, 3);       // (6,128,3) batched projections
    dim3 gFin(DIM / 128, MLB / 128, 1);     // final K=2304
    dim3 gF(LQ / 128, BH, 3);               // batched flash

    // Q projections (A differs per z)
    hgemm_nt<1><<<gP, 128, SM_H>>>(qh, twoq, threeq, wh, nullptr, Qh,
        MLB, DIM, DIM, DIM, DIM, (size_t)WIN, SLAB);
    // K projections (A = kh)
    hgemm_nt<1><<<gP, 128, SM_H>>>(kh, kh, kh, wh + DIM * DIM, nullptr, Kh,
        MLB, DIM, DIM, DIM, DIM, (size_t)WIN, SLAB);
    // V projections (A = vh)
    hgemm_nt<1><<<gP, 128, SM_H>>>(vh, vh, vh, wh + 2 * DIM * DIM, nullptr, Vh,
        MLB, DIM, DIM, DIM, DIM, (size_t)WIN, SLAB);

    // fused attention (all 3 MHAs) -> ctx [M, 2304]
    flash_kernel<<<gF, 256, SM_F>>>(Qh, Kh, Vh, ctx, invs);

    // out = ctx @ wcat^T  (K=2304, coef folded)
    hgemm_nt<3><<<gFin, 128, SM_H>>>(ctx, ctx, ctx, wcat, out, nullptr,
        MLB, DIM, CSTR, CSTR, CSTR, 0, 0);
}

// round 10
// speedup vs baseline: 8.2604x; 1.0621x over previous
#include <cuda_runtime.h>
#include <cuda_fp16.h>
#include <math.h>
#include <stdint.h>

// Problem constants (fixed shapes)
#define LQ   512
#define NB   32
#define DIM  768
#define NH   8
#define HD   96
#define NR   196
#define TT   316               // text length
#define MLB  (LQ*NB)           // 16384
#define BH   (NB*NH)           // 256
#define LDQ  (NB*DIM)          // 24576 row stride of [L,B,D] per l
#define CSTR (3*DIM)           // 2304: ctxcat row stride
#define WIN  (2304*DIM)        // fp16 w_in slab per MHA
#define SLAB ((size_t)MLB*DIM) // one [L,B,D] fp16 slab
#define EPSW 1e-8f

// -------------------- device scratch --------------------
__device__ __half g_qh [MLB*DIM];
__device__ __half g_kh [MLB*DIM];
__device__ __half g_vh [MLB*DIM];
__device__ __half g_twoq  [MLB*DIM];
__device__ __half g_threeq[MLB*DIM];
__device__ __half g_wh  [3*WIN];              // fp16 w_in x3
__device__ __half g_wcat[DIM*CSTR];           // [768, 2304] coef-folded w_out concat
__device__ __half g_QKV[9*MLB*DIM];           // slabs: z=wt*3+mha (Q:0-2, K:3-5, V:6-8)
__device__ __half g_ctx[(size_t)MLB*CSTR];    // [M, 2304] ctx concat

// -------------------- PTX helpers --------------------
__device__ __forceinline__ void cp16(uint32_t dst, const void* gptr) {
    asm volatile("cp.async.cg.shared.global [%0], [%1], 16;\n" :: "r"(dst), "l"(gptr));
}
__device__ __forceinline__ void cp_commit() { asm volatile("cp.async.commit_group;\n"); }
__device__ __forceinline__ void cp_wait1()  { asm volatile("cp.async.wait_group 1;\n"); }

__device__ __forceinline__ void mma_f16(float c[4], const uint32_t a[4],
                                        uint32_t b0, uint32_t b1) {
    asm volatile("mma.sync.aligned.m16n8k16.row.col.f32.f16.f16.f32 "
        "{%0,%1,%2,%3}, {%4,%5,%6,%7}, {%8,%9}, {%0,%1,%2,%3};\n"
        : "+f"(c[0]), "+f"(c[1]), "+f"(c[2]), "+f"(c[3])
        : "r"(a[0]), "r"(a[1]), "r"(a[2]), "r"(a[3]), "r"(b0), "r"(b1));
}
__device__ __forceinline__ void ldmx4t(uint32_t& r0, uint32_t& r1,
                                       uint32_t& r2, uint32_t& r3, uint32_t addr) {
    asm volatile("ldmatrix.sync.aligned.m8n8.x4.trans.shared.b16 {%0,%1,%2,%3}, [%4];"
        : "=r"(r0), "=r"(r1), "=r"(r2), "=r"(r3) : "r"(addr));
}
__device__ __forceinline__ uint32_t packh2(float lo, float hi) {
    __half2 h = __floats2half2_rn(lo, hi);
    return reinterpret_cast<uint32_t&>(h);
}

// -------------------- fp32 -> fp16 conversion --------------------
__global__ void cvt_half_kernel(const float* __restrict__ src,
                                __half* __restrict__ dst, int n4)
{
    int i = blockIdx.x * blockDim.x + threadIdx.x;
    if (i < n4) {
        float4 v = reinterpret_cast<const float4*>(src)[i];
        __half2* d = reinterpret_cast<__half2*>(dst) + 2 * i;
        d[0] = __floats2half2_rn(v.x, v.y);
        d[1] = __floats2half2_rn(v.z, v.w);
    }
}

// -------------------- w_out concat (coef folded) --------------------
__global__ void build_wcat_kernel(const float* __restrict__ w,
                                  const float* __restrict__ coef,
                                  __half* __restrict__ dst, int i)
{
    int idx = blockIdx.x * blockDim.x + threadIdx.x;
    if (idx < DIM * DIM / 2) {
        float c = *coef;
        float2 v = reinterpret_cast<const float2*>(w)[idx];
        int n = (2 * idx) / DIM, k = (2 * idx) % DIM;
        *reinterpret_cast<__half2*>(&dst[(size_t)n * CSTR + i * DIM + k]) =
            __floats2half2_rn(c * v.x, c * v.y);
    }
}

// -------------------- visual tokens -> two_q/three_q (fp16) --------------------
__global__ void copy_visual_kernel(const float* __restrict__ q,
                                   __half* __restrict__ twoq,
                                   __half* __restrict__ threeq)
{
    int i = blockIdx.x * blockDim.x + threadIdx.x;
    const int n = NR * NB * DIM / 4;
    if (i < n) {
        float4 v = reinterpret_cast<const float4*>(q)[i];
        __half2 h0 = __floats2half2_rn(v.x, v.y);
        __half2 h1 = __floats2half2_rn(v.z, v.w);
        reinterpret_cast<__half2*>(twoq)[2 * i]     = h0;
        reinterpret_cast<__half2*>(twoq)[2 * i + 1] = h1;
        reinterpret_cast<__half2*>(threeq)[2 * i]     = h0;
        reinterpret_cast<__half2*>(threeq)[2 * i + 1] = h1;
    }
}

// -------------------- window aggregation (fp16 outputs) --------------------
__global__ void window_agg_kernel(const float* __restrict__ q,
                                  __half* __restrict__ twoq,
                                  __half* __restrict__ threeq)
{
    int t = blockIdx.x;
    int b = blockIdx.y;
    int tid = threadIdx.x;

    __shared__ float xs[5][DIM];
    __shared__ float red[10][8];
    __shared__ float fin[10];

    #pragma unroll
    for (int w = 0; w < 5; w++) {
        int tw = t + w - 2;
        bool ok = (tw >= 0) && (tw < TT);
        const float* src = q + ((size_t)(NR + tw) * NB + b) * DIM;
        for (int c = tid; c < DIM; c += 256)
            xs[w][c] = ok ? src[c] : 0.0f;
    }
    __syncthreads();

    float p[10];
    #pragma unroll
    for (int k = 0; k < 10; k++) p[k] = 0.0f;

    for (int c = tid; c < DIM; c += 256) {
        float x0 = xs[0][c], x1 = xs[1][c], x2 = xs[2][c], x3 = xs[3][c], x4 = xs[4][c];
        p[0] += x0 * x0;  p[1] += x1 * x1;  p[2] += x2 * x2;
        p[3] += x3 * x3;  p[4] += x4 * x4;
        p[5] += x2 * x1;  p[6] += x2 * x3;
        p[7] += x3 * x0;  p[8] += x3 * x1;  p[9] += x3 * x4;
    }
    #pragma unroll
    for (int o = 16; o; o >>= 1) {
        #pragma unroll
        for (int k = 0; k < 10; k++)
            p[k] += __shfl_xor_sync(0xFFFFFFFFu, p[k], o);
    }
    int wid = tid >> 5, lane = tid & 31;
    if (lane == 0) {
        #pragma unroll
        for (int k = 0; k < 10; k++) red[k][wid] = p[k];
    }
    __syncthreads();
    if (tid < 10) {
        float s = 0.0f;
        #pragma unroll
        for (int w = 0; w < 8; w++) s += red[tid][w];
        fin[tid] = s;
    }
    __syncthreads();

    float n0 = fin[0], n1 = fin[1], n2 = fin[2], n3 = fin[3], n4 = fin[4];
    float in0 = 1.0f / fmaxf(sqrtf(n0), EPSW);
    float in1 = 1.0f / fmaxf(sqrtf(n1), EPSW);
    float in2 = 1.0f / fmaxf(sqrtf(n2), EPSW);
    float in3 = 1.0f / fmaxf(sqrtf(n3), EPSW);
    float in4 = 1.0f / fmaxf(sqrtf(n4), EPSW);

    float w2_1 = fin[5] * in2 * in1;
    float w2_2 = n2     * in2 * in2;
    float w2_3 = fin[6] * in2 * in3;
    float w3_0 = fin[7] * in3 * in0;
    float w3_1 = fin[8] * in3 * in1;
    float w3_2 = fin[6] * in3 * in2;
    float w3_3 = n3     * in3 * in3;
    float w3_4 = fin[9] * in3 * in4;

    size_t base = ((size_t)(NR + t) * NB + b) * DIM;
    for (int c = tid; c < DIM; c += 256) {
        float x0 = xs[0][c], x1 = xs[1][c], x2 = xs[2][c], x3 = xs[3][c], x4 = xs[4][c];
        twoq[base + c]   = __float2half(w2_1 * x1 + w2_2 * x2 + w2_3 * x3);
        threeq[base + c] = __float2half(w3_0 * x0 + w3_1 * x1 + w3_2 * x2 + w3_3 * x3 + w3_4 * x4);
    }
}

// ==================== fp16 NT GEMM (64x64 warp tiles, 128 thr, 3 CTAs/SM) ====================
// EPI 1 (proj): z = wt*3 + mha. A = src table; B = wh + mha*WIN + wt*DIM*DIM;
//               Ch[z*SLAB + r*N + col] = half(acc)
// EPI 3 (final): z = 0; A = A0, B = Bg; Cf[r*N + col] = acc
template<int EPI>
__global__ __launch_bounds__(128, 3)
void hgemm_nt(const __half* __restrict__ A0, const __half* __restrict__ A1,
              const __half* __restrict__ A2, const __half* __restrict__ A3,
              const __half* __restrict__ A4, const __half* __restrict__ Bg,
              float* __restrict__ Cf, __half* __restrict__ Ch,
              int M, int N, int K, int lda, int ldb)
{
    constexpr int BM = 128, BN = 128, BK = 32, ST = 3;
    constexpr int AST = BK + 8;           // 40 halves (u32-stride 20 -> conflict-free)
    constexpr int TS  = BM * AST;         // 5120 halves

    extern __shared__ __half hsm[];
    __half* As = hsm;
    __half* Bs = hsm + ST * TS;

    const int z = blockIdx.z;
    const int wt = z / 3, mha = z - 3 * wt;
    const __half* A;
    const __half* B;
    if (EPI == 1) {
        A = (wt == 0) ? ((mha == 0) ? A0 : ((mha == 1) ? A1 : A2))
                      : ((wt == 1) ? A3 : A4);
        B = Bg + (size_t)mha * WIN + (size_t)wt * DIM * DIM;
    } else {
        A = A0;
        B = Bg;
    }
    const int m0 = blockIdx.y * BM;
    const int n0 = blockIdx.x * BN;
    const int tid = threadIdx.x;
    const int lane = tid & 31;
    const int wid = tid >> 5;
    const int warp_m = (wid >> 1) * 64;
    const int warp_n = (wid & 1) * 64;
    const int gr = lane >> 2;
    const int tg = lane & 3;

    float acc[4][8][4];
    #pragma unroll
    for (int i = 0; i < 4; i++)
        #pragma unroll
        for (int j = 0; j < 8; j++)
            #pragma unroll
            for (int e = 0; e < 4; e++) acc[i][j][e] = 0.0f;

    const int nt = K / BK;

    uint32_t as_sh = (uint32_t)__cvta_generic_to_shared(As);
    uint32_t bs_sh = (uint32_t)__cvta_generic_to_shared(Bs);

    auto load_tile = [&](int s, int kt) {
        int k0 = kt * BK;
        #pragma unroll
        for (int r = 0; r < 4; r++) {
            int c = tid + 128 * r;
            int row = c >> 2, ch = c & 3;
            const __half* g = A + (size_t)(m0 + row) * lda + k0 + ch * 8;
            cp16(as_sh + (s * TS + row * AST + ch * 8) * 2, g);
        }
        #pragma unroll
        for (int r = 0; r < 4; r++) {
            int c = tid + 128 * r;
            int row = c >> 2, ch = c & 3;
            const __half* g = B + (size_t)(n0 + row) * ldb + k0 + ch * 8;
            cp16(bs_sh + (s * TS + row * AST + ch * 8) * 2, g);
        }
    };

    load_tile(0, 0); cp_commit();
    if (nt > 1) load_tile(1, 1);
    cp_commit();

    for (int kt = 0; kt < nt; kt++) {
        cp_wait1();
        __syncthreads();
        if (kt + 2 < nt) load_tile((kt + 2) % ST, kt + 2);
        cp_commit();

        const uint32_t* au = reinterpret_cast<const uint32_t*>(As + (kt % ST) * TS);
        const uint32_t* bu = reinterpret_cast<const uint32_t*>(Bs + (kt % ST) * TS);

        #pragma unroll
        for (int ks = 0; ks < 2; ks++) {
            int kb = ks * 8;
            uint32_t af[4][4];
            #pragma unroll
            for (int i = 0; i < 4; i++) {
                int rb = warp_m + i * 16 + gr;
                af[i][0] = au[rb * 20 + kb + tg];
                af[i][1] = au[(rb + 8) * 20 + kb + tg];
                af[i][2] = au[rb * 20 + kb + tg + 4];
                af[i][3] = au[(rb + 8) * 20 + kb + tg + 4];
            }
            uint32_t bf[8][2];
            #pragma unroll
            for (int j = 0; j < 8; j++) {
                int nb = warp_n + j * 8 + gr;
                bf[j][0] = bu[nb * 20 + kb + tg];
                bf[j][1] = bu[nb * 20 + kb + tg + 4];
            }
            #pragma unroll
            for (int i = 0; i < 4; i++)
                #pragma unroll
                for (int j = 0; j < 8; j++)
                    mma_f16(acc[i][j], af[i], bf[j][0], bf[j][1]);
        }
        // NOTE: no trailing __syncthreads needed — top-of-loop sync at kt+1
        // orders all reads of buffer kt%3 before cp.async writes to it (iter kt+1
        // writes buffer (kt+3)%3 == kt%3).
    }

    #pragma unroll
    for (int i = 0; i < 4; i++) {
        #pragma unroll
        for (int j = 0; j < 8; j++) {
            int row = m0 + warp_m + i * 16 + gr;
            int col = n0 + warp_n + j * 8 + 2 * tg;
            #pragma unroll
            for (int half_ = 0; half_ < 2; half_++) {
                int r = row + half_ * 8;
                float v0 = acc[i][j][half_ * 2 + 0];
                float v1 = acc[i][j][half_ * 2 + 1];
                if (EPI == 1) {
                    *reinterpret_cast<__half2*>(&Ch[(size_t)z * SLAB + (size_t)r * N + col]) =
                        __floats2half2_rn(v0, v1);
                } else {
                    *reinterpret_cast<float2*>(&Cf[(size_t)r * N + col]) = make_float2(v0, v1);
                }
            }
        }
    }
}

// ==================== fused flash attention (batched over 3 MHAs) ====================
// grid (LQ/128, BH, 3). CTA: 256 thr (8 warps x 16 q-rows). Online softmax.
#define FSTR  104              // smem row stride (halves)
#define FSTRU 52               // in u32
#define FTILE (128*FSTR)       // halves per 128-row tile

__global__ __launch_bounds__(256)
void flash_kernel(const __half* __restrict__ QKV, __half* __restrict__ Ch, float invs)
{
    extern __shared__ __half fsm[];
    __half* Qs = fsm;                    // [128][104]
    __half* Ks = fsm + FTILE;            // [2][128][104]
    __half* Vs = Ks + 2 * FTILE;         // [2][128][104]

    const int z  = blockIdx.y;           // b*8 + h
    const int z2 = blockIdx.z;           // MHA index
    const size_t hoff = (size_t)(z >> 3) * DIM + (size_t)(z & 7) * HD;
    const __half* Qg = QKV + (size_t)(0 + z2) * SLAB + hoff;
    const __half* Kg = QKV + (size_t)(3 + z2) * SLAB + hoff;
    const __half* Vg = QKV + (size_t)(6 + z2) * SLAB + hoff;
    const int m0 = blockIdx.x * 128;
    const int tid = threadIdx.x;
    const int lane = tid & 31;
    const int wid = tid >> 5;
    const int gr = lane >> 2, tg = lane & 3;

    uint32_t qs_sh = (uint32_t)__cvta_generic_to_shared(Qs);
    uint32_t ks_sh = (uint32_t)__cvta_generic_to_shared(Ks);
    uint32_t vs_sh = (uint32_t)__cvta_generic_to_shared(Vs);

    auto load_t = [&](uint32_t dst_sh, const __half* src, int l0) {
        #pragma unroll
        for (int r = 0; r < 6; r++) {
            int c = tid + 256 * r;
            int row = c / 12, ch = c % 12;
            const __half* g = src + (size_t)(l0 + row) * LDQ + ch * 8;
            cp16(dst_sh + (row * FSTR + ch * 8) * 2, g);
        }
    };

    load_t(qs_sh, Qg, m0);
    load_t(ks_sh, Kg, 0);
    load_t(vs_sh, Vg, 0);
    cp_commit();
    load_t(ks_sh + FTILE * 2, Kg, 128);
    load_t(vs_sh + FTILE * 2, Vg, 128);
    cp_commit();

    uint32_t qfrag[6][4];
    float o[12][4];
    #pragma unroll
    for (int j = 0; j < 12; j++)
        #pragma unroll
        for (int e = 0; e < 4; e++) o[j][e] = 0.0f;
    float m0r = -1e30f, m1r = -1e30f, l0s = 0.0f, l1s = 0.0f;

    const int lg = lane >> 3, li = lane & 7;
    const int laneoff = ((lg & 1) * 8 + li) * FSTR + (lg >> 1) * 8;

    #pragma unroll
    for (int kt = 0; kt < 4; kt++) {
        if (kt < 3) { asm volatile("cp.async.wait_group 1;\n"); }
        else        { asm volatile("cp.async.wait_group 0;\n"); }
        __syncthreads();

        if (kt == 0) {
            const uint32_t* qu = reinterpret_cast<const uint32_t*>(Qs);
            #pragma unroll
            for (int ks = 0; ks < 6; ks++) {
                int rb = wid * 16 + gr;
                qfrag[ks][0] = qu[rb * FSTRU + ks * 8 + tg];
                qfrag[ks][1] = qu[(rb + 8) * FSTRU + ks * 8 + tg];
                qfrag[ks][2] = qu[rb * FSTRU + ks * 8 + tg + 4];
                qfrag[ks][3] = qu[(rb + 8) * FSTRU + ks * 8 + tg + 4];
            }
        }

        const int st = kt & 1;
        const uint32_t* ku = reinterpret_cast<const uint32_t*>(Ks + st * FTILE);
        const uint32_t vbase = vs_sh + (st * FTILE + laneoff) * 2;

        float s[16][4];
        #pragma unroll
        for (int nf = 0; nf < 16; nf++)
            #pragma unroll
            for (int e = 0; e < 4; e++) s[nf][e] = 0.0f;
        #pragma unroll
        for (int ks = 0; ks < 6; ks++) {
            #pragma unroll
            for (int nf = 0; nf < 16; nf++) {
                int nb = nf * 8 + gr;
                uint32_t b0 = ku[nb * FSTRU + ks * 8 + tg];
                uint32_t b1 = ku[nb * FSTRU + ks * 8 + tg + 4];
                mma_f16(s[nf], qfrag[ks], b0, b1);
            }
        }

        float mx0 = -1e30f, mx1 = -1e30f;
        #pragma unroll
        for (int nf = 0; nf < 16; nf++) {
            s[nf][0] *= invs; s[nf][1] *= invs; s[nf][2] *= invs; s[nf][3] *= invs;
            mx0 = fmaxf(mx0, fmaxf(s[nf][0], s[nf][1]));
            mx1 = fmaxf(mx1, fmaxf(s[nf][2], s[nf][3]));
        }
        mx0 = fmaxf(mx0, __shfl_xor_sync(0xFFFFFFFFu, mx0, 1));
        mx0 = fmaxf(mx0, __shfl_xor_sync(0xFFFFFFFFu, mx0, 2));
        mx1 = fmaxf(mx1, __shfl_xor_sync(0xFFFFFFFFu, mx1, 1));
        mx1 = fmaxf(mx1, __shfl_xor_sync(0xFFFFFFFFu, mx1, 2));

        float mn0 = fmaxf(m0r, mx0), mn1 = fmaxf(m1r, mx1);
        float al0 = __expf(m0r - mn0), al1 = __expf(m1r - mn1);
        m0r = mn0; m1r = mn1;

        float rs0 = 0.0f, rs1 = 0.0f;
        uint32_t ph[32];
        #pragma unroll
        for (int nf = 0; nf < 16; nf++) {
            float p0 = __expf(s[nf][0] - mn0);
            float p1 = __expf(s[nf][1] - mn0);
            float p2 = __expf(s[nf][2] - mn1);
            float p3 = __expf(s[nf][3] - mn1);
            rs0 += p0 + p1; rs1 += p2 + p3;
            ph[2 * nf]     = packh2(p0, p1);
            ph[2 * nf + 1] = packh2(p2, p3);
        }
        rs0 += __shfl_xor_sync(0xFFFFFFFFu, rs0, 1);
        rs0 += __shfl_xor_sync(0xFFFFFFFFu, rs0, 2);
        rs1 += __shfl_xor_sync(0xFFFFFFFFu, rs1, 1);
        rs1 += __shfl_xor_sync(0xFFFFFFFFu, rs1, 2);
        l0s = l0s * al0 + rs0;
        l1s = l1s * al1 + rs1;

        #pragma unroll
        for (int j = 0; j < 12; j++) {
            o[j][0] *= al0; o[j][1] *= al0;
            o[j][2] *= al1; o[j][3] *= al1;
        }

        #pragma unroll
        for (int s8 = 0; s8 < 8; s8++) {
            const uint32_t* a = &ph[4 * s8];
            #pragma unroll
            for (int np = 0; np < 6; np++) {
                uint32_t r0, r1, r2, r3;
                ldmx4t(r0, r1, r2, r3, vbase + (s8 * 16 * FSTR + np * 16) * 2);
                mma_f16(o[2 * np],     a, r0, r1);
                mma_f16(o[2 * np + 1], a, r2, r3);
            }
        }

        __syncthreads();
        if (kt + 2 < 4) {
            load_t(ks_sh + st * FTILE * 2, Kg, (kt + 2) * 128);
            load_t(vs_sh + st * FTILE * 2, Vg, (kt + 2) * 128);
        }
        cp_commit();
    }

    // ---- normalize + write ctx into [M, 2304] concat ----
    float il0 = 1.0f / l0s, il1 = 1.0f / l1s;
    int r0 = m0 + wid * 16 + gr;
    int r1 = r0 + 8;
    const size_t cbase = (size_t)(z >> 3) * CSTR + (size_t)z2 * DIM + (size_t)(z & 7) * HD;
    #pragma unroll
    for (int j = 0; j < 12; j++) {
        int col = j * 8 + 2 * tg;
        *reinterpret_cast<__half2*>(&Ch[(size_t)r0 * NB * CSTR + cbase + col]) =
            __floats2half2_rn(o[j][0] * il0, o[j][1] * il0);
        *reinterpret_cast<__half2*>(&Ch[(size_t)r1 * NB * CSTR + cbase + col]) =
            __floats2half2_rn(o[j][2] * il1, o[j][3] * il1);
    }
}

// -------------------- launch --------------------
template<typename T>
static T* sym_addr_t(const void* symbol)
{
    void* p = nullptr;
    cudaGetSymbolAddress(&p, symbol);
    return reinterpret_cast<T*>(p);
}

extern "C" void kernel_launch(void* const* d_in, const int* in_sizes, int n_in,
                              void* d_out, int out_size)
{
    const float* query = (const float*)d_in[0];
    const float* keyi  = (const float*)d_in[1];
    const float* value = (const float*)d_in[2];
    const float* w_in[3]  = { (const float*)d_in[3], (const float*)d_in[5], (const float*)d_in[7] };
    const float* w_out[3] = { (const float*)d_in[4], (const float*)d_in[6], (const float*)d_in[8] };
    const float* coef[3]  = { (const float*)d_in[9], (const float*)d_in[10], (const float*)d_in[11] };
    float* out = (float*)d_out;

    __half* qh  = sym_addr_t<__half>(g_qh);
    __half* kh  = sym_addr_t<__half>(g_kh);
    __half* vh  = sym_addr_t<__half>(g_vh);
    __half* twoq   = sym_addr_t<__half>(g_twoq);
    __half* threeq = sym_addr_t<__half>(g_threeq);
    __half* wh   = sym_addr_t<__half>(g_wh);
    __half* wcat = sym_addr_t<__half>(g_wcat);
    __half* QKV  = sym_addr_t<__half>(g_QKV);
    __half* ctx  = sym_addr_t<__half>(g_ctx);

    const float invs = 1.0f / sqrtf((float)HD);

    const int SM_H = 3 * 2 * 128 * 40 * 2;        // 61440 B
    const int SM_F = 5 * FTILE * 2;               // 133120 B
    cudaFuncSetAttribute(hgemm_nt<1>, cudaFuncAttributeMaxDynamicSharedMemorySize, SM_H);
    cudaFuncSetAttribute(hgemm_nt<3>, cudaFuncAttributeMaxDynamicSharedMemorySize, SM_H);
    cudaFuncSetAttribute(flash_kernel, cudaFuncAttributeMaxDynamicSharedMemorySize, SM_F);

    // ---- prep: conversions, wcat, window aggregation ----
    {
        int n4 = MLB * DIM / 4;
        int nb = (n4 + 255) / 256;
        cvt_half_kernel<<<nb, 256>>>(query, qh, n4);
        cvt_half_kernel<<<nb, 256>>>(keyi,  kh, n4);
        cvt_half_kernel<<<nb, 256>>>(value, vh, n4);
        int nwi = 2304 * DIM / 4;
        int nwc = DIM * DIM / 2;
        for (int i = 0; i < 3; i++) {
            cvt_half_kernel<<<(nwi + 255) / 256, 256>>>(w_in[i], wh + (size_t)i * WIN, nwi);
            build_wcat_kernel<<<(nwc + 255) / 256, 256>>>(w_out[i], coef[i], wcat, i);
        }
        int nv4 = NR * NB * DIM / 4;
        copy_visual_kernel<<<(nv4 + 255) / 256, 256>>>(query, twoq, threeq);
        window_agg_kernel<<<dim3(TT, NB), 256>>>(query, twoq, threeq);
    }

    dim3 gP(DIM / 128, MLB / 128, 9);       // all 9 projections in one launch
    dim3 gFin(DIM / 128, MLB / 128, 1);     // final K=2304
    dim3 gF(LQ / 128, BH, 3);               // batched flash

    // Q/K/V projections -> QKV slabs (z = wt*3 + mha)
    hgemm_nt<1><<<gP, 128, SM_H>>>(qh, twoq, threeq, kh, vh, wh, nullptr, QKV,
        MLB, DIM, DIM, DIM, DIM);

    // fused attention (all 3 MHAs) -> ctx [M, 2304]
    flash_kernel<<<gF, 256, SM_F>>>(QKV, ctx, invs);

    // out = ctx @ wcat^T  (K=2304, coef folded)
    hgemm_nt<3><<<gFin, 128, SM_H>>>(ctx, ctx, ctx, ctx, ctx, wcat, out, nullptr,
        MLB, DIM, CSTR, CSTR, CSTR);
}

// round 11
// speedup vs baseline: 8.5928x; 1.0402x over previous
#include <cuda_runtime.h>
#include <cuda_fp16.h>
#include <math.h>
#include <stdint.h>

// Problem constants (fixed shapes)
#define LQ   512
#define NB   32
#define DIM  768
#define NH   8
#define HD   96
#define NR   196
#define TT   316               // text length
#define MLB  (LQ*NB)           // 16384
#define BH   (NB*NH)           // 256
#define LDQ  (NB*DIM)          // 24576 row stride of [L,B,D] per l
#define CSTR (3*DIM)           // 2304: ctxcat row stride
#define WIN  (2304*DIM)        // fp16 w_in slab per MHA
#define SLAB ((size_t)MLB*DIM) // one [L,B,D] fp16 slab
#define EPSW 1e-8f

// -------------------- device scratch --------------------
__device__ __half g_qh [MLB*DIM];
__device__ __half g_kh [MLB*DIM];
__device__ __half g_vh [MLB*DIM];
__device__ __half g_twoq  [MLB*DIM];
__device__ __half g_threeq[MLB*DIM];
__device__ __half g_wh  [3*WIN];              // fp16 w_in x3
__device__ __half g_wcat[DIM*CSTR];           // [768, 2304] coef-folded w_out concat
__device__ __half g_QKV[9*MLB*DIM];           // slabs: z=wt*3+mha (Q:0-2, K:3-5, V:6-8)
__device__ __half g_ctx[(size_t)MLB*CSTR];    // [M, 2304] ctx concat

// -------------------- PTX helpers --------------------
__device__ __forceinline__ void cp16(uint32_t dst, const void* gptr) {
    asm volatile("cp.async.cg.shared.global [%0], [%1], 16;\n" :: "r"(dst), "l"(gptr));
}
__device__ __forceinline__ void cp_commit() { asm volatile("cp.async.commit_group;\n"); }
__device__ __forceinline__ void cp_wait1()  { asm volatile("cp.async.wait_group 1;\n"); }

__device__ __forceinline__ void mma_f16(float c[4], const uint32_t a[4],
                                        uint32_t b0, uint32_t b1) {
    asm volatile("mma.sync.aligned.m16n8k16.row.col.f32.f16.f16.f32 "
        "{%0,%1,%2,%3}, {%4,%5,%6,%7}, {%8,%9}, {%0,%1,%2,%3};\n"
        : "+f"(c[0]), "+f"(c[1]), "+f"(c[2]), "+f"(c[3])
        : "r"(a[0]), "r"(a[1]), "r"(a[2]), "r"(a[3]), "r"(b0), "r"(b1));
}
__device__ __forceinline__ void ldmx4t(uint32_t& r0, uint32_t& r1,
                                       uint32_t& r2, uint32_t& r3, uint32_t addr) {
    asm volatile("ldmatrix.sync.aligned.m8n8.x4.trans.shared.b16 {%0,%1,%2,%3}, [%4];"
        : "=r"(r0), "=r"(r1), "=r"(r2), "=r"(r3) : "r"(addr));
}
__device__ __forceinline__ uint32_t packh2(float lo, float hi) {
    __half2 h = __floats2half2_rn(lo, hi);
    return reinterpret_cast<uint32_t&>(h);
}

// -------------------- batched fp32 -> fp16 conversions --------------------
// grid.y selects (src,dst) pair
__global__ void cvt3_kernel(const float* __restrict__ s0, const float* __restrict__ s1,
                            const float* __restrict__ s2,
                            __half* __restrict__ d0, __half* __restrict__ d1,
                            __half* __restrict__ d2, int n4)
{
    int i = blockIdx.x * blockDim.x + threadIdx.x;
    if (i >= n4) return;
    int zz = blockIdx.y;
    const float* s = (zz == 0) ? s0 : ((zz == 1) ? s1 : s2);
    __half* d = (zz == 0) ? d0 : ((zz == 1) ? d1 : d2);
    float4 v = reinterpret_cast<const float4*>(s)[i];
    __half2* dd = reinterpret_cast<__half2*>(d) + 2 * i;
    dd[0] = __floats2half2_rn(v.x, v.y);
    dd[1] = __floats2half2_rn(v.z, v.w);
}

// -------------------- w_out concat (coef folded), batched --------------------
__global__ void build_wcat3_kernel(const float* __restrict__ w0, const float* __restrict__ w1,
                                   const float* __restrict__ w2,
                                   const float* __restrict__ c0, const float* __restrict__ c1,
                                   const float* __restrict__ c2,
                                   __half* __restrict__ dst)
{
    int idx = blockIdx.x * blockDim.x + threadIdx.x;
    if (idx >= DIM * DIM / 2) return;
    int i = blockIdx.y;
    const float* w = (i == 0) ? w0 : ((i == 1) ? w1 : w2);
    float c = *((i == 0) ? c0 : ((i == 1) ? c1 : c2));
    float2 v = reinterpret_cast<const float2*>(w)[idx];
    int n = (2 * idx) / DIM, k = (2 * idx) % DIM;
    *reinterpret_cast<__half2*>(&dst[(size_t)n * CSTR + i * DIM + k]) =
        __floats2half2_rn(c * v.x, c * v.y);
}

// -------------------- visual tokens -> two_q/three_q (fp16) --------------------
__global__ void copy_visual_kernel(const float* __restrict__ q,
                                   __half* __restrict__ twoq,
                                   __half* __restrict__ threeq)
{
    int i = blockIdx.x * blockDim.x + threadIdx.x;
    const int n = NR * NB * DIM / 4;
    if (i < n) {
        float4 v = reinterpret_cast<const float4*>(q)[i];
        __half2 h0 = __floats2half2_rn(v.x, v.y);
        __half2 h1 = __floats2half2_rn(v.z, v.w);
        reinterpret_cast<__half2*>(twoq)[2 * i]     = h0;
        reinterpret_cast<__half2*>(twoq)[2 * i + 1] = h1;
        reinterpret_cast<__half2*>(threeq)[2 * i]     = h0;
        reinterpret_cast<__half2*>(threeq)[2 * i + 1] = h1;
    }
}

// -------------------- window aggregation (fp16 outputs) --------------------
__global__ void window_agg_kernel(const float* __restrict__ q,
                                  __half* __restrict__ twoq,
                                  __half* __restrict__ threeq)
{
    int t = blockIdx.x;
    int b = blockIdx.y;
    int tid = threadIdx.x;

    __shared__ float xs[5][DIM];
    __shared__ float red[10][8];
    __shared__ float fin[10];

    #pragma unroll
    for (int w = 0; w < 5; w++) {
        int tw = t + w - 2;
        bool ok = (tw >= 0) && (tw < TT);
        const float* src = q + ((size_t)(NR + tw) * NB + b) * DIM;
        for (int c = tid; c < DIM; c += 256)
            xs[w][c] = ok ? src[c] : 0.0f;
    }
    __syncthreads();

    float p[10];
    #pragma unroll
    for (int k = 0; k < 10; k++) p[k] = 0.0f;

    for (int c = tid; c < DIM; c += 256) {
        float x0 = xs[0][c], x1 = xs[1][c], x2 = xs[2][c], x3 = xs[3][c], x4 = xs[4][c];
        p[0] += x0 * x0;  p[1] += x1 * x1;  p[2] += x2 * x2;
        p[3] += x3 * x3;  p[4] += x4 * x4;
        p[5] += x2 * x1;  p[6] += x2 * x3;
        p[7] += x3 * x0;  p[8] += x3 * x1;  p[9] += x3 * x4;
    }
    #pragma unroll
    for (int o = 16; o; o >>= 1) {
        #pragma unroll
        for (int k = 0; k < 10; k++)
            p[k] += __shfl_xor_sync(0xFFFFFFFFu, p[k], o);
    }
    int wid = tid >> 5, lane = tid & 31;
    if (lane == 0) {
        #pragma unroll
        for (int k = 0; k < 10; k++) red[k][wid] = p[k];
    }
    __syncthreads();
    if (tid < 10) {
        float s = 0.0f;
        #pragma unroll
        for (int w = 0; w < 8; w++) s += red[tid][w];
        fin[tid] = s;
    }
    __syncthreads();

    float n0 = fin[0], n1 = fin[1], n2 = fin[2], n3 = fin[3], n4 = fin[4];
    float in0 = 1.0f / fmaxf(sqrtf(n0), EPSW);
    float in1 = 1.0f / fmaxf(sqrtf(n1), EPSW);
    float in2 = 1.0f / fmaxf(sqrtf(n2), EPSW);
    float in3 = 1.0f / fmaxf(sqrtf(n3), EPSW);
    float in4 = 1.0f / fmaxf(sqrtf(n4), EPSW);

    float w2_1 = fin[5] * in2 * in1;
    float w2_2 = n2     * in2 * in2;
    float w2_3 = fin[6] * in2 * in3;
    float w3_0 = fin[7] * in3 * in0;
    float w3_1 = fin[8] * in3 * in1;
    float w3_2 = fin[6] * in3 * in2;
    float w3_3 = n3     * in3 * in3;
    float w3_4 = fin[9] * in3 * in4;

    size_t base = ((size_t)(NR + t) * NB + b) * DIM;
    for (int c = tid; c < DIM; c += 256) {
        float x0 = xs[0][c], x1 = xs[1][c], x2 = xs[2][c], x3 = xs[3][c], x4 = xs[4][c];
        twoq[base + c]   = __float2half(w2_1 * x1 + w2_2 * x2 + w2_3 * x3);
        threeq[base + c] = __float2half(w3_0 * x0 + w3_1 * x1 + w3_2 * x2 + w3_3 * x3 + w3_4 * x4);
    }
}

// ==================== fp16 NT GEMM (64x64 warp tiles, 128 thr, 3 CTAs/SM) ====================
// EPI 1 (proj): z = wt*3 + mha. A = src table; B = wh + mha*WIN + wt*DIM*DIM;
//               Ch[z*SLAB + r*N + col] = half(acc)
// EPI 3 (final): z = 0; A = A0, B = Bg; Cf[r*N + col] = acc
template<int EPI>
__global__ __launch_bounds__(128, 3)
void hgemm_nt(const __half* __restrict__ A0, const __half* __restrict__ A1,
              const __half* __restrict__ A2, const __half* __restrict__ A3,
              const __half* __restrict__ A4, const __half* __restrict__ Bg,
              float* __restrict__ Cf, __half* __restrict__ Ch,
              int M, int N, int K, int lda, int ldb)
{
    constexpr int BM = 128, BN = 128, BK = 32, ST = 3;
    constexpr int AST = BK + 8;           // 40 halves (u32-stride 20 -> conflict-free)
    constexpr int TS  = BM * AST;         // 5120 halves

    extern __shared__ __half hsm[];
    __half* As = hsm;
    __half* Bs = hsm + ST * TS;

    const int z = blockIdx.z;
    const int wt = z / 3, mha = z - 3 * wt;
    const __half* A;
    const __half* B;
    if (EPI == 1) {
        A = (wt == 0) ? ((mha == 0) ? A0 : ((mha == 1) ? A1 : A2))
                      : ((wt == 1) ? A3 : A4);
        B = Bg + (size_t)mha * WIN + (size_t)wt * DIM * DIM;
    } else {
        A = A0;
        B = Bg;
    }
    const int m0 = blockIdx.y * BM;
    const int n0 = blockIdx.x * BN;
    const int tid = threadIdx.x;
    const int lane = tid & 31;
    const int wid = tid >> 5;
    const int warp_m = (wid >> 1) * 64;
    const int warp_n = (wid & 1) * 64;
    const int gr = lane >> 2;
    const int tg = lane & 3;

    float acc[4][8][4];
    #pragma unroll
    for (int i = 0; i < 4; i++)
        #pragma unroll
        for (int j = 0; j < 8; j++)
            #pragma unroll
            for (int e = 0; e < 4; e++) acc[i][j][e] = 0.0f;

    const int nt = K / BK;

    uint32_t as_sh = (uint32_t)__cvta_generic_to_shared(As);
    uint32_t bs_sh = (uint32_t)__cvta_generic_to_shared(Bs);

    auto load_tile = [&](int s, int kt) {
        int k0 = kt * BK;
        #pragma unroll
        for (int r = 0; r < 4; r++) {
            int c = tid + 128 * r;
            int row = c >> 2, ch = c & 3;
            const __half* g = A + (size_t)(m0 + row) * lda + k0 + ch * 8;
            cp16(as_sh + (s * TS + row * AST + ch * 8) * 2, g);
        }
        #pragma unroll
        for (int r = 0; r < 4; r++) {
            int c = tid + 128 * r;
            int row = c >> 2, ch = c & 3;
            const __half* g = B + (size_t)(n0 + row) * ldb + k0 + ch * 8;
            cp16(bs_sh + (s * TS + row * AST + ch * 8) * 2, g);
        }
    };

    load_tile(0, 0); cp_commit();
    if (nt > 1) load_tile(1, 1);
    cp_commit();

    for (int kt = 0; kt < nt; kt++) {
        cp_wait1();
        __syncthreads();
        if (kt + 2 < nt) load_tile((kt + 2) % ST, kt + 2);
        cp_commit();

        const uint32_t* au = reinterpret_cast<const uint32_t*>(As + (kt % ST) * TS);
        const uint32_t* bu = reinterpret_cast<const uint32_t*>(Bs + (kt % ST) * TS);

        #pragma unroll
        for (int ks = 0; ks < 2; ks++) {
            int kb = ks * 8;
            uint32_t af[4][4];
            #pragma unroll
            for (int i = 0; i < 4; i++) {
                int rb = warp_m + i * 16 + gr;
                af[i][0] = au[rb * 20 + kb + tg];
                af[i][1] = au[(rb + 8) * 20 + kb + tg];
                af[i][2] = au[rb * 20 + kb + tg + 4];
                af[i][3] = au[(rb + 8) * 20 + kb + tg + 4];
            }
            uint32_t bf[8][2];
            #pragma unroll
            for (int j = 0; j < 8; j++) {
                int nb = warp_n + j * 8 + gr;
                bf[j][0] = bu[nb * 20 + kb + tg];
                bf[j][1] = bu[nb * 20 + kb + tg + 4];
            }
            #pragma unroll
            for (int i = 0; i < 4; i++)
                #pragma unroll
                for (int j = 0; j < 8; j++)
                    mma_f16(acc[i][j], af[i], bf[j][0], bf[j][1]);
        }
    }

    #pragma unroll
    for (int i = 0; i < 4; i++) {
        #pragma unroll
        for (int j = 0; j < 8; j++) {
            int row = m0 + warp_m + i * 16 + gr;
            int col = n0 + warp_n + j * 8 + 2 * tg;
            #pragma unroll
            for (int half_ = 0; half_ < 2; half_++) {
                int r = row + half_ * 8;
                float v0 = acc[i][j][half_ * 2 + 0];
                float v1 = acc[i][j][half_ * 2 + 1];
                if (EPI == 1) {
                    *reinterpret_cast<__half2*>(&Ch[(size_t)z * SLAB + (size_t)r * N + col]) =
                        __floats2half2_rn(v0, v1);
                } else {
                    *reinterpret_cast<float2*>(&Cf[(size_t)r * N + col]) = make_float2(v0, v1);
                }
            }
        }
    }
}

// ==================== fused flash attention (64-key tiles, 2 CTAs/SM) ====================
// grid (LQ/128, BH, 3). CTA: 256 thr (8 warps x 16 q-rows). Online softmax.
#define FSTR  104              // smem row stride (halves)
#define FSTRU 52               // in u32
#define FQT  (128*FSTR)        // Q tile halves
#define FKT  (64*FSTR)         // 64-key K/V tile halves
#define NKT  (LQ/64)           // 8 key tiles

__global__ __launch_bounds__(256, 2)
void flash_kernel(const __half* __restrict__ QKV, __half* __restrict__ Ch, float invs)
{
    extern __shared__ __half fsm[];
    __half* Qs = fsm;                    // [128][104]
    __half* Ks = fsm + FQT;              // [2][64][104]
    __half* Vs = Ks + 2 * FKT;           // [2][64][104]

    const int z  = blockIdx.y;           // b*8 + h
    const int z2 = blockIdx.z;           // MHA index
    const size_t hoff = (size_t)(z >> 3) * DIM + (size_t)(z & 7) * HD;
    const __half* Qg = QKV + (size_t)(0 + z2) * SLAB + hoff;
    const __half* Kg = QKV + (size_t)(3 + z2) * SLAB + hoff;
    const __half* Vg = QKV + (size_t)(6 + z2) * SLAB + hoff;
    const int m0 = blockIdx.x * 128;
    const int tid = threadIdx.x;
    const int lane = tid & 31;
    const int wid = tid >> 5;
    const int gr = lane >> 2, tg = lane & 3;

    uint32_t qs_sh = (uint32_t)__cvta_generic_to_shared(Qs);
    uint32_t ks_sh = (uint32_t)__cvta_generic_to_shared(Ks);
    uint32_t vs_sh = (uint32_t)__cvta_generic_to_shared(Vs);

    // Q loader: 128 rows x 12 chunks
    auto load_q = [&]() {
        #pragma unroll
        for (int r = 0; r < 6; r++) {
            int c = tid + 256 * r;
            int row = c / 12, ch = c % 12;
            cp16(qs_sh + (row * FSTR + ch * 8) * 2,
                 Qg + (size_t)(m0 + row) * LDQ + ch * 8);
        }
    };
    // 64-row K/V tile loader
    auto load_kv = [&](uint32_t dst_sh, const __half* src, int l0) {
        #pragma unroll
        for (int r = 0; r < 3; r++) {
            int c = tid + 256 * r;
            int row = c / 12, ch = c % 12;
            cp16(dst_sh + (row * FSTR + ch * 8) * 2,
                 src + (size_t)(l0 + row) * LDQ + ch * 8);
        }
    };

    load_q();
    load_kv(ks_sh, Kg, 0);
    load_kv(vs_sh, Vg, 0);
    cp_commit();
    load_kv(ks_sh + FKT * 2, Kg, 64);
    load_kv(vs_sh + FKT * 2, Vg, 64);
    cp_commit();

    uint32_t qfrag[6][4];
    float o[12][4];
    #pragma unroll
    for (int j = 0; j < 12; j++)
        #pragma unroll
        for (int e = 0; e < 4; e++) o[j][e] = 0.0f;
    float m0r = -1e30f, m1r = -1e30f, l0s = 0.0f, l1s = 0.0f;

    const int lg = lane >> 3, li = lane & 7;
    const int laneoff = ((lg & 1) * 8 + li) * FSTR + (lg >> 1) * 8;

    #pragma unroll
    for (int kt = 0; kt < NKT; kt++) {
        if (kt < NKT - 1) { asm volatile("cp.async.wait_group 1;\n"); }
        else              { asm volatile("cp.async.wait_group 0;\n"); }
        __syncthreads();

        if (kt == 0) {
            const uint32_t* qu = reinterpret_cast<const uint32_t*>(Qs);
            #pragma unroll
            for (int ks = 0; ks < 6; ks++) {
                int rb = wid * 16 + gr;
                qfrag[ks][0] = qu[rb * FSTRU + ks * 8 + tg];
                qfrag[ks][1] = qu[(rb + 8) * FSTRU + ks * 8 + tg];
                qfrag[ks][2] = qu[rb * FSTRU + ks * 8 + tg + 4];
                qfrag[ks][3] = qu[(rb + 8) * FSTRU + ks * 8 + tg + 4];
            }
        }

        const int st = kt & 1;
        const uint32_t* ku = reinterpret_cast<const uint32_t*>(Ks + st * FKT);
        const uint32_t vbase = vs_sh + (st * FKT + laneoff) * 2;

        // ---- S = Q K^T (16 x 64) ----
        float s[8][4];
        #pragma unroll
        for (int nf = 0; nf < 8; nf++)
            #pragma unroll
            for (int e = 0; e < 4; e++) s[nf][e] = 0.0f;
        #pragma unroll
        for (int ks = 0; ks < 6; ks++) {
            #pragma unroll
            for (int nf = 0; nf < 8; nf++) {
                int nb = nf * 8 + gr;
                uint32_t b0 = ku[nb * FSTRU + ks * 8 + tg];
                uint32_t b1 = ku[nb * FSTRU + ks * 8 + tg + 4];
                mma_f16(s[nf], qfrag[ks], b0, b1);
            }
        }

        // ---- online softmax ----
        float mx0 = -1e30f, mx1 = -1e30f;
        #pragma unroll
        for (int nf = 0; nf < 8; nf++) {
            s[nf][0] *= invs; s[nf][1] *= invs; s[nf][2] *= invs; s[nf][3] *= invs;
            mx0 = fmaxf(mx0, fmaxf(s[nf][0], s[nf][1]));
            mx1 = fmaxf(mx1, fmaxf(s[nf][2], s[nf][3]));
        }
        mx0 = fmaxf(mx0, __shfl_xor_sync(0xFFFFFFFFu, mx0, 1));
        mx0 = fmaxf(mx0, __shfl_xor_sync(0xFFFFFFFFu, mx0, 2));
        mx1 = fmaxf(mx1, __shfl_xor_sync(0xFFFFFFFFu, mx1, 1));
        mx1 = fmaxf(mx1, __shfl_xor_sync(0xFFFFFFFFu, mx1, 2));

        float mn0 = fmaxf(m0r, mx0), mn1 = fmaxf(m1r, mx1);
        float al0 = __expf(m0r - mn0), al1 = __expf(m1r - mn1);
        m0r = mn0; m1r = mn1;

        float rs0 = 0.0f, rs1 = 0.0f;
        uint32_t ph[16];
        #pragma unroll
        for (int nf = 0; nf < 8; nf++) {
            float p0 = __expf(s[nf][0] - mn0);
            float p1 = __expf(s[nf][1] - mn0);
            float p2 = __expf(s[nf][2] - mn1);
            float p3 = __expf(s[nf][3] - mn1);
            rs0 += p0 + p1; rs1 += p2 + p3;
            ph[2 * nf]     = packh2(p0, p1);
            ph[2 * nf + 1] = packh2(p2, p3);
        }
        rs0 += __shfl_xor_sync(0xFFFFFFFFu, rs0, 1);
        rs0 += __shfl_xor_sync(0xFFFFFFFFu, rs0, 2);
        rs1 += __shfl_xor_sync(0xFFFFFFFFu, rs1, 1);
        rs1 += __shfl_xor_sync(0xFFFFFFFFu, rs1, 2);
        l0s = l0s * al0 + rs0;
        l1s = l1s * al1 + rs1;

        #pragma unroll
        for (int j = 0; j < 12; j++) {
            o[j][0] *= al0; o[j][1] *= al0;
            o[j][2] *= al1; o[j][3] *= al1;
        }

        // ---- O += P V (P: 16x64 fp16 frags; V via ldmatrix.trans) ----
        #pragma unroll
        for (int s8 = 0; s8 < 4; s8++) {
            const uint32_t* a = &ph[4 * s8];
            #pragma unroll
            for (int np = 0; np < 6; np++) {
                uint32_t r0, r1, r2, r3;
                ldmx4t(r0, r1, r2, r3, vbase + (s8 * 16 * FSTR + np * 16) * 2);
                mma_f16(o[2 * np],     a, r0, r1);
                mma_f16(o[2 * np + 1], a, r2, r3);
            }
        }

        __syncthreads();
        if (kt + 2 < NKT) {
            load_kv(ks_sh + st * FKT * 2, Kg, (kt + 2) * 64);
            load_kv(vs_sh + st * FKT * 2, Vg, (kt + 2) * 64);
        }
        cp_commit();
    }

    // ---- normalize + write ctx into [M, 2304] concat ----
    float il0 = 1.0f / l0s, il1 = 1.0f / l1s;
    int r0 = m0 + wid * 16 + gr;
    int r1 = r0 + 8;
    const size_t cbase = (size_t)(z >> 3) * CSTR + (size_t)z2 * DIM + (size_t)(z & 7) * HD;
    #pragma unroll
    for (int j = 0; j < 12; j++) {
        int col = j * 8 + 2 * tg;
        *reinterpret_cast<__half2*>(&Ch[(size_t)r0 * NB * CSTR + cbase + col]) =
            __floats2half2_rn(o[j][0] * il0, o[j][1] * il0);
        *reinterpret_cast<__half2*>(&Ch[(size_t)r1 * NB * CSTR + cbase + col]) =
            __floats2half2_rn(o[j][2] * il1, o[j][3] * il1);
    }
}

// -------------------- launch --------------------
template<typename T>
static T* sym_addr_t(const void* symbol)
{
    void* p = nullptr;
    cudaGetSymbolAddress(&p, symbol);
    return reinterpret_cast<T*>(p);
}

extern "C" void kernel_launch(void* const* d_in, const int* in_sizes, int n_in,
                              void* d_out, int out_size)
{
    const float* query = (const float*)d_in[0];
    const float* keyi  = (const float*)d_in[1];
    const float* value = (const float*)d_in[2];
    const float* w_in[3]  = { (const float*)d_in[3], (const float*)d_in[5], (const float*)d_in[7] };
    const float* w_out[3] = { (const float*)d_in[4], (const float*)d_in[6], (const float*)d_in[8] };
    const float* coef[3]  = { (const float*)d_in[9], (const float*)d_in[10], (const float*)d_in[11] };
    float* out = (float*)d_out;

    __half* qh  = sym_addr_t<__half>(g_qh);
    __half* kh  = sym_addr_t<__half>(g_kh);
    __half* vh  = sym_addr_t<__half>(g_vh);
    __half* twoq   = sym_addr_t<__half>(g_twoq);
    __half* threeq = sym_addr_t<__half>(g_threeq);
    __half* wh   = sym_addr_t<__half>(g_wh);
    __half* wcat = sym_addr_t<__half>(g_wcat);
    __half* QKV  = sym_addr_t<__half>(g_QKV);
    __half* ctx  = sym_addr_t<__half>(g_ctx);

    const float invs = 1.0f / sqrtf((float)HD);

    const int SM_H = 3 * 2 * 128 * 40 * 2;                 // 61440 B
    const int SM_F = (FQT + 4 * FKT) * 2;                  // 79872 B
    cudaFuncSetAttribute(hgemm_nt<1>, cudaFuncAttributeMaxDynamicSharedMemorySize, SM_H);
    cudaFuncSetAttribute(hgemm_nt<3>, cudaFuncAttributeMaxDynamicSharedMemorySize, SM_H);
    cudaFuncSetAttribute(flash_kernel, cudaFuncAttributeMaxDynamicSharedMemorySize, SM_F);

    // ---- prep: conversions, wcat, window aggregation (batched) ----
    {
        int n4 = MLB * DIM / 4;
        cvt3_kernel<<<dim3((n4 + 255) / 256, 3), 256>>>(query, keyi, value, qh, kh, vh, n4);
        int nwi = 2304 * DIM / 4;
        cvt3_kernel<<<dim3((nwi + 255) / 256, 3), 256>>>(
            w_in[0], w_in[1], w_in[2], wh, wh + WIN, wh + 2 * (size_t)WIN, nwi);
        int nwc = DIM * DIM / 2;
        build_wcat3_kernel<<<dim3((nwc + 255) / 256, 3), 256>>>(
            w_out[0], w_out[1], w_out[2], coef[0], coef[1], coef[2], wcat);
        int nv4 = NR * NB * DIM / 4;
        copy_visual_kernel<<<(nv4 + 255) / 256, 256>>>(query, twoq, threeq);
        window_agg_kernel<<<dim3(TT, NB), 256>>>(query, twoq, threeq);
    }

    dim3 gP(DIM / 128, MLB / 128, 9);       // all 9 projections in one launch
    dim3 gFin(DIM / 128, MLB / 128, 1);     // final K=2304
    dim3 gF(LQ / 128, BH, 3);               // batched flash

    // Q/K/V projections -> QKV slabs (z = wt*3 + mha)
    hgemm_nt<1><<<gP, 128, SM_H>>>(qh, twoq, threeq, kh, vh, wh, nullptr, QKV,
        MLB, DIM, DIM, DIM, DIM);

    // fused attention (all 3 MHAs) -> ctx [M, 2304]
    flash_kernel<<<gF, 256, SM_F>>>(QKV, ctx, invs);

    // out = ctx @ wcat^T  (K=2304, coef folded)
    hgemm_nt<3><<<gFin, 128, SM_H>>>(ctx, ctx, ctx, ctx, ctx, wcat, out, nullptr,
        MLB, DIM, CSTR, CSTR, CSTR);
}

// round 12
// speedup vs baseline: 9.1106x; 1.0603x over previous
#include <cuda_runtime.h>
#include <cuda_fp16.h>
#include <math.h>
#include <stdint.h>

// Problem constants (fixed shapes)
#define LQ   512
#define NB   32
#define DIM  768
#define NH   8
#define HD   96
#define NR   196
#define TT   316               // text length
#define MLB  (LQ*NB)           // 16384
#define BH   (NB*NH)           // 256
#define LDQ  (NB*DIM)          // 24576 row stride of [L,B,D] per l
#define CSTR (3*DIM)           // 2304: ctxcat row stride
#define WIN  (2304*DIM)        // fp16 w_in slab per MHA
#define SLAB ((size_t)MLB*DIM) // one [L,B,D] fp16 slab
#define EPSW 1e-8f

// -------------------- device scratch --------------------
__device__ __half g_qh [MLB*DIM];
__device__ __half g_kh [MLB*DIM];
__device__ __half g_vh [MLB*DIM];
__device__ __half g_twoq  [MLB*DIM];
__device__ __half g_threeq[MLB*DIM];
__device__ __half g_wh  [3*WIN];              // fp16 w_in x3
__device__ __half g_wcat[DIM*CSTR];           // [768, 2304] coef-folded w_out concat
__device__ __half g_QKV[9*MLB*DIM];           // slabs: z=wt*3+mha (Q:0-2, K:3-5, V:6-8)
__device__ __half g_ctx[(size_t)MLB*CSTR];    // [M, 2304] ctx concat

// -------------------- PTX helpers --------------------
__device__ __forceinline__ void cp16(uint32_t dst, const void* gptr) {
    asm volatile("cp.async.cg.shared.global [%0], [%1], 16;\n" :: "r"(dst), "l"(gptr));
}
__device__ __forceinline__ void cp_commit() { asm volatile("cp.async.commit_group;\n"); }
__device__ __forceinline__ void cp_wait1()  { asm volatile("cp.async.wait_group 1;\n"); }

__device__ __forceinline__ void mma_f16(float c[4], const uint32_t a[4],
                                        uint32_t b0, uint32_t b1) {
    asm volatile("mma.sync.aligned.m16n8k16.row.col.f32.f16.f16.f32 "
        "{%0,%1,%2,%3}, {%4,%5,%6,%7}, {%8,%9}, {%0,%1,%2,%3};\n"
        : "+f"(c[0]), "+f"(c[1]), "+f"(c[2]), "+f"(c[3])
        : "r"(a[0]), "r"(a[1]), "r"(a[2]), "r"(a[3]), "r"(b0), "r"(b1));
}
__device__ __forceinline__ void ldmx4(uint32_t& r0, uint32_t& r1,
                                      uint32_t& r2, uint32_t& r3, uint32_t addr) {
    asm volatile("ldmatrix.sync.aligned.m8n8.x4.shared.b16 {%0,%1,%2,%3}, [%4];"
        : "=r"(r0), "=r"(r1), "=r"(r2), "=r"(r3) : "r"(addr));
}
__device__ __forceinline__ void ldmx4t(uint32_t& r0, uint32_t& r1,
                                       uint32_t& r2, uint32_t& r3, uint32_t addr) {
    asm volatile("ldmatrix.sync.aligned.m8n8.x4.trans.shared.b16 {%0,%1,%2,%3}, [%4];"
        : "=r"(r0), "=r"(r1), "=r"(r2), "=r"(r3) : "r"(addr));
}
__device__ __forceinline__ uint32_t packh2(float lo, float hi) {
    __half2 h = __floats2half2_rn(lo, hi);
    return reinterpret_cast<uint32_t&>(h);
}

// -------------------- batched fp32 -> fp16 conversions --------------------
__global__ void cvt3_kernel(const float* __restrict__ s0, const float* __restrict__ s1,
                            const float* __restrict__ s2,
                            __half* __restrict__ d0, __half* __restrict__ d1,
                            __half* __restrict__ d2, int n4)
{
    int i = blockIdx.x * blockDim.x + threadIdx.x;
    if (i >= n4) return;
    int zz = blockIdx.y;
    const float* s = (zz == 0) ? s0 : ((zz == 1) ? s1 : s2);
    __half* d = (zz == 0) ? d0 : ((zz == 1) ? d1 : d2);
    float4 v = reinterpret_cast<const float4*>(s)[i];
    __half2* dd = reinterpret_cast<__half2*>(d) + 2 * i;
    dd[0] = __floats2half2_rn(v.x, v.y);
    dd[1] = __floats2half2_rn(v.z, v.w);
}

// -------------------- w_out concat (coef folded), batched --------------------
__global__ void build_wcat3_kernel(const float* __restrict__ w0, const float* __restrict__ w1,
                                   const float* __restrict__ w2,
                                   const float* __restrict__ c0, const float* __restrict__ c1,
                                   const float* __restrict__ c2,
                                   __half* __restrict__ dst)
{
    int idx = blockIdx.x * blockDim.x + threadIdx.x;
    if (idx >= DIM * DIM / 2) return;
    int i = blockIdx.y;
    const float* w = (i == 0) ? w0 : ((i == 1) ? w1 : w2);
    float c = *((i == 0) ? c0 : ((i == 1) ? c1 : c2));
    float2 v = reinterpret_cast<const float2*>(w)[idx];
    int n = (2 * idx) / DIM, k = (2 * idx) % DIM;
    *reinterpret_cast<__half2*>(&dst[(size_t)n * CSTR + i * DIM + k]) =
        __floats2half2_rn(c * v.x, c * v.y);
}

// -------------------- visual tokens -> two_q/three_q (fp16) --------------------
__global__ void copy_visual_kernel(const float* __restrict__ q,
                                   __half* __restrict__ twoq,
                                   __half* __restrict__ threeq)
{
    int i = blockIdx.x * blockDim.x + threadIdx.x;
    const int n = NR * NB * DIM / 4;
    if (i < n) {
        float4 v = reinterpret_cast<const float4*>(q)[i];
        __half2 h0 = __floats2half2_rn(v.x, v.y);
        __half2 h1 = __floats2half2_rn(v.z, v.w);
        reinterpret_cast<__half2*>(twoq)[2 * i]     = h0;
        reinterpret_cast<__half2*>(twoq)[2 * i + 1] = h1;
        reinterpret_cast<__half2*>(threeq)[2 * i]     = h0;
        reinterpret_cast<__half2*>(threeq)[2 * i + 1] = h1;
    }
}

// -------------------- window aggregation (fp16 outputs) --------------------
__global__ void window_agg_kernel(const float* __restrict__ q,
                                  __half* __restrict__ twoq,
                                  __half* __restrict__ threeq)
{
    int t = blockIdx.x;
    int b = blockIdx.y;
    int tid = threadIdx.x;

    __shared__ float xs[5][DIM];
    __shared__ float red[10][8];
    __shared__ float fin[10];

    #pragma unroll
    for (int w = 0; w < 5; w++) {
        int tw = t + w - 2;
        bool ok = (tw >= 0) && (tw < TT);
        const float* src = q + ((size_t)(NR + tw) * NB + b) * DIM;
        for (int c = tid; c < DIM; c += 256)
            xs[w][c] = ok ? src[c] : 0.0f;
    }
    __syncthreads();

    float p[10];
    #pragma unroll
    for (int k = 0; k < 10; k++) p[k] = 0.0f;

    for (int c = tid; c < DIM; c += 256) {
        float x0 = xs[0][c], x1 = xs[1][c], x2 = xs[2][c], x3 = xs[3][c], x4 = xs[4][c];
        p[0] += x0 * x0;  p[1] += x1 * x1;  p[2] += x2 * x2;
        p[3] += x3 * x3;  p[4] += x4 * x4;
        p[5] += x2 * x1;  p[6] += x2 * x3;
        p[7] += x3 * x0;  p[8] += x3 * x1;  p[9] += x3 * x4;
    }
    #pragma unroll
    for (int o = 16; o; o >>= 1) {
        #pragma unroll
        for (int k = 0; k < 10; k++)
            p[k] += __shfl_xor_sync(0xFFFFFFFFu, p[k], o);
    }
    int wid = tid >> 5, lane = tid & 31;
    if (lane == 0) {
        #pragma unroll
        for (int k = 0; k < 10; k++) red[k][wid] = p[k];
    }
    __syncthreads();
    if (tid < 10) {
        float s = 0.0f;
        #pragma unroll
        for (int w = 0; w < 8; w++) s += red[tid][w];
        fin[tid] = s;
    }
    __syncthreads();

    float n0 = fin[0], n1 = fin[1], n2 = fin[2], n3 = fin[3], n4 = fin[4];
    float in0 = 1.0f / fmaxf(sqrtf(n0), EPSW);
    float in1 = 1.0f / fmaxf(sqrtf(n1), EPSW);
    float in2 = 1.0f / fmaxf(sqrtf(n2), EPSW);
    float in3 = 1.0f / fmaxf(sqrtf(n3), EPSW);
    float in4 = 1.0f / fmaxf(sqrtf(n4), EPSW);

    float w2_1 = fin[5] * in2 * in1;
    float w2_2 = n2     * in2 * in2;
    float w2_3 = fin[6] * in2 * in3;
    float w3_0 = fin[7] * in3 * in0;
    float w3_1 = fin[8] * in3 * in1;
    float w3_2 = fin[6] * in3 * in2;
    float w3_3 = n3     * in3 * in3;
    float w3_4 = fin[9] * in3 * in4;

    size_t base = ((size_t)(NR + t) * NB + b) * DIM;
    for (int c = tid; c < DIM; c += 256) {
        float x0 = xs[0][c], x1 = xs[1][c], x2 = xs[2][c], x3 = xs[3][c], x4 = xs[4][c];
        twoq[base + c]   = __float2half(w2_1 * x1 + w2_2 * x2 + w2_3 * x3);
        threeq[base + c] = __float2half(w3_0 * x0 + w3_1 * x1 + w3_2 * x2 + w3_3 * x3 + w3_4 * x4);
    }
}

// ==================== fp16 NT GEMM (64x64 warp tiles, ldmatrix frags) ====================
// EPI 1 (proj): z = wt*3 + mha. A = src table; B = wh + mha*WIN + wt*DIM*DIM;
//               Ch[z*SLAB + r*N + col] = half(acc)
// EPI 3 (final): z = 0; A = A0, B = Bg; Cf[r*N + col] = acc
template<int EPI>
__global__ __launch_bounds__(128, 3)
void hgemm_nt(const __half* __restrict__ A0, const __half* __restrict__ A1,
              const __half* __restrict__ A2, const __half* __restrict__ A3,
              const __half* __restrict__ A4, const __half* __restrict__ Bg,
              float* __restrict__ Cf, __half* __restrict__ Ch,
              int M, int N, int K, int lda, int ldb)
{
    constexpr int BM = 128, BN = 128, BK = 32, ST = 3;
    constexpr int AST = BK + 8;           // 40 halves (80B rows -> conflict-free ldmatrix)
    constexpr int TS  = BM * AST;         // 5120 halves

    extern __shared__ __half hsm[];
    __half* As = hsm;
    __half* Bs = hsm + ST * TS;

    const int z = blockIdx.z;
    const int wt = z / 3, mha = z - 3 * wt;
    const __half* A;
    const __half* B;
    if (EPI == 1) {
        A = (wt == 0) ? ((mha == 0) ? A0 : ((mha == 1) ? A1 : A2))
                      : ((wt == 1) ? A3 : A4);
        B = Bg + (size_t)mha * WIN + (size_t)wt * DIM * DIM;
    } else {
        A = A0;
        B = Bg;
    }
    const int m0 = blockIdx.y * BM;
    const int n0 = blockIdx.x * BN;
    const int tid = threadIdx.x;
    const int lane = tid & 31;
    const int wid = tid >> 5;
    const int warp_m = (wid >> 1) * 64;
    const int warp_n = (wid & 1) * 64;
    const int gr = lane >> 2;
    const int tg = lane & 3;
    const int lg = lane >> 3, li = lane & 7;

    float acc[4][8][4];
    #pragma unroll
    for (int i = 0; i < 4; i++)
        #pragma unroll
        for (int j = 0; j < 8; j++)
            #pragma unroll
            for (int e = 0; e < 4; e++) acc[i][j][e] = 0.0f;

    const int nt = K / BK;

    uint32_t as_sh = (uint32_t)__cvta_generic_to_shared(As);
    uint32_t bs_sh = (uint32_t)__cvta_generic_to_shared(Bs);

    // per-lane ldmatrix offsets (halves)
    // A: matrices (lg&1)->row half, (lg>>1)->k half of the 16x16 fragment
    const int a_lane = ((lg & 1) * 8 + li) * AST + (lg >> 1) * 8;
    // B: matrices (lg>>1)->n half (j pair), (lg&1)->k half
    const int b_lane = ((lg >> 1) * 8 + li) * AST + (lg & 1) * 8;

    auto load_tile = [&](int s, int kt) {
        int k0 = kt * BK;
        #pragma unroll
        for (int r = 0; r < 4; r++) {
            int c = tid + 128 * r;
            int row = c >> 2, ch = c & 3;
            const __half* g = A + (size_t)(m0 + row) * lda + k0 + ch * 8;
            cp16(as_sh + (s * TS + row * AST + ch * 8) * 2, g);
        }
        #pragma unroll
        for (int r = 0; r < 4; r++) {
            int c = tid + 128 * r;
            int row = c >> 2, ch = c & 3;
            const __half* g = B + (size_t)(n0 + row) * ldb + k0 + ch * 8;
            cp16(bs_sh + (s * TS + row * AST + ch * 8) * 2, g);
        }
    };

    load_tile(0, 0); cp_commit();
    if (nt > 1) load_tile(1, 1);
    cp_commit();

    for (int kt = 0; kt < nt; kt++) {
        cp_wait1();
        __syncthreads();
        if (kt + 2 < nt) load_tile((kt + 2) % ST, kt + 2);
        cp_commit();

        const uint32_t abase = as_sh + ((kt % ST) * TS + a_lane) * 2;
        const uint32_t bbase = bs_sh + ((kt % ST) * TS + b_lane) * 2;

        #pragma unroll
        for (int ks = 0; ks < 2; ks++) {
            int kh2 = ks * 16 * 2;                 // k halves offset in bytes
            uint32_t af[4][4];
            #pragma unroll
            for (int i = 0; i < 4; i++)
                ldmx4(af[i][0], af[i][1], af[i][2], af[i][3],
                      abase + (warp_m + i * 16) * AST * 2 + kh2);
            uint32_t bf[8][2];
            #pragma unroll
            for (int j2 = 0; j2 < 4; j2++)
                ldmx4(bf[2 * j2][0], bf[2 * j2][1], bf[2 * j2 + 1][0], bf[2 * j2 + 1][1],
                      bbase + (warp_n + j2 * 16) * AST * 2 + kh2);
            #pragma unroll
            for (int i = 0; i < 4; i++)
                #pragma unroll
                for (int j = 0; j < 8; j++)
                    mma_f16(acc[i][j], af[i], bf[j][0], bf[j][1]);
        }
    }

    #pragma unroll
    for (int i = 0; i < 4; i++) {
        #pragma unroll
        for (int j = 0; j < 8; j++) {
            int row = m0 + warp_m + i * 16 + gr;
            int col = n0 + warp_n + j * 8 + 2 * tg;
            #pragma unroll
            for (int half_ = 0; half_ < 2; half_++) {
                int r = row + half_ * 8;
                float v0 = acc[i][j][half_ * 2 + 0];
                float v1 = acc[i][j][half_ * 2 + 1];
                if (EPI == 1) {
                    *reinterpret_cast<__half2*>(&Ch[(size_t)z * SLAB + (size_t)r * N + col]) =
                        __floats2half2_rn(v0, v1);
                } else {
                    *reinterpret_cast<float2*>(&Cf[(size_t)r * N + col]) = make_float2(v0, v1);
                }
            }
        }
    }
}

// ==================== fused flash attention (64-key tiles, 2 CTAs/SM) ====================
#define FSTR  104              // smem row stride (halves)
#define FSTRU 52               // in u32
#define FQT  (128*FSTR)        // Q tile halves
#define FKT  (64*FSTR)         // 64-key K/V tile halves
#define NKT  (LQ/64)           // 8 key tiles

__global__ __launch_bounds__(256, 2)
void flash_kernel(const __half* __restrict__ QKV, __half* __restrict__ Ch, float invs)
{
    extern __shared__ __half fsm[];
    __half* Qs = fsm;                    // [128][104]
    __half* Ks = fsm + FQT;              // [2][64][104]
    __half* Vs = Ks + 2 * FKT;           // [2][64][104]

    const int z  = blockIdx.y;           // b*8 + h
    const int z2 = blockIdx.z;           // MHA index
    const size_t hoff = (size_t)(z >> 3) * DIM + (size_t)(z & 7) * HD;
    const __half* Qg = QKV + (size_t)(0 + z2) * SLAB + hoff;
    const __half* Kg = QKV + (size_t)(3 + z2) * SLAB + hoff;
    const __half* Vg = QKV + (size_t)(6 + z2) * SLAB + hoff;
    const int m0 = blockIdx.x * 128;
    const int tid = threadIdx.x;
    const int lane = tid & 31;
    const int wid = tid >> 5;
    const int gr = lane >> 2, tg = lane & 3;

    uint32_t qs_sh = (uint32_t)__cvta_generic_to_shared(Qs);
    uint32_t ks_sh = (uint32_t)__cvta_generic_to_shared(Ks);
    uint32_t vs_sh = (uint32_t)__cvta_generic_to_shared(Vs);

    auto load_q = [&]() {
        #pragma unroll
        for (int r = 0; r < 6; r++) {
            int c = tid + 256 * r;
            int row = c / 12, ch = c % 12;
            cp16(qs_sh + (row * FSTR + ch * 8) * 2,
                 Qg + (size_t)(m0 + row) * LDQ + ch * 8);
        }
    };
    auto load_kv = [&](uint32_t dst_sh, const __half* src, int l0) {
        #pragma unroll
        for (int r = 0; r < 3; r++) {
            int c = tid + 256 * r;
            int row = c / 12, ch = c % 12;
            cp16(dst_sh + (row * FSTR + ch * 8) * 2,
                 src + (size_t)(l0 + row) * LDQ + ch * 8);
        }
    };

    load_q();
    load_kv(ks_sh, Kg, 0);
    load_kv(vs_sh, Vg, 0);
    cp_commit();
    load_kv(ks_sh + FKT * 2, Kg, 64);
    load_kv(vs_sh + FKT * 2, Vg, 64);
    cp_commit();

    uint32_t qfrag[6][4];
    float o[12][4];
    #pragma unroll
    for (int j = 0; j < 12; j++)
        #pragma unroll
        for (int e = 0; e < 4; e++) o[j][e] = 0.0f;
    float m0r = -1e30f, m1r = -1e30f, l0s = 0.0f, l1s = 0.0f;

    const int lg = lane >> 3, li = lane & 7;
    const int laneoff = ((lg & 1) * 8 + li) * FSTR + (lg >> 1) * 8;

    #pragma unroll
    for (int kt = 0; kt < NKT; kt++) {
        if (kt < NKT - 1) { asm volatile("cp.async.wait_group 1;\n"); }
        else              { asm volatile("cp.async.wait_group 0;\n"); }
        __syncthreads();

        if (kt == 0) {
            const uint32_t* qu = reinterpret_cast<const uint32_t*>(Qs);
            #pragma unroll
            for (int ks = 0; ks < 6; ks++) {
                int rb = wid * 16 + gr;
                qfrag[ks][0] = qu[rb * FSTRU + ks * 8 + tg];
                qfrag[ks][1] = qu[(rb + 8) * FSTRU + ks * 8 + tg];
                qfrag[ks][2] = qu[rb * FSTRU + ks * 8 + tg + 4];
                qfrag[ks][3] = qu[(rb + 8) * FSTRU + ks * 8 + tg + 4];
            }
        }

        const int st = kt & 1;
        const uint32_t* ku = reinterpret_cast<const uint32_t*>(Ks + st * FKT);
        const uint32_t vbase = vs_sh + (st * FKT + laneoff) * 2;

        float s[8][4];
        #pragma unroll
        for (int nf = 0; nf < 8; nf++)
            #pragma unroll
            for (int e = 0; e < 4; e++) s[nf][e] = 0.0f;
        #pragma unroll
        for (int ks = 0; ks < 6; ks++) {
            #pragma unroll
            for (int nf = 0; nf < 8; nf++) {
                int nb = nf * 8 + gr;
                uint32_t b0 = ku[nb * FSTRU + ks * 8 + tg];
                uint32_t b1 = ku[nb * FSTRU + ks * 8 + tg + 4];
                mma_f16(s[nf], qfrag[ks], b0, b1);
            }
        }

        float mx0 = -1e30f, mx1 = -1e30f;
        #pragma unroll
        for (int nf = 0; nf < 8; nf++) {
            s[nf][0] *= invs; s[nf][1] *= invs; s[nf][2] *= invs; s[nf][3] *= invs;
            mx0 = fmaxf(mx0, fmaxf(s[nf][0], s[nf][1]));
            mx1 = fmaxf(mx1, fmaxf(s[nf][2], s[nf][3]));
        }
        mx0 = fmaxf(mx0, __shfl_xor_sync(0xFFFFFFFFu, mx0, 1));
        mx0 = fmaxf(mx0, __shfl_xor_sync(0xFFFFFFFFu, mx0, 2));
        mx1 = fmaxf(mx1, __shfl_xor_sync(0xFFFFFFFFu, mx1, 1));
        mx1 = fmaxf(mx1, __shfl_xor_sync(0xFFFFFFFFu, mx1, 2));

        float mn0 = fmaxf(m0r, mx0), mn1 = fmaxf(m1r, mx1);
        float al0 = __expf(m0r - mn0), al1 = __expf(m1r - mn1);
        m0r = mn0; m1r = mn1;

        float rs0 = 0.0f, rs1 = 0.0f;
        uint32_t ph[16];
        #pragma unroll
        for (int nf = 0; nf < 8; nf++) {
            float p0 = __expf(s[nf][0] - mn0);
            float p1 = __expf(s[nf][1] - mn0);
            float p2 = __expf(s[nf][2] - mn1);
            float p3 = __expf(s[nf][3] - mn1);
            rs0 += p0 + p1; rs1 += p2 + p3;
            ph[2 * nf]     = packh2(p0, p1);
            ph[2 * nf + 1] = packh2(p2, p3);
        }
        rs0 += __shfl_xor_sync(0xFFFFFFFFu, rs0, 1);
        rs0 += __shfl_xor_sync(0xFFFFFFFFu, rs0, 2);
        rs1 += __shfl_xor_sync(0xFFFFFFFFu, rs1, 1);
        rs1 += __shfl_xor_sync(0xFFFFFFFFu, rs1, 2);
        l0s = l0s * al0 + rs0;
        l1s = l1s * al1 + rs1;

        #pragma unroll
        for (int j = 0; j < 12; j++) {
            o[j][0] *= al0; o[j][1] *= al0;
            o[j][2] *= al1; o[j][3] *= al1;
        }

        #pragma unroll
        for (int s8 = 0; s8 < 4; s8++) {
            const uint32_t* a = &ph[4 * s8];
            #pragma unroll
            for (int np = 0; np < 6; np++) {
                uint32_t r0, r1, r2, r3;
                ldmx4t(r0, r1, r2, r3, vbase + (s8 * 16 * FSTR + np * 16) * 2);
                mma_f16(o[2 * np],     a, r0, r1);
                mma_f16(o[2 * np + 1], a, r2, r3);
            }
        }

        __syncthreads();
        if (kt + 2 < NKT) {
            load_kv(ks_sh + st * FKT * 2, Kg, (kt + 2) * 64);
            load_kv(vs_sh + st * FKT * 2, Vg, (kt + 2) * 64);
        }
        cp_commit();
    }

    float il0 = 1.0f / l0s, il1 = 1.0f / l1s;
    int r0 = m0 + wid * 16 + gr;
    int r1 = r0 + 8;
    const size_t cbase = (size_t)(z >> 3) * CSTR + (size_t)z2 * DIM + (size_t)(z & 7) * HD;
    #pragma unroll
    for (int j = 0; j < 12; j++) {
        int col = j * 8 + 2 * tg;
        *reinterpret_cast<__half2*>(&Ch[(size_t)r0 * NB * CSTR + cbase + col]) =
            __floats2half2_rn(o[j][0] * il0, o[j][1] * il0);
        *reinterpret_cast<__half2*>(&Ch[(size_t)r1 * NB * CSTR + cbase + col]) =
            __floats2half2_rn(o[j][2] * il1, o[j][3] * il1);
    }
}

// -------------------- launch --------------------
template<typename T>
static T* sym_addr_t(const void* symbol)
{
    void* p = nullptr;
    cudaGetSymbolAddress(&p, symbol);
    return reinterpret_cast<T*>(p);
}

extern "C" void kernel_launch(void* const* d_in, const int* in_sizes, int n_in,
                              void* d_out, int out_size)
{
    const float* query = (const float*)d_in[0];
    const float* keyi  = (const float*)d_in[1];
    const float* value = (const float*)d_in[2];
    const float* w_in[3]  = { (const float*)d_in[3], (const float*)d_in[5], (const float*)d_in[7] };
    const float* w_out[3] = { (const float*)d_in[4], (const float*)d_in[6], (const float*)d_in[8] };
    const float* coef[3]  = { (const float*)d_in[9], (const float*)d_in[10], (const float*)d_in[11] };
    float* out = (float*)d_out;

    __half* qh  = sym_addr_t<__half>(g_qh);
    __half* kh  = sym_addr_t<__half>(g_kh);
    __half* vh  = sym_addr_t<__half>(g_vh);
    __half* twoq   = sym_addr_t<__half>(g_twoq);
    __half* threeq = sym_addr_t<__half>(g_threeq);
    __half* wh   = sym_addr_t<__half>(g_wh);
    __half* wcat = sym_addr_t<__half>(g_wcat);
    __half* QKV  = sym_addr_t<__half>(g_QKV);
    __half* ctx  = sym_addr_t<__half>(g_ctx);

    const float invs = 1.0f / sqrtf((float)HD);

    const int SM_H = 3 * 2 * 128 * 40 * 2;                 // 61440 B
    const int SM_F = (FQT + 4 * FKT) * 2;                  // 79872 B
    cudaFuncSetAttribute(hgemm_nt<1>, cudaFuncAttributeMaxDynamicSharedMemorySize, SM_H);
    cudaFuncSetAttribute(hgemm_nt<3>, cudaFuncAttributeMaxDynamicSharedMemorySize, SM_H);
    cudaFuncSetAttribute(flash_kernel, cudaFuncAttributeMaxDynamicSharedMemorySize, SM_F);

    // ---- prep: conversions, wcat, window aggregation (batched) ----
    {
        int n4 = MLB * DIM / 4;
        cvt3_kernel<<<dim3((n4 + 255) / 256, 3), 256>>>(query, keyi, value, qh, kh, vh, n4);
        int nwi = 2304 * DIM / 4;
        cvt3_kernel<<<dim3((nwi + 255) / 256, 3), 256>>>(
            w_in[0], w_in[1], w_in[2], wh, wh + WIN, wh + 2 * (size_t)WIN, nwi);
        int nwc = DIM * DIM / 2;
        build_wcat3_kernel<<<dim3((nwc + 255) / 256, 3), 256>>>(
            w_out[0], w_out[1], w_out[2], coef[0], coef[1], coef[2], wcat);
        int nv4 = NR * NB * DIM / 4;
        copy_visual_kernel<<<(nv4 + 255) / 256, 256>>>(query, twoq, threeq);
        window_agg_kernel<<<dim3(TT, NB), 256>>>(query, twoq, threeq);
    }

    dim3 gP(DIM / 128, MLB / 128, 9);       // all 9 projections in one launch
    dim3 gFin(DIM / 128, MLB / 128, 1);     // final K=2304
    dim3 gF(LQ / 128, BH, 3);               // batched flash

    // Q/K/V projections -> QKV slabs (z = wt*3 + mha)
    hgemm_nt<1><<<gP, 128, SM_H>>>(qh, twoq, threeq, kh, vh, wh, nullptr, QKV,
        MLB, DIM, DIM, DIM, DIM);

    // fused attention (all 3 MHAs) -> ctx [M, 2304]
    flash_kernel<<<gF, 256, SM_F>>>(QKV, ctx, invs);

    // out = ctx @ wcat^T  (K=2304, coef folded)
    hgemm_nt<3><<<gFin, 128, SM_H>>>(ctx, ctx, ctx, ctx, ctx, wcat, out, nullptr,
        MLB, DIM, CSTR, CSTR, CSTR);
}

// round 13
// speedup vs baseline: 9.1624x; 1.0057x over previous
#include <cuda_runtime.h>
#include <cuda_fp16.h>
#include <math.h>
#include <stdint.h>

// Problem constants (fixed shapes)
#define LQ   512
#define NB   32
#define DIM  768
#define NH   8
#define HD   96
#define NR   196
#define TT   316               // text length
#define MLB  (LQ*NB)           // 16384
#define BH   (NB*NH)           // 256
#define LDQ  (NB*DIM)          // 24576 row stride of [L,B,D] per l
#define CSTR (3*DIM)           // 2304: ctxcat row stride
#define WIN  (2304*DIM)        // fp16 w_in slab per MHA
#define SLAB ((size_t)MLB*DIM) // one [L,B,D] fp16 slab
#define EPSW 1e-8f

// -------------------- device scratch --------------------
__device__ __half g_qh [MLB*DIM];
__device__ __half g_kh [MLB*DIM];
__device__ __half g_vh [MLB*DIM];
__device__ __half g_twoq  [MLB*DIM];
__device__ __half g_threeq[MLB*DIM];
__device__ __half g_wh  [3*WIN];              // fp16 w_in x3
__device__ __half g_wcat[DIM*CSTR];           // [768, 2304] coef-folded w_out concat
__device__ __half g_QKV[9*MLB*DIM];           // slabs: z=wt*3+mha (Q:0-2, K:3-5, V:6-8)
__device__ __half g_ctx[(size_t)MLB*CSTR];    // [M, 2304] ctx concat

// -------------------- PTX helpers --------------------
__device__ __forceinline__ void cp16(uint32_t dst, const void* gptr) {
    asm volatile("cp.async.cg.shared.global [%0], [%1], 16;\n" :: "r"(dst), "l"(gptr));
}
__device__ __forceinline__ void cp_commit() { asm volatile("cp.async.commit_group;\n"); }
__device__ __forceinline__ void cp_wait1()  { asm volatile("cp.async.wait_group 1;\n"); }

__device__ __forceinline__ void mma_f16(float c[4], const uint32_t a[4],
                                        uint32_t b0, uint32_t b1) {
    asm volatile("mma.sync.aligned.m16n8k16.row.col.f32.f16.f16.f32 "
        "{%0,%1,%2,%3}, {%4,%5,%6,%7}, {%8,%9}, {%0,%1,%2,%3};\n"
        : "+f"(c[0]), "+f"(c[1]), "+f"(c[2]), "+f"(c[3])
        : "r"(a[0]), "r"(a[1]), "r"(a[2]), "r"(a[3]), "r"(b0), "r"(b1));
}
__device__ __forceinline__ void ldmx4(uint32_t& r0, uint32_t& r1,
                                      uint32_t& r2, uint32_t& r3, uint32_t addr) {
    asm volatile("ldmatrix.sync.aligned.m8n8.x4.shared.b16 {%0,%1,%2,%3}, [%4];"
        : "=r"(r0), "=r"(r1), "=r"(r2), "=r"(r3) : "r"(addr));
}
__device__ __forceinline__ void ldmx4t(uint32_t& r0, uint32_t& r1,
                                       uint32_t& r2, uint32_t& r3, uint32_t addr) {
    asm volatile("ldmatrix.sync.aligned.m8n8.x4.trans.shared.b16 {%0,%1,%2,%3}, [%4];"
        : "=r"(r0), "=r"(r1), "=r"(r2), "=r"(r3) : "r"(addr));
}
__device__ __forceinline__ uint32_t packh2(float lo, float hi) {
    __half2 h = __floats2half2_rn(lo, hi);
    return reinterpret_cast<uint32_t&>(h);
}

// -------------------- batched fp32 -> fp16 conversions --------------------
__global__ void cvt3_kernel(const float* __restrict__ s0, const float* __restrict__ s1,
                            const float* __restrict__ s2,
                            __half* __restrict__ d0, __half* __restrict__ d1,
                            __half* __restrict__ d2, int n4)
{
    int i = blockIdx.x * blockDim.x + threadIdx.x;
    if (i >= n4) return;
    int zz = blockIdx.y;
    const float* s = (zz == 0) ? s0 : ((zz == 1) ? s1 : s2);
    __half* d = (zz == 0) ? d0 : ((zz == 1) ? d1 : d2);
    float4 v = reinterpret_cast<const float4*>(s)[i];
    __half2* dd = reinterpret_cast<__half2*>(d) + 2 * i;
    dd[0] = __floats2half2_rn(v.x, v.y);
    dd[1] = __floats2half2_rn(v.z, v.w);
}

// -------------------- w_out concat (coef folded), batched --------------------
__global__ void build_wcat3_kernel(const float* __restrict__ w0, const float* __restrict__ w1,
                                   const float* __restrict__ w2,
                                   const float* __restrict__ c0, const float* __restrict__ c1,
                                   const float* __restrict__ c2,
                                   __half* __restrict__ dst)
{
    int idx = blockIdx.x * blockDim.x + threadIdx.x;
    if (idx >= DIM * DIM / 2) return;
    int i = blockIdx.y;
    const float* w = (i == 0) ? w0 : ((i == 1) ? w1 : w2);
    float c = *((i == 0) ? c0 : ((i == 1) ? c1 : c2));
    float2 v = reinterpret_cast<const float2*>(w)[idx];
    int n = (2 * idx) / DIM, k = (2 * idx) % DIM;
    *reinterpret_cast<__half2*>(&dst[(size_t)n * CSTR + i * DIM + k]) =
        __floats2half2_rn(c * v.x, c * v.y);
}

// -------------------- visual tokens -> two_q/three_q (fp16) --------------------
__global__ void copy_visual_kernel(const float* __restrict__ q,
                                   __half* __restrict__ twoq,
                                   __half* __restrict__ threeq)
{
    int i = blockIdx.x * blockDim.x + threadIdx.x;
    const int n = NR * NB * DIM / 4;
    if (i < n) {
        float4 v = reinterpret_cast<const float4*>(q)[i];
        __half2 h0 = __floats2half2_rn(v.x, v.y);
        __half2 h1 = __floats2half2_rn(v.z, v.w);
        reinterpret_cast<__half2*>(twoq)[2 * i]     = h0;
        reinterpret_cast<__half2*>(twoq)[2 * i + 1] = h1;
        reinterpret_cast<__half2*>(threeq)[2 * i]     = h0;
        reinterpret_cast<__half2*>(threeq)[2 * i + 1] = h1;
    }
}

// -------------------- window aggregation (fp16 outputs) --------------------
__global__ void window_agg_kernel(const float* __restrict__ q,
                                  __half* __restrict__ twoq,
                                  __half* __restrict__ threeq)
{
    int t = blockIdx.x;
    int b = blockIdx.y;
    int tid = threadIdx.x;

    __shared__ float xs[5][DIM];
    __shared__ float red[10][8];
    __shared__ float fin[10];

    #pragma unroll
    for (int w = 0; w < 5; w++) {
        int tw = t + w - 2;
        bool ok = (tw >= 0) && (tw < TT);
        const float* src = q + ((size_t)(NR + tw) * NB + b) * DIM;
        for (int c = tid; c < DIM; c += 256)
            xs[w][c] = ok ? src[c] : 0.0f;
    }
    __syncthreads();

    float p[10];
    #pragma unroll
    for (int k = 0; k < 10; k++) p[k] = 0.0f;

    for (int c = tid; c < DIM; c += 256) {
        float x0 = xs[0][c], x1 = xs[1][c], x2 = xs[2][c], x3 = xs[3][c], x4 = xs[4][c];
        p[0] += x0 * x0;  p[1] += x1 * x1;  p[2] += x2 * x2;
        p[3] += x3 * x3;  p[4] += x4 * x4;
        p[5] += x2 * x1;  p[6] += x2 * x3;
        p[7] += x3 * x0;  p[8] += x3 * x1;  p[9] += x3 * x4;
    }
    #pragma unroll
    for (int o = 16; o; o >>= 1) {
        #pragma unroll
        for (int k = 0; k < 10; k++)
            p[k] += __shfl_xor_sync(0xFFFFFFFFu, p[k], o);
    }
    int wid = tid >> 5, lane = tid & 31;
    if (lane == 0) {
        #pragma unroll
        for (int k = 0; k < 10; k++) red[k][wid] = p[k];
    }
    __syncthreads();
    if (tid < 10) {
        float s = 0.0f;
        #pragma unroll
        for (int w = 0; w < 8; w++) s += red[tid][w];
        fin[tid] = s;
    }
    __syncthreads();

    float n0 = fin[0], n1 = fin[1], n2 = fin[2], n3 = fin[3], n4 = fin[4];
    float in0 = 1.0f / fmaxf(sqrtf(n0), EPSW);
    float in1 = 1.0f / fmaxf(sqrtf(n1), EPSW);
    float in2 = 1.0f / fmaxf(sqrtf(n2), EPSW);
    float in3 = 1.0f / fmaxf(sqrtf(n3), EPSW);
    float in4 = 1.0f / fmaxf(sqrtf(n4), EPSW);

    float w2_1 = fin[5] * in2 * in1;
    float w2_2 = n2     * in2 * in2;
    float w2_3 = fin[6] * in2 * in3;
    float w3_0 = fin[7] * in3 * in0;
    float w3_1 = fin[8] * in3 * in1;
    float w3_2 = fin[6] * in3 * in2;
    float w3_3 = n3     * in3 * in3;
    float w3_4 = fin[9] * in3 * in4;

    size_t base = ((size_t)(NR + t) * NB + b) * DIM;
    for (int c = tid; c < DIM; c += 256) {
        float x0 = xs[0][c], x1 = xs[1][c], x2 = xs[2][c], x3 = xs[3][c], x4 = xs[4][c];
        twoq[base + c]   = __float2half(w2_1 * x1 + w2_2 * x2 + w2_3 * x3);
        threeq[base + c] = __float2half(w3_0 * x0 + w3_1 * x1 + w3_2 * x2 + w3_3 * x3 + w3_4 * x4);
    }
}

// ==================== fp16 NT GEMM (64x64 warp tiles, ldmatrix frags) ====================
// EPI 1 (proj): z = wt*3 + mha. A = src table; B = wh + mha*WIN + wt*DIM*DIM;
//               Ch[z*SLAB + r*N + col] = half(acc)
// EPI 3 (final): z = 0; A = A0, B = Bg; Cf[r*N + col] = acc
template<int EPI>
__global__ __launch_bounds__(128, 3)
void hgemm_nt(const __half* __restrict__ A0, const __half* __restrict__ A1,
              const __half* __restrict__ A2, const __half* __restrict__ A3,
              const __half* __restrict__ A4, const __half* __restrict__ Bg,
              float* __restrict__ Cf, __half* __restrict__ Ch,
              int M, int N, int K, int lda, int ldb)
{
    constexpr int BM = 128, BN = 128, BK = 32, ST = 3;
    constexpr int AST = BK + 8;           // 40 halves (80B rows -> conflict-free ldmatrix)
    constexpr int TS  = BM * AST;         // 5120 halves

    extern __shared__ __half hsm[];
    __half* As = hsm;
    __half* Bs = hsm + ST * TS;

    const int z = blockIdx.z;
    const int wt = z / 3, mha = z - 3 * wt;
    const __half* A;
    const __half* B;
    if (EPI == 1) {
        A = (wt == 0) ? ((mha == 0) ? A0 : ((mha == 1) ? A1 : A2))
                      : ((wt == 1) ? A3 : A4);
        B = Bg + (size_t)mha * WIN + (size_t)wt * DIM * DIM;
    } else {
        A = A0;
        B = Bg;
    }
    const int m0 = blockIdx.y * BM;
    const int n0 = blockIdx.x * BN;
    const int tid = threadIdx.x;
    const int lane = tid & 31;
    const int wid = tid >> 5;
    const int warp_m = (wid >> 1) * 64;
    const int warp_n = (wid & 1) * 64;
    const int gr = lane >> 2;
    const int tg = lane & 3;
    const int lg = lane >> 3, li = lane & 7;

    float acc[4][8][4];
    #pragma unroll
    for (int i = 0; i < 4; i++)
        #pragma unroll
        for (int j = 0; j < 8; j++)
            #pragma unroll
            for (int e = 0; e < 4; e++) acc[i][j][e] = 0.0f;

    const int nt = K / BK;

    uint32_t as_sh = (uint32_t)__cvta_generic_to_shared(As);
    uint32_t bs_sh = (uint32_t)__cvta_generic_to_shared(Bs);

    const int a_lane = ((lg & 1) * 8 + li) * AST + (lg >> 1) * 8;
    const int b_lane = ((lg >> 1) * 8 + li) * AST + (lg & 1) * 8;

    auto load_tile = [&](int s, int kt) {
        int k0 = kt * BK;
        #pragma unroll
        for (int r = 0; r < 4; r++) {
            int c = tid + 128 * r;
            int row = c >> 2, ch = c & 3;
            const __half* g = A + (size_t)(m0 + row) * lda + k0 + ch * 8;
            cp16(as_sh + (s * TS + row * AST + ch * 8) * 2, g);
        }
        #pragma unroll
        for (int r = 0; r < 4; r++) {
            int c = tid + 128 * r;
            int row = c >> 2, ch = c & 3;
            const __half* g = B + (size_t)(n0 + row) * ldb + k0 + ch * 8;
            cp16(bs_sh + (s * TS + row * AST + ch * 8) * 2, g);
        }
    };

    load_tile(0, 0); cp_commit();
    if (nt > 1) load_tile(1, 1);
    cp_commit();

    for (int kt = 0; kt < nt; kt++) {
        cp_wait1();
        __syncthreads();
        if (kt + 2 < nt) load_tile((kt + 2) % ST, kt + 2);
        cp_commit();

        const uint32_t abase = as_sh + ((kt % ST) * TS + a_lane) * 2;
        const uint32_t bbase = bs_sh + ((kt % ST) * TS + b_lane) * 2;

        #pragma unroll
        for (int ks = 0; ks < 2; ks++) {
            int kh2 = ks * 16 * 2;
            uint32_t af[4][4];
            #pragma unroll
            for (int i = 0; i < 4; i++)
                ldmx4(af[i][0], af[i][1], af[i][2], af[i][3],
                      abase + (warp_m + i * 16) * AST * 2 + kh2);
            uint32_t bf[8][2];
            #pragma unroll
            for (int j2 = 0; j2 < 4; j2++)
                ldmx4(bf[2 * j2][0], bf[2 * j2][1], bf[2 * j2 + 1][0], bf[2 * j2 + 1][1],
                      bbase + (warp_n + j2 * 16) * AST * 2 + kh2);
            #pragma unroll
            for (int i = 0; i < 4; i++)
                #pragma unroll
                for (int j = 0; j < 8; j++)
                    mma_f16(acc[i][j], af[i], bf[j][0], bf[j][1]);
        }
    }

    #pragma unroll
    for (int i = 0; i < 4; i++) {
        #pragma unroll
        for (int j = 0; j < 8; j++) {
            int row = m0 + warp_m + i * 16 + gr;
            int col = n0 + warp_n + j * 8 + 2 * tg;
            #pragma unroll
            for (int half_ = 0; half_ < 2; half_++) {
                int r = row + half_ * 8;
                float v0 = acc[i][j][half_ * 2 + 0];
                float v1 = acc[i][j][half_ * 2 + 1];
                if (EPI == 1) {
                    *reinterpret_cast<__half2*>(&Ch[(size_t)z * SLAB + (size_t)r * N + col]) =
                        __floats2half2_rn(v0, v1);
                } else {
                    *reinterpret_cast<float2*>(&Cf[(size_t)r * N + col]) = make_float2(v0, v1);
                }
            }
        }
    }
}

// ==================== fused flash attention (64-key tiles, ldmatrix frags) ====================
#define FSTR  104              // smem row stride (halves)
#define FSTRU 52               // in u32
#define FQT  (128*FSTR)        // Q tile halves
#define FKT  (64*FSTR)         // 64-key K/V tile halves
#define NKT  (LQ/64)           // 8 key tiles

__global__ __launch_bounds__(256, 2)
void flash_kernel(const __half* __restrict__ QKV, __half* __restrict__ Ch, float invs)
{
    extern __shared__ __half fsm[];
    __half* Qs = fsm;                    // [128][104]
    __half* Ks = fsm + FQT;              // [2][64][104]
    __half* Vs = Ks + 2 * FKT;           // [2][64][104]

    const int z  = blockIdx.y;           // b*8 + h
    const int z2 = blockIdx.z;           // MHA index
    const size_t hoff = (size_t)(z >> 3) * DIM + (size_t)(z & 7) * HD;
    const __half* Qg = QKV + (size_t)(0 + z2) * SLAB + hoff;
    const __half* Kg = QKV + (size_t)(3 + z2) * SLAB + hoff;
    const __half* Vg = QKV + (size_t)(6 + z2) * SLAB + hoff;
    const int m0 = blockIdx.x * 128;
    const int tid = threadIdx.x;
    const int lane = tid & 31;
    const int wid = tid >> 5;
    const int gr = lane >> 2, tg = lane & 3;
    const int lg = lane >> 3, li = lane & 7;

    uint32_t qs_sh = (uint32_t)__cvta_generic_to_shared(Qs);
    uint32_t ks_sh = (uint32_t)__cvta_generic_to_shared(Ks);
    uint32_t vs_sh = (uint32_t)__cvta_generic_to_shared(Vs);

    auto load_q = [&]() {
        #pragma unroll
        for (int r = 0; r < 6; r++) {
            int c = tid + 256 * r;
            int row = c / 12, ch = c % 12;
            cp16(qs_sh + (row * FSTR + ch * 8) * 2,
                 Qg + (size_t)(m0 + row) * LDQ + ch * 8);
        }
    };
    auto load_kv = [&](uint32_t dst_sh, const __half* src, int l0) {
        #pragma unroll
        for (int r = 0; r < 3; r++) {
            int c = tid + 256 * r;
            int row = c / 12, ch = c % 12;
            cp16(dst_sh + (row * FSTR + ch * 8) * 2,
                 src + (size_t)(l0 + row) * LDQ + ch * 8);
        }
    };

    load_q();
    load_kv(ks_sh, Kg, 0);
    load_kv(vs_sh, Vg, 0);
    cp_commit();
    load_kv(ks_sh + FKT * 2, Kg, 64);
    load_kv(vs_sh + FKT * 2, Vg, 64);
    cp_commit();

    uint32_t qfrag[6][4];
    float o[12][4];
    #pragma unroll
    for (int j = 0; j < 12; j++)
        #pragma unroll
        for (int e = 0; e < 4; e++) o[j][e] = 0.0f;
    float m0r = -1e30f, m1r = -1e30f, l0s = 0.0f, l1s = 0.0f;

    // ldmatrix lane offsets (halves)
    const int qa_lane = ((lg & 1) * 8 + li) * FSTR + (lg >> 1) * 8;   // A-operand (Q)
    const int kb_lane = ((lg >> 1) * 8 + li) * FSTR + (lg & 1) * 8;   // B-operand (K)
    const int v_lane  = ((lg & 1) * 8 + li) * FSTR + (lg >> 1) * 8;   // V (trans)

    #pragma unroll
    for (int kt = 0; kt < NKT; kt++) {
        if (kt < NKT - 1) { asm volatile("cp.async.wait_group 1;\n"); }
        else              { asm volatile("cp.async.wait_group 0;\n"); }
        __syncthreads();

        if (kt == 0) {
            const uint32_t qbase = qs_sh + (wid * 16 * FSTR + qa_lane) * 2;
            #pragma unroll
            for (int ks = 0; ks < 6; ks++)
                ldmx4(qfrag[ks][0], qfrag[ks][1], qfrag[ks][2], qfrag[ks][3],
                      qbase + ks * 16 * 2);
        }

        const int st = kt & 1;
        const uint32_t kbase = ks_sh + (st * FKT + kb_lane) * 2;
        const uint32_t vbase = vs_sh + (st * FKT + v_lane) * 2;

        // ---- S = Q K^T (16 x 64), K frags via ldmatrix ----
        float s[8][4];
        #pragma unroll
        for (int nf = 0; nf < 8; nf++)
            #pragma unroll
            for (int e = 0; e < 4; e++) s[nf][e] = 0.0f;
        #pragma unroll
        for (int ks = 0; ks < 6; ks++) {
            uint32_t bf[8][2];
            #pragma unroll
            for (int nf2 = 0; nf2 < 4; nf2++)
                ldmx4(bf[2 * nf2][0], bf[2 * nf2][1], bf[2 * nf2 + 1][0], bf[2 * nf2 + 1][1],
                      kbase + (nf2 * 16 * FSTR + ks * 16) * 2);
            #pragma unroll
            for (int nf = 0; nf < 8; nf++)
                mma_f16(s[nf], qfrag[ks], bf[nf][0], bf[nf][1]);
        }

        // ---- online softmax ----
        float mx0 = -1e30f, mx1 = -1e30f;
        #pragma unroll
        for (int nf = 0; nf < 8; nf++) {
            s[nf][0] *= invs; s[nf][1] *= invs; s[nf][2] *= invs; s[nf][3] *= invs;
            mx0 = fmaxf(mx0, fmaxf(s[nf][0], s[nf][1]));
            mx1 = fmaxf(mx1, fmaxf(s[nf][2], s[nf][3]));
        }
        mx0 = fmaxf(mx0, __shfl_xor_sync(0xFFFFFFFFu, mx0, 1));
        mx0 = fmaxf(mx0, __shfl_xor_sync(0xFFFFFFFFu, mx0, 2));
        mx1 = fmaxf(mx1, __shfl_xor_sync(0xFFFFFFFFu, mx1, 1));
        mx1 = fmaxf(mx1, __shfl_xor_sync(0xFFFFFFFFu, mx1, 2));

        float mn0 = fmaxf(m0r, mx0), mn1 = fmaxf(m1r, mx1);
        float al0 = __expf(m0r - mn0), al1 = __expf(m1r - mn1);
        m0r = mn0; m1r = mn1;

        float rs0 = 0.0f, rs1 = 0.0f;
        uint32_t ph[16];
        #pragma unroll
        for (int nf = 0; nf < 8; nf++) {
            float p0 = __expf(s[nf][0] - mn0);
            float p1 = __expf(s[nf][1] - mn0);
            float p2 = __expf(s[nf][2] - mn1);
            float p3 = __expf(s[nf][3] - mn1);
            rs0 += p0 + p1; rs1 += p2 + p3;
            ph[2 * nf]     = packh2(p0, p1);
            ph[2 * nf + 1] = packh2(p2, p3);
        }
        rs0 += __shfl_xor_sync(0xFFFFFFFFu, rs0, 1);
        rs0 += __shfl_xor_sync(0xFFFFFFFFu, rs0, 2);
        rs1 += __shfl_xor_sync(0xFFFFFFFFu, rs1, 1);
        rs1 += __shfl_xor_sync(0xFFFFFFFFu, rs1, 2);
        l0s = l0s * al0 + rs0;
        l1s = l1s * al1 + rs1;

        #pragma unroll
        for (int j = 0; j < 12; j++) {
            o[j][0] *= al0; o[j][1] *= al0;
            o[j][2] *= al1; o[j][3] *= al1;
        }

        // ---- O += P V (P fp16 frags; V via ldmatrix.trans) ----
        #pragma unroll
        for (int s8 = 0; s8 < 4; s8++) {
            const uint32_t* a = &ph[4 * s8];
            #pragma unroll
            for (int np = 0; np < 6; np++) {
                uint32_t r0, r1, r2, r3;
                ldmx4t(r0, r1, r2, r3, vbase + (s8 * 16 * FSTR + np * 16) * 2);
                mma_f16(o[2 * np],     a, r0, r1);
                mma_f16(o[2 * np + 1], a, r2, r3);
            }
        }

        __syncthreads();
        if (kt + 2 < NKT) {
            load_kv(ks_sh + st * FKT * 2, Kg, (kt + 2) * 64);
            load_kv(vs_sh + st * FKT * 2, Vg, (kt + 2) * 64);
        }
        cp_commit();
    }

    float il0 = 1.0f / l0s, il1 = 1.0f / l1s;
    int r0 = m0 + wid * 16 + gr;
    int r1 = r0 + 8;
    const size_t cbase = (size_t)(z >> 3) * CSTR + (size_t)z2 * DIM + (size_t)(z & 7) * HD;
    #pragma unroll
    for (int j = 0; j < 12; j++) {
        int col = j * 8 + 2 * tg;
        *reinterpret_cast<__half2*>(&Ch[(size_t)r0 * NB * CSTR + cbase + col]) =
            __floats2half2_rn(o[j][0] * il0, o[j][1] * il0);
        *reinterpret_cast<__half2*>(&Ch[(size_t)r1 * NB * CSTR + cbase + col]) =
            __floats2half2_rn(o[j][2] * il1, o[j][3] * il1);
    }
}

// -------------------- launch --------------------
template<typename T>
static T* sym_addr_t(const void* symbol)
{
    void* p = nullptr;
    cudaGetSymbolAddress(&p, symbol);
    return reinterpret_cast<T*>(p);
}

extern "C" void kernel_launch(void* const* d_in, const int* in_sizes, int n_in,
                              void* d_out, int out_size)
{
    const float* query = (const float*)d_in[0];
    const float* keyi  = (const float*)d_in[1];
    const float* value = (const float*)d_in[2];
    const float* w_in[3]  = { (const float*)d_in[3], (const float*)d_in[5], (const float*)d_in[7] };
    const float* w_out[3] = { (const float*)d_in[4], (const float*)d_in[6], (const float*)d_in[8] };
    const float* coef[3]  = { (const float*)d_in[9], (const float*)d_in[10], (const float*)d_in[11] };
    float* out = (float*)d_out;

    __half* qh  = sym_addr_t<__half>(g_qh);
    __half* kh  = sym_addr_t<__half>(g_kh);
    __half* vh  = sym_addr_t<__half>(g_vh);
    __half* twoq   = sym_addr_t<__half>(g_twoq);
    __half* threeq = sym_addr_t<__half>(g_threeq);
    __half* wh   = sym_addr_t<__half>(g_wh);
    __half* wcat = sym_addr_t<__half>(g_wcat);
    __half* QKV  = sym_addr_t<__half>(g_QKV);
    __half* ctx  = sym_addr_t<__half>(g_ctx);

    const float invs = 1.0f / sqrtf((float)HD);

    const int SM_H = 3 * 2 * 128 * 40 * 2;                 // 61440 B
    const int SM_F = (FQT + 4 * FKT) * 2;                  // 79872 B
    cudaFuncSetAttribute(hgemm_nt<1>, cudaFuncAttributeMaxDynamicSharedMemorySize, SM_H);
    cudaFuncSetAttribute(hgemm_nt<3>, cudaFuncAttributeMaxDynamicSharedMemorySize, SM_H);
    cudaFuncSetAttribute(flash_kernel, cudaFuncAttributeMaxDynamicSharedMemorySize, SM_F);

    // ---- prep: conversions, wcat, window aggregation (batched) ----
    {
        int n4 = MLB * DIM / 4;
        cvt3_kernel<<<dim3((n4 + 255) / 256, 3), 256>>>(query, keyi, value, qh, kh, vh, n4);
        int nwi = 2304 * DIM / 4;
        cvt3_kernel<<<dim3((nwi + 255) / 256, 3), 256>>>(
            w_in[0], w_in[1], w_in[2], wh, wh + WIN, wh + 2 * (size_t)WIN, nwi);
        int nwc = DIM * DIM / 2;
        build_wcat3_kernel<<<dim3((nwc + 255) / 256, 3), 256>>>(
            w_out[0], w_out[1], w_out[2], coef[0], coef[1], coef[2], wcat);
        int nv4 = NR * NB * DIM / 4;
        copy_visual_kernel<<<(nv4 + 255) / 256, 256>>>(query, twoq, threeq);
        window_agg_kernel<<<dim3(TT, NB), 256>>>(query, twoq, threeq);
    }

    dim3 gP(DIM / 128, MLB / 128, 9);       // all 9 projections in one launch
    dim3 gFin(DIM / 128, MLB / 128, 1);     // final K=2304
    dim3 gF(LQ / 128, BH, 3);               // batched flash

    // Q/K/V projections -> QKV slabs (z = wt*3 + mha)
    hgemm_nt<1><<<gP, 128, SM_H>>>(qh, twoq, threeq, kh, vh, wh, nullptr, QKV,
        MLB, DIM, DIM, DIM, DIM);

    // fused attention (all 3 MHAs) -> ctx [M, 2304]
    flash_kernel<<<gF, 256, SM_F>>>(QKV, ctx, invs);

    // out = ctx @ wcat^T  (K=2304, coef folded)
    hgemm_nt<3><<<gFin, 128, SM_H>>>(ctx, ctx, ctx, ctx, ctx, wcat, out, nullptr,
        MLB, DIM, CSTR, CSTR, CSTR);
}